// round 1
// baseline (speedup 1.0000x reference)
#include <cuda_runtime.h>
#include <cuda_bf16.h>

// Shapes (fixed by the problem): B=4, W=H=64, C=256 -> N=4096 tokens/batch,
// d_qk = 128, d_v = 256.
//
// Pipeline:
//   1) gemm_bias_kernel x3 : q = x@Wq+bq, k = x@Wk+bk, v = x@Wv+bv
//      stored in natural [B*N, d] layout (== the flat buffer the reference
//      reinterprets as [B][d][N]).
//   2) flash_kernel: per (batch, 64-query tile) flash attention over all 4096
//      keys, O written in [C][N] layout (so final reshape is a no-op).
//   3) remap_kernel: y = gamma*O + x elementwise on flat index.

#define NTOK   4096
#define DQK    128
#define DV     256
#define BATCH  4

// -------- scratch (no allocations allowed; __device__ globals) --------
__device__ float g_q[BATCH * NTOK * DQK];   // 8 MB
__device__ float g_k[BATCH * NTOK * DQK];   // 8 MB
__device__ float g_v[BATCH * NTOK * DV];    // 16 MB
__device__ float g_o[BATCH * NTOK * DV];    // 16 MB

// ---------------------------------------------------------------------
// GEMM: C[M,Nout] = A[M,256] @ W[256,Nout] + bias.  BM=128, BN=64, BK=16,
// 256 threads, each computes 8x4.
// ---------------------------------------------------------------------
__global__ __launch_bounds__(256) void gemm_bias_kernel(
    const float* __restrict__ A, const float* __restrict__ W,
    const float* __restrict__ bias, float* __restrict__ C,
    int M, int Nout)
{
    constexpr int K = 256, BM = 128, BN = 64, BK = 16;
    __shared__ float As[BK][BM];   // stored transposed: As[k][m]
    __shared__ float Ws[BK][BN];

    const int m0 = blockIdx.y * BM;
    const int n0 = blockIdx.x * BN;
    const int t  = threadIdx.x;
    const int tx = t & 15;   // n direction, TN=4
    const int ty = t >> 4;   // m direction, TM=8

    float acc[8][4];
#pragma unroll
    for (int i = 0; i < 8; i++)
#pragma unroll
        for (int j = 0; j < 4; j++) acc[i][j] = 0.f;

    for (int k0 = 0; k0 < K; k0 += BK) {
        // A tile: 128x16 = 512 float4 loads
#pragma unroll
        for (int u = 0; u < 2; u++) {
            int f   = t + u * 256;
            int row = f >> 2;
            int kc  = (f & 3) * 4;
            float4 av = *(const float4*)(A + (size_t)(m0 + row) * K + k0 + kc);
            As[kc + 0][row] = av.x;
            As[kc + 1][row] = av.y;
            As[kc + 2][row] = av.z;
            As[kc + 3][row] = av.w;
        }
        // W tile: 16x64 = 256 float4 loads
        {
            int row = t >> 4;
            int nc  = (t & 15) * 4;
            *(float4*)&Ws[row][nc] =
                *(const float4*)(W + (size_t)(k0 + row) * Nout + n0 + nc);
        }
        __syncthreads();
#pragma unroll
        for (int kk = 0; kk < BK; kk++) {
            float4 a0 = *(const float4*)&As[kk][ty * 8];
            float4 a1 = *(const float4*)&As[kk][ty * 8 + 4];
            float4 wv = *(const float4*)&Ws[kk][tx * 4];
            float a[8] = {a0.x, a0.y, a0.z, a0.w, a1.x, a1.y, a1.z, a1.w};
            float w4[4] = {wv.x, wv.y, wv.z, wv.w};
#pragma unroll
            for (int i = 0; i < 8; i++)
#pragma unroll
                for (int j = 0; j < 4; j++) acc[i][j] += a[i] * w4[j];
        }
        __syncthreads();
    }
    // epilogue with bias
    float4 bv = *(const float4*)(bias + n0 + tx * 4);
#pragma unroll
    for (int i = 0; i < 8; i++) {
        int row = m0 + ty * 8 + i;
        float4 out;
        out.x = acc[i][0] + bv.x;
        out.y = acc[i][1] + bv.y;
        out.z = acc[i][2] + bv.z;
        out.w = acc[i][3] + bv.w;
        *(float4*)(C + (size_t)row * Nout + n0 + tx * 4) = out;
    }
}

// ---------------------------------------------------------------------
// Flash attention. Block = 64 queries, 8 warps (warp w owns queries w*8..w*8+7,
// lane owns channels lane+32*i). Streams 32 keys/iter. O stored [C][N].
// ---------------------------------------------------------------------
#define FBM 64
#define FBK 32
// shared layout (floats), padded rows to kill bank conflicts
#define QS_LD 132
#define KS_LD 132
#define VS_LD 260
#define SM_QS 0
#define SM_KS (SM_QS + 64 * QS_LD)          // 8448
#define SM_VS (SM_KS + 32 * KS_LD)          // +4224
#define SM_PS (SM_VS + 32 * VS_LD)          // +8320
#define SM_FLOATS (SM_PS + 8 * 32 * 8)      // +2048 = 23040 floats = 92160 B

__global__ __launch_bounds__(256, 2) void flash_kernel(
    const float* __restrict__ qb, const float* __restrict__ kb,
    const float* __restrict__ vb, float* __restrict__ ob)
{
    extern __shared__ float sm[];
    float* Qs = sm + SM_QS;
    float* Ks = sm + SM_KS;
    float* Vs = sm + SM_VS;
    float* Ps = sm + SM_PS;

    const int b  = blockIdx.y;
    const int n0 = blockIdx.x * FBM;
    const float* q = qb + (size_t)b * NTOK * DQK;  // flat: [c*4096 + n]
    const float* k = kb + (size_t)b * NTOK * DQK;
    const float* v = vb + (size_t)b * NTOK * DV;
    float*       o = ob + (size_t)b * NTOK * DV;

    const int t = threadIdx.x, w = t >> 5, lane = t & 31;

    // Load Q tile: Qs[qi][c] = q[c*4096 + n0+qi]  (coalesced over qi)
    for (int i = t; i < 64 * 128; i += 256) {
        int c  = i >> 6;
        int qi = i & 63;
        Qs[qi * QS_LD + c] = q[(size_t)c * NTOK + n0 + qi];
    }

    float acc[8][8];
    float mrun[8], lrun[8];
#pragma unroll
    for (int qq = 0; qq < 8; qq++) {
        mrun[qq] = -1e30f;
        lrun[qq] = 0.f;
#pragma unroll
        for (int i = 0; i < 8; i++) acc[qq][i] = 0.f;
    }
    __syncthreads();

    for (int m0 = 0; m0 < NTOK; m0 += FBK) {
        // load K tile [32][128] and V tile [32][256] (coalesced over j)
        for (int i = t; i < 32 * 128; i += 256) {
            int c = i >> 5, j = i & 31;
            Ks[j * KS_LD + c] = k[(size_t)c * NTOK + m0 + j];
        }
        for (int i = t; i < 32 * 256; i += 256) {
            int ch = i >> 5, j = i & 31;
            Vs[j * VS_LD + ch] = v[(size_t)ch * NTOK + m0 + j];
        }
        __syncthreads();

        // ---- S = Q K^T : lane computes 8 dots against key `lane` ----
        float s[8];
#pragma unroll
        for (int qq = 0; qq < 8; qq++) s[qq] = 0.f;
        const float* Krow = Ks + lane * KS_LD;
#pragma unroll 8
        for (int c = 0; c < 128; c += 4) {
            float4 kv = *(const float4*)(Krow + c);
#pragma unroll
            for (int qq = 0; qq < 8; qq++) {
                float4 qv = *(const float4*)(Qs + (w * 8 + qq) * QS_LD + c);
                s[qq] += qv.x * kv.x + qv.y * kv.y + qv.z * kv.z + qv.w * kv.w;
            }
        }

        // ---- online softmax update ----
        float p[8];
#pragma unroll
        for (int qq = 0; qq < 8; qq++) {
            float vmax = s[qq];
#pragma unroll
            for (int off = 16; off > 0; off >>= 1)
                vmax = fmaxf(vmax, __shfl_xor_sync(0xffffffffu, vmax, off));
            float mn = fmaxf(mrun[qq], vmax);
            float sc = __expf(mrun[qq] - mn);
            p[qq] = __expf(s[qq] - mn);
            float ps = p[qq];
#pragma unroll
            for (int off = 16; off > 0; off >>= 1)
                ps += __shfl_xor_sync(0xffffffffu, ps, off);
            lrun[qq] = lrun[qq] * sc + ps;
            mrun[qq] = mn;
#pragma unroll
            for (int i = 0; i < 8; i++) acc[qq][i] *= sc;
        }

        // stash P transposed per-warp: Pt[j][q]
        float* Pw = Ps + w * 256 + lane * 8;
#pragma unroll
        for (int qq = 0; qq < 8; qq++) Pw[qq] = p[qq];
        __syncwarp();

        // ---- O += P @ V ----
        const float* Pr = Ps + w * 256;
#pragma unroll 2
        for (int j = 0; j < 32; j++) {
            float4 p0 = *(const float4*)(Pr + j * 8);
            float4 p1 = *(const float4*)(Pr + j * 8 + 4);
            float pj[8] = {p0.x, p0.y, p0.z, p0.w, p1.x, p1.y, p1.z, p1.w};
            const float* Vrow = Vs + j * VS_LD;
            float vv[8];
#pragma unroll
            for (int i = 0; i < 8; i++) vv[i] = Vrow[lane + 32 * i];
#pragma unroll
            for (int qq = 0; qq < 8; qq++)
#pragma unroll
                for (int i = 0; i < 8; i++) acc[qq][i] += pj[qq] * vv[i];
        }
        __syncthreads();   // all reads of Ks/Vs done before next overwrite
    }

    // normalize
#pragma unroll
    for (int qq = 0; qq < 8; qq++) {
        float inv = 1.f / lrun[qq];
#pragma unroll
        for (int i = 0; i < 8; i++) acc[qq][i] *= inv;
    }

    // transpose through shared and store O in [C][N] layout
    __syncthreads();
    float* St = sm;   // reuse: [64][260]
#pragma unroll
    for (int qq = 0; qq < 8; qq++)
#pragma unroll
        for (int i = 0; i < 8; i++)
            St[(w * 8 + qq) * VS_LD + lane + 32 * i] = acc[qq][i];
    __syncthreads();
    for (int i = t; i < 64 * 256; i += 256) {
        int c  = i >> 6;
        int qi = i & 63;
        o[(size_t)c * NTOK + n0 + qi] = St[qi * VS_LD + c];
    }
}

// ---------------------------------------------------------------------
// y = gamma * O + x   (flat elementwise; reshape is identity on flat index)
// ---------------------------------------------------------------------
__global__ __launch_bounds__(256) void remap_kernel(
    const float* __restrict__ ob, const float* __restrict__ x,
    const float* __restrict__ gamma, float* __restrict__ y, int n4)
{
    float g = gamma[0];
    int i = blockIdx.x * blockDim.x + threadIdx.x;
    int stride = gridDim.x * blockDim.x;
    const float4* o4 = (const float4*)ob;
    const float4* x4 = (const float4*)x;
    float4*       y4 = (float4*)y;
    for (; i < n4; i += stride) {
        float4 a = o4[i], b = x4[i], r;
        r.x = g * a.x + b.x;
        r.y = g * a.y + b.y;
        r.z = g * a.z + b.z;
        r.w = g * a.w + b.w;
        y4[i] = r;
    }
}

// ---------------------------------------------------------------------
extern "C" void kernel_launch(void* const* d_in, const int* in_sizes, int n_in,
                              void* d_out, int out_size)
{
    const float* x     = (const float*)d_in[0];
    const float* Wq    = (const float*)d_in[1];
    const float* bq    = (const float*)d_in[2];
    const float* Wk    = (const float*)d_in[3];
    const float* bk    = (const float*)d_in[4];
    const float* Wv    = (const float*)d_in[5];
    const float* bv    = (const float*)d_in[6];
    const float* gamma = (const float*)d_in[7];
    float* out = (float*)d_out;

    float *qbuf, *kbuf, *vbuf, *obuf;
    cudaGetSymbolAddress((void**)&qbuf, g_q);
    cudaGetSymbolAddress((void**)&kbuf, g_k);
    cudaGetSymbolAddress((void**)&vbuf, g_v);
    cudaGetSymbolAddress((void**)&obuf, g_o);

    const int M = BATCH * NTOK;   // 16384

    // projections
    gemm_bias_kernel<<<dim3(DQK / 64, M / 128), 256>>>(x, Wq, bq, qbuf, M, DQK);
    gemm_bias_kernel<<<dim3(DQK / 64, M / 128), 256>>>(x, Wk, bk, kbuf, M, DQK);
    gemm_bias_kernel<<<dim3(DV  / 64, M / 128), 256>>>(x, Wv, bv, vbuf, M, DV);

    // flash attention
    static_assert(SM_FLOATS * 4 == 92160, "smem layout");
    cudaFuncSetAttribute(flash_kernel,
                         cudaFuncAttributeMaxDynamicSharedMemorySize, 92160);
    flash_kernel<<<dim3(NTOK / FBM, BATCH), 256, 92160>>>(qbuf, kbuf, vbuf, obuf);

    // residual + gamma
    int n4 = out_size / 4;   // float4 count
    remap_kernel<<<4096, 256>>>(obuf, x, gamma, out, n4);
}

// round 3
// speedup vs baseline: 2.4144x; 2.4144x over previous
#include <cuda_runtime.h>
#include <cuda_bf16.h>
#include <cstdint>

// B=4, N=4096 tok/batch, d_qk=128, d_v=256.
// All "reshape" ops in the reference are flat reinterprets:
//   pq[b][c][n] = q_flat[b][c*4096+n]  (token-major q buffer read as [c][n])
// so attention operands index the flat projection buffers directly, and the
// output O stored [c][n] makes the final reshape a no-op.
//
// Pipeline:
//  1) gemm_bias x3 (fp32 FFMA, verified round 1)
//  2) prep kernels: fp32 -> bf16 hi/lo padded tile images (row-pad kills
//     ldmatrix bank conflicts; flash tile load is a linear uint4 copy)
//  3) flash_kernel: warp-level HMMA (mma.sync.m16n8k16.bf16, non-'a' ISA),
//     3-term split precision for S and PV; unnormalized exp (no max-sub,
//     |S|<~45 so fp32-safe); P converted accum->A-frag fully in registers;
//     epilogue fuses /l, *gamma, +x.

#define NTOK  4096
#define DQK   128
#define DV    256
#define BATCH 4
#define BM    64      // queries per CTA
#define BN    32      // keys per iteration
#define NKT   (NTOK / BN)          // 128 iters
#define LDQ   136     // padded row stride (halves) for Q/K images
#define LDV   40      // padded row stride (halves) for V images

// -------- device scratch (no allocations allowed) --------
__device__ float g_q[BATCH * NTOK * DQK];
__device__ float g_k[BATCH * NTOK * DQK];
__device__ float g_v[BATCH * NTOK * DV];
// Q image: per (b, qt<64): [hi 64x136 | lo 64x136]
__device__ __align__(16) __nv_bfloat16 g_qimg[BATCH * 64 * 2 * BM * LDQ];
// K image: per (b, kt<128): [hi 32x136 | lo 32x136]
__device__ __align__(16) __nv_bfloat16 g_kimg[BATCH * 128 * 2 * BN * LDQ];
// V image: per (b, kt<128): [hi 256x40 | lo 256x40]  (rows = v-channels)
__device__ __align__(16) __nv_bfloat16 g_vimg[BATCH * 128 * 2 * DV * LDV];

// ---------------- wrappers ----------------
__device__ __forceinline__ uint32_t smem_u32(const void* p) {
    uint32_t a;
    asm("{ .reg .u64 t; cvta.to.shared.u64 t, %1; cvt.u32.u64 %0, t; }" : "=r"(a) : "l"(p));
    return a;
}
__device__ __forceinline__ void ldsm_x4(uint32_t* r, uint32_t saddr) {
    asm volatile("ldmatrix.sync.aligned.m8n8.x4.shared.b16 {%0,%1,%2,%3}, [%4];"
        : "=r"(r[0]), "=r"(r[1]), "=r"(r[2]), "=r"(r[3]) : "r"(saddr));
}
__device__ __forceinline__ void mma_bf16(float* d, const uint32_t* a, const uint32_t* b) {
    asm volatile("mma.sync.aligned.m16n8k16.row.col.f32.bf16.bf16.f32 "
        "{%0,%1,%2,%3}, {%4,%5,%6,%7}, {%8,%9}, {%0,%1,%2,%3};"
        : "+f"(d[0]), "+f"(d[1]), "+f"(d[2]), "+f"(d[3])
        : "r"(a[0]), "r"(a[1]), "r"(a[2]), "r"(a[3]), "r"(b[0]), "r"(b[1]));
}
__device__ __forceinline__ uint32_t packbf2(__nv_bfloat16 x, __nv_bfloat16 y) {
    __nv_bfloat162 t; t.x = x; t.y = y;   // .x = low 16 bits = first element
    return *reinterpret_cast<uint32_t*>(&t);
}

// ---------------- projections (verified round 1) ----------------
__global__ __launch_bounds__(256) void gemm_bias_kernel(
    const float* __restrict__ A, const float* __restrict__ W,
    const float* __restrict__ bias, float* __restrict__ C, int M, int Nout)
{
    constexpr int K = 256, BK = 16;
    __shared__ float As[BK][128];
    __shared__ float Ws[BK][64];
    const int m0 = blockIdx.y * 128, n0 = blockIdx.x * 64;
    const int t = threadIdx.x, tx = t & 15, ty = t >> 4;
    float acc[8][4];
#pragma unroll
    for (int i = 0; i < 8; i++)
#pragma unroll
        for (int j = 0; j < 4; j++) acc[i][j] = 0.f;
    for (int k0 = 0; k0 < K; k0 += BK) {
#pragma unroll
        for (int u = 0; u < 2; u++) {
            int f = t + u * 256, row = f >> 2, kc = (f & 3) * 4;
            float4 av = *(const float4*)(A + (size_t)(m0 + row) * K + k0 + kc);
            As[kc + 0][row] = av.x; As[kc + 1][row] = av.y;
            As[kc + 2][row] = av.z; As[kc + 3][row] = av.w;
        }
        {
            int row = t >> 4, nc = (t & 15) * 4;
            *(float4*)&Ws[row][nc] = *(const float4*)(W + (size_t)(k0 + row) * Nout + n0 + nc);
        }
        __syncthreads();
#pragma unroll
        for (int kk = 0; kk < BK; kk++) {
            float4 a0 = *(const float4*)&As[kk][ty * 8];
            float4 a1 = *(const float4*)&As[kk][ty * 8 + 4];
            float4 wv = *(const float4*)&Ws[kk][tx * 4];
            float a[8] = {a0.x,a0.y,a0.z,a0.w,a1.x,a1.y,a1.z,a1.w};
            float w4[4] = {wv.x,wv.y,wv.z,wv.w};
#pragma unroll
            for (int i = 0; i < 8; i++)
#pragma unroll
                for (int j = 0; j < 4; j++) acc[i][j] += a[i] * w4[j];
        }
        __syncthreads();
    }
    float4 bv = *(const float4*)(bias + n0 + tx * 4);
#pragma unroll
    for (int i = 0; i < 8; i++) {
        int row = m0 + ty * 8 + i;
        float4 o = {acc[i][0]+bv.x, acc[i][1]+bv.y, acc[i][2]+bv.z, acc[i][3]+bv.w};
        *(float4*)(C + (size_t)row * Nout + n0 + tx * 4) = o;
    }
}

// ---------------- prep: fp32 -> split bf16 padded images ----------------
// Q/K: tile = R rows (queries/keys) x 128 ch, row stride LDQ.
// img[(b*T + tile)] = [hi RxLDQ | lo RxLDQ]. src read as pq[c][n] flat.
__global__ __launch_bounds__(128) void prep_qk_kernel(
    const float* __restrict__ buf, __nv_bfloat16* __restrict__ img, int R, int T)
{
    const int tile = blockIdx.x, b = blockIdx.y, c = threadIdx.x;   // c in [0,128)
    const float* src = buf + (size_t)b * NTOK * DQK;
    __nv_bfloat16* dst = img + (size_t)(b * T + tile) * (2 * R * LDQ);
    const int n0 = tile * R;
    for (int q = 0; q < R; q++) {
        float v = src[(size_t)c * NTOK + n0 + q];
        __nv_bfloat16 hi = __float2bfloat16(v);
        __nv_bfloat16 lo = __float2bfloat16(v - __bfloat162float(hi));
        dst[q * LDQ + c] = hi;
        dst[R * LDQ + q * LDQ + c] = lo;
    }
}
// V: tile = 32 keys; rows = 256 v-channels, cols = keys, row stride LDV.
__global__ __launch_bounds__(256) void prep_v_kernel()
{
    const int tile = blockIdx.x, b = blockIdx.y, t = threadIdx.x;
    const int m = t & 31;          // key within tile
    const float* src = g_v + (size_t)b * NTOK * DV;
    __nv_bfloat16* dst = g_vimg + (size_t)(b * 128 + tile) * (2 * DV * LDV);
    const int n0 = tile * BN;
    for (int c = (t >> 5); c < DV; c += 8) {
        float v = src[(size_t)c * NTOK + n0 + m];
        __nv_bfloat16 hi = __float2bfloat16(v);
        __nv_bfloat16 lo = __float2bfloat16(v - __bfloat162float(hi));
        dst[c * LDV + m] = hi;
        dst[DV * LDV + c * LDV + m] = lo;
    }
}

// ---------------- flash kernel (HMMA) ----------------
// smem halves: Qhi[64x136]@0, Qlo@8704, Khi[32x136]@17408, Klo@21760,
//              Vhi[256x40]@26112, Vlo@36352; total 46592 halves = 93184 B.
#define SQHI 0
#define SQLO 8704
#define SKHI 17408
#define SKLO 21760
#define SVHI 26112
#define SVLO 36352
#define SM_BYTES 93184

__global__ __launch_bounds__(256, 2) void flash_kernel(
    const float* __restrict__ xin, const float* __restrict__ gamma_p,
    float* __restrict__ yout)
{
    extern __shared__ __nv_bfloat16 sm[];
    const uint32_t sb = smem_u32(sm);
    const int t = threadIdx.x, lane = t & 31, wid = t >> 5;
    const int mw = wid >> 1, nw = wid & 1;    // warp = (row-group, v-half)
    const int qt = blockIdx.x, b = blockIdx.y;
    const int n0 = qt * BM;

    // per-lane ldmatrix base offsets (halves)
    const int lg = lane >> 3, lr = lane & 7;
    const uint32_t qa_base = (uint32_t)((16 * mw + lr + (lg & 1) * 8) * LDQ + (lg >> 1) * 8);
    const uint32_t kb_base = (uint32_t)(lr * LDQ + lg * 8);
    const uint32_t vb_base = (uint32_t)((lr + nw * 128) * LDV + lg * 8);

    // Q tile copy (2176 uint4, linear)
    {
        const uint4* src = (const uint4*)(g_qimg + (size_t)(b * 64 + qt) * (2 * BM * LDQ));
        uint4* dst = (uint4*)sm;
#pragma unroll
        for (int i = 0; i < 9; i++) {
            int j = t + i * 256;
            if (j < 2176) dst[j] = src[j];
        }
    }

    float oacc[16][4];
#pragma unroll
    for (int nf = 0; nf < 16; nf++)
#pragma unroll
        for (int e = 0; e < 4; e++) oacc[nf][e] = 0.f;
    float lsum0 = 0.f, lsum1 = 0.f;

    const uint4* kimg = (const uint4*)(g_kimg + (size_t)b * 128 * (2 * BN * LDQ));
    const uint4* vimg = (const uint4*)(g_vimg + (size_t)b * 128 * (2 * DV * LDV));

    for (int kt = 0; kt < NKT; kt++) {
        __syncthreads();   // prior reads done (also covers Q copy on iter 0)
        {
            const uint4* ks = kimg + (size_t)kt * 1088;
            uint4* kd = (uint4*)(sm + SKHI);
#pragma unroll
            for (int i = 0; i < 5; i++) {
                int j = t + i * 256;
                if (j < 1088) kd[j] = ks[j];
            }
            const uint4* vs = vimg + (size_t)kt * 2560;
            uint4* vd = (uint4*)(sm + SVHI);
#pragma unroll
            for (int i = 0; i < 10; i++) vd[t + i * 256] = vs[t + i * 256];
        }
        __syncthreads();

        // ---- S = Q K^T (split: hi*hi + hi*lo + lo*hi) ----
        float sacc[4][4];
#pragma unroll
        for (int nn = 0; nn < 4; nn++)
#pragma unroll
            for (int e = 0; e < 4; e++) sacc[nn][e] = 0.f;

#pragma unroll
        for (int kkp = 0; kkp < 4; kkp++) {          // k-chunk pairs (32 ch)
            uint32_t qh0[4], qh1[4], ql0[4], ql1[4];
            ldsm_x4(qh0, sb + 2 * (SQHI + qa_base + 32 * kkp));
            ldsm_x4(qh1, sb + 2 * (SQHI + qa_base + 32 * kkp + 16));
            ldsm_x4(ql0, sb + 2 * (SQLO + qa_base + 32 * kkp));
            ldsm_x4(ql1, sb + 2 * (SQLO + qa_base + 32 * kkp + 16));
#pragma unroll
            for (int nn = 0; nn < 4; nn++) {
                uint32_t kh[4], kl[4];
                ldsm_x4(kh, sb + 2 * (SKHI + kb_base + nn * 8 * LDQ + 32 * kkp));
                ldsm_x4(kl, sb + 2 * (SKLO + kb_base + nn * 8 * LDQ + 32 * kkp));
                mma_bf16(sacc[nn], qh0, kh);
                mma_bf16(sacc[nn], qh1, kh + 2);
                mma_bf16(sacc[nn], qh0, kl);
                mma_bf16(sacc[nn], qh1, kl + 2);
                mma_bf16(sacc[nn], ql0, kh);
                mma_bf16(sacc[nn], ql1, kh + 2);
            }
        }

        // ---- P = exp(S) (unnormalized), accumulate row sums, pack A-frags ----
        float pex[4][4];
#pragma unroll
        for (int nn = 0; nn < 4; nn++) {
#pragma unroll
            for (int e = 0; e < 4; e++) pex[nn][e] = __expf(sacc[nn][e]);
            lsum0 += pex[nn][0] + pex[nn][1];
            lsum1 += pex[nn][2] + pex[nn][3];
        }
        uint32_t phi[2][4], plo[2][4];
#pragma unroll
        for (int kk = 0; kk < 2; kk++) {
#pragma unroll
            for (int half = 0; half < 2; half++) {   // nfrag 2kk+half
                const float* p = pex[2 * kk + half];
                __nv_bfloat16 h0 = __float2bfloat16(p[0]);
                __nv_bfloat16 h1 = __float2bfloat16(p[1]);
                __nv_bfloat16 h2 = __float2bfloat16(p[2]);
                __nv_bfloat16 h3 = __float2bfloat16(p[3]);
                phi[kk][2 * half + 0] = packbf2(h0, h1);
                phi[kk][2 * half + 1] = packbf2(h2, h3);
                plo[kk][2 * half + 0] = packbf2(
                    __float2bfloat16(p[0] - __bfloat162float(h0)),
                    __float2bfloat16(p[1] - __bfloat162float(h1)));
                plo[kk][2 * half + 1] = packbf2(
                    __float2bfloat16(p[2] - __bfloat162float(h2)),
                    __float2bfloat16(p[3] - __bfloat162float(h3)));
            }
        }
        // A-frag order fix: a0,a1 = rows r,r+8 cols 0..7 (nfrag 2kk);
        // a2,a3 = cols 8..15 (nfrag 2kk+1) — already laid out that way above:
        // phi[kk] = {nfrag2kk:(c0,c1),(c2,c3), nfrag2kk+1:(c0,c1),(c2,c3)} ✓

        // ---- O += P V (split) ----
#pragma unroll
        for (int nf = 0; nf < 16; nf++) {
            uint32_t vh[4], vl[4];
            ldsm_x4(vh, sb + 2 * (SVHI + vb_base + nf * 8 * LDV));
            ldsm_x4(vl, sb + 2 * (SVLO + vb_base + nf * 8 * LDV));
#pragma unroll
            for (int kk = 0; kk < 2; kk++) {
                mma_bf16(oacc[nf], phi[kk], vh + 2 * kk);
                mma_bf16(oacc[nf], phi[kk], vl + 2 * kk);
                mma_bf16(oacc[nf], plo[kk], vh + 2 * kk);
            }
        }
    }

    // ---- epilogue: y = gamma*(O/l) + x  (flat [b][c][n] indexing) ----
    lsum0 += __shfl_xor_sync(0xffffffffu, lsum0, 1);
    lsum0 += __shfl_xor_sync(0xffffffffu, lsum0, 2);
    lsum1 += __shfl_xor_sync(0xffffffffu, lsum1, 1);
    lsum1 += __shfl_xor_sync(0xffffffffu, lsum1, 2);
    const float g = gamma_p[0];
    const float s0 = g / lsum0, s1 = g / lsum1;
    const float* xb = xin  + (size_t)b * DV * NTOK;
    float*       yb = yout + (size_t)b * DV * NTOK;
    const int r0 = n0 + 16 * mw + (lane >> 2);
#pragma unroll
    for (int nf = 0; nf < 16; nf++) {
        const int c = nw * 128 + nf * 8 + 2 * (lane & 3);
        size_t i00 = (size_t)c * NTOK + r0;
        size_t i10 = i00 + NTOK;            // c+1, row r0
        yb[i00]     = oacc[nf][0] * s0 + xb[i00];
        yb[i10]     = oacc[nf][1] * s0 + xb[i10];
        yb[i00 + 8] = oacc[nf][2] * s1 + xb[i00 + 8];
        yb[i10 + 8] = oacc[nf][3] * s1 + xb[i10 + 8];
    }
}

// ---------------- launch ----------------
extern "C" void kernel_launch(void* const* d_in, const int* in_sizes, int n_in,
                              void* d_out, int out_size)
{
    const float* x     = (const float*)d_in[0];
    const float* Wq    = (const float*)d_in[1];
    const float* bq    = (const float*)d_in[2];
    const float* Wk    = (const float*)d_in[3];
    const float* bk    = (const float*)d_in[4];
    const float* Wv    = (const float*)d_in[5];
    const float* bv    = (const float*)d_in[6];
    const float* gamma = (const float*)d_in[7];
    float* out = (float*)d_out;

    float *qbuf, *kbuf, *vbuf;
    __nv_bfloat16 *qimg, *kimg;
    cudaGetSymbolAddress((void**)&qbuf, g_q);
    cudaGetSymbolAddress((void**)&kbuf, g_k);
    cudaGetSymbolAddress((void**)&vbuf, g_v);
    cudaGetSymbolAddress((void**)&qimg, g_qimg);
    cudaGetSymbolAddress((void**)&kimg, g_kimg);

    const int M = BATCH * NTOK;
    gemm_bias_kernel<<<dim3(DQK / 64, M / 128), 256>>>(x, Wq, bq, qbuf, M, DQK);
    gemm_bias_kernel<<<dim3(DQK / 64, M / 128), 256>>>(x, Wk, bk, kbuf, M, DQK);
    gemm_bias_kernel<<<dim3(DV  / 64, M / 128), 256>>>(x, Wv, bv, vbuf, M, DV);

    prep_qk_kernel<<<dim3(64, BATCH), 128>>>(qbuf, qimg, BM, 64);
    prep_qk_kernel<<<dim3(128, BATCH), 128>>>(kbuf, kimg, BN, 128);
    prep_v_kernel<<<dim3(128, BATCH), 256>>>();

    cudaFuncSetAttribute(flash_kernel,
                         cudaFuncAttributeMaxDynamicSharedMemorySize, SM_BYTES);
    flash_kernel<<<dim3(NTOK / BM, BATCH), 256, SM_BYTES>>>(x, gamma, out);
}

// round 4
// speedup vs baseline: 2.7075x; 1.1214x over previous
#include <cuda_runtime.h>
#include <cuda_bf16.h>
#include <cstdint>

// B=4, N=4096 tok/batch, d_qk=128, d_v=256.  All reference reshapes are flat
// reinterprets, so attention indexes flat projection buffers as [c][n] and the
// output stored [b][c][n] flat makes the final reshape+residual elementwise.
//
// Pipeline (all GEMMs on tensor pipe, 3-term split-bf16 for fp32-grade accuracy):
//  1) prep_x / prep_w: split x and W into bf16 hi/lo operand images
//  2) gemm_tensor: q|k|v = x@W + b  (HMMA, fused 512-wide N)
//  3) prep_qk / prep_v: fp32 q/k/v -> bf16 hi/lo padded tile images
//  4) flash_kernel: BM=128, 8 warps x 16 rows, full 256 v-ch per warp (no
//     duplicated S work), cp.async double-buffered K/V, unnormalized exp
//     (|S|<~45 so fp32-safe), epilogue fuses /l, *gamma, +x.

#define NTOK  4096
#define DQK   128
#define DV    256
#define BATCH 4
#define BM    128
#define BN    32
#define NKT   (NTOK / BN)
#define LDQ   136
#define LDV   40

// -------- device scratch (no allocations allowed) --------
__device__ float g_q[BATCH * NTOK * DQK];
__device__ float g_k[BATCH * NTOK * DQK];
__device__ float g_v[BATCH * NTOK * DV];
__device__ __align__(16) __nv_bfloat16 g_xhi[BATCH * NTOK * 256];
__device__ __align__(16) __nv_bfloat16 g_xlo[BATCH * NTOK * 256];
__device__ __align__(16) __nv_bfloat16 g_whi[512 * 256];
__device__ __align__(16) __nv_bfloat16 g_wlo[512 * 256];
__device__ float g_bias[512];
__device__ __align__(16) __nv_bfloat16 g_qimg[BATCH * 32 * 2 * BM * LDQ];
__device__ __align__(16) __nv_bfloat16 g_kimg[BATCH * 128 * 2 * BN * LDQ];
__device__ __align__(16) __nv_bfloat16 g_vimg[BATCH * 128 * 2 * DV * LDV];

// ---------------- wrappers ----------------
__device__ __forceinline__ uint32_t smem_u32(const void* p) {
    uint32_t a;
    asm("{ .reg .u64 t; cvta.to.shared.u64 t, %1; cvt.u32.u64 %0, t; }" : "=r"(a) : "l"(p));
    return a;
}
__device__ __forceinline__ void ldsm_x4(uint32_t* r, uint32_t saddr) {
    asm volatile("ldmatrix.sync.aligned.m8n8.x4.shared.b16 {%0,%1,%2,%3}, [%4];"
        : "=r"(r[0]), "=r"(r[1]), "=r"(r[2]), "=r"(r[3]) : "r"(saddr));
}
__device__ __forceinline__ void mma_bf16(float* d, const uint32_t* a, const uint32_t* b) {
    asm volatile("mma.sync.aligned.m16n8k16.row.col.f32.bf16.bf16.f32 "
        "{%0,%1,%2,%3}, {%4,%5,%6,%7}, {%8,%9}, {%0,%1,%2,%3};"
        : "+f"(d[0]), "+f"(d[1]), "+f"(d[2]), "+f"(d[3])
        : "r"(a[0]), "r"(a[1]), "r"(a[2]), "r"(a[3]), "r"(b[0]), "r"(b[1]));
}
__device__ __forceinline__ uint32_t packbf2(__nv_bfloat16 x, __nv_bfloat16 y) {
    __nv_bfloat162 t; t.x = x; t.y = y;
    return *reinterpret_cast<uint32_t*>(&t);
}
__device__ __forceinline__ void cp16(uint32_t saddr, const void* g) {
    asm volatile("cp.async.cg.shared.global [%0], [%1], 16;" :: "r"(saddr), "l"(g));
}
#define CP_COMMIT() asm volatile("cp.async.commit_group;" ::: "memory")
#define CP_WAIT(n)  asm volatile("cp.async.wait_group %0;" :: "n"(n) : "memory")

// ---------------- prep_x: x fp32 -> hi/lo bf16 row-major ----------------
__global__ __launch_bounds__(256) void prep_x_kernel(const float* __restrict__ x) {
    size_t i = (size_t)blockIdx.x * 256 + threadIdx.x;   // float2 index
    float2 v = ((const float2*)x)[i];
    __nv_bfloat16 h0 = __float2bfloat16(v.x);
    __nv_bfloat16 h1 = __float2bfloat16(v.y);
    __nv_bfloat162 hp; hp.x = h0; hp.y = h1;
    __nv_bfloat162 lp;
    lp.x = __float2bfloat16(v.x - __bfloat162float(h0));
    lp.y = __float2bfloat16(v.y - __bfloat162float(h1));
    ((__nv_bfloat162*)g_xhi)[i] = hp;
    ((__nv_bfloat162*)g_xlo)[i] = lp;
}

// ---------------- prep_w: transpose+split weights, concat bias ----------------
__global__ __launch_bounds__(256) void prep_w_kernel(
    const float* __restrict__ Wq, const float* __restrict__ bq,
    const float* __restrict__ Wk, const float* __restrict__ bk,
    const float* __restrict__ Wv, const float* __restrict__ bv)
{
    const int d = blockIdx.x, c = threadIdx.x;   // d<512, c<256
    float w;
    if (d < 128)      w = Wq[c * 128 + d];
    else if (d < 256) w = Wk[c * 128 + (d - 128)];
    else              w = Wv[c * 256 + (d - 256)];
    __nv_bfloat16 hi = __float2bfloat16(w);
    g_whi[d * 256 + c] = hi;
    g_wlo[d * 256 + c] = __float2bfloat16(w - __bfloat162float(hi));
    if (c == 0)
        g_bias[d] = (d < 128) ? bq[d] : (d < 256) ? bk[d - 128] : bv[d - 256];
}

// ---------------- tensorized projection GEMM ----------------
// [16384,256] @ [256,512] + bias.  BM=128 tokens, BN=128 out-ch, BK=64.
#define GLDA 72
#define GSAHI 0
#define GSALO 9216
#define GSBHI 18432
#define GSBLO 27648
#define GSM_BYTES 73728

__global__ __launch_bounds__(256, 2) void gemm_tensor_kernel() {
    extern __shared__ __nv_bfloat16 sg[];
    const uint32_t sb = smem_u32(sg);
    const int t = threadIdx.x, lane = t & 31, wid = t >> 5;
    const int nt = blockIdx.x;                 // 0..3 (128 out-ch each)
    const int m0 = blockIdx.y * 128;           // token base
    const int n0 = nt * 128;
    const int lg = lane >> 3, lr = lane & 7;
    const uint32_t a_base = (uint32_t)((16 * wid + lr + (lg & 1) * 8) * GLDA + (lg >> 1) * 8);
    const uint32_t b_base = (uint32_t)(lr * GLDA + lg * 8);

    float acc[16][4];
#pragma unroll
    for (int nf = 0; nf < 16; nf++)
#pragma unroll
        for (int e = 0; e < 4; e++) acc[nf][e] = 0.f;

    for (int k0 = 0; k0 < 256; k0 += 64) {
        __syncthreads();
        // load A(hi/lo) and B(hi/lo) tiles: 1024 uint4 each
        {
            const uint4* ah = (const uint4*)g_xhi + ((size_t)m0 * 256 + k0) / 8;
            const uint4* al = (const uint4*)g_xlo + ((size_t)m0 * 256 + k0) / 8;
            const uint4* bh = (const uint4*)g_whi + ((size_t)n0 * 256 + k0) / 8;
            const uint4* bl = (const uint4*)g_wlo + ((size_t)n0 * 256 + k0) / 8;
            uint4* sah = (uint4*)(sg + GSAHI);
            uint4* sal = (uint4*)(sg + GSALO);
            uint4* sbh = (uint4*)(sg + GSBHI);
            uint4* sbl = (uint4*)(sg + GSBLO);
#pragma unroll
            for (int u = 0; u < 4; u++) {
                int idx = t + u * 256, row = idx >> 3, ch = idx & 7;
                sah[row * 9 + ch] = ah[(size_t)row * 32 + ch];
                sal[row * 9 + ch] = al[(size_t)row * 32 + ch];
                sbh[row * 9 + ch] = bh[(size_t)row * 32 + ch];
                sbl[row * 9 + ch] = bl[(size_t)row * 32 + ch];
            }
        }
        __syncthreads();
#pragma unroll
        for (int kkp = 0; kkp < 2; kkp++) {
            uint32_t qh0[4], qh1[4], ql0[4], ql1[4];
            ldsm_x4(qh0, sb + 2 * (GSAHI + a_base + 32 * kkp));
            ldsm_x4(qh1, sb + 2 * (GSAHI + a_base + 32 * kkp + 16));
            ldsm_x4(ql0, sb + 2 * (GSALO + a_base + 32 * kkp));
            ldsm_x4(ql1, sb + 2 * (GSALO + a_base + 32 * kkp + 16));
#pragma unroll
            for (int nf = 0; nf < 16; nf++) {
                uint32_t bh[4], bl[4];
                ldsm_x4(bh, sb + 2 * (GSBHI + b_base + nf * 8 * GLDA + 32 * kkp));
                ldsm_x4(bl, sb + 2 * (GSBLO + b_base + nf * 8 * GLDA + 32 * kkp));
                mma_bf16(acc[nf], qh0, bh);
                mma_bf16(acc[nf], qh1, bh + 2);
                mma_bf16(acc[nf], qh0, bl);
                mma_bf16(acc[nf], qh1, bl + 2);
                mma_bf16(acc[nf], ql0, bh);
                mma_bf16(acc[nf], ql1, bh + 2);
            }
        }
    }

    // epilogue: bias + store fp32 to q/k/v (token-major)
    float* dst; int doff, Dd;
    if (nt == 0)      { dst = g_q; doff = 0;   Dd = 128; }
    else if (nt == 1) { dst = g_k; doff = 0;   Dd = 128; }
    else              { dst = g_v; doff = (nt - 2) * 128; Dd = 256; }
    const int r0 = m0 + 16 * wid + (lane >> 2);
#pragma unroll
    for (int nf = 0; nf < 16; nf++) {
        const int cg = nf * 8 + 2 * (lane & 3);          // 0..127 within block
        const float b0 = g_bias[n0 + cg], b1 = g_bias[n0 + cg + 1];
        const int dd = doff + cg;
        float2 v0 = {acc[nf][0] + b0, acc[nf][1] + b1};
        float2 v1 = {acc[nf][2] + b0, acc[nf][3] + b1};
        *(float2*)(dst + (size_t)r0 * Dd + dd) = v0;
        *(float2*)(dst + (size_t)(r0 + 8) * Dd + dd) = v1;
    }
}

// ---------------- prep: fp32 -> split bf16 padded images ----------------
__global__ __launch_bounds__(128) void prep_qk_kernel(
    const float* __restrict__ buf, __nv_bfloat16* __restrict__ img, int R, int T)
{
    const int tile = blockIdx.x, b = blockIdx.y, c = threadIdx.x;
    const float* src = buf + (size_t)b * NTOK * DQK;
    __nv_bfloat16* dst = img + (size_t)(b * T + tile) * (2 * R * LDQ);
    const int n0 = tile * R;
    for (int q = 0; q < R; q++) {
        float v = src[(size_t)c * NTOK + n0 + q];
        __nv_bfloat16 hi = __float2bfloat16(v);
        dst[q * LDQ + c] = hi;
        dst[R * LDQ + q * LDQ + c] = __float2bfloat16(v - __bfloat162float(hi));
    }
}
__global__ __launch_bounds__(256) void prep_v_kernel()
{
    const int tile = blockIdx.x, b = blockIdx.y, t = threadIdx.x;
    const int m = t & 31;
    const float* src = g_v + (size_t)b * NTOK * DV;
    __nv_bfloat16* dst = g_vimg + (size_t)(b * 128 + tile) * (2 * DV * LDV);
    const int n0 = tile * BN;
    for (int c = (t >> 5); c < DV; c += 8) {
        float v = src[(size_t)c * NTOK + n0 + m];
        __nv_bfloat16 hi = __float2bfloat16(v);
        dst[c * LDV + m] = hi;
        dst[DV * LDV + c * LDV + m] = __float2bfloat16(v - __bfloat162float(hi));
    }
}

// ---------------- flash kernel ----------------
// smem (halves): Qhi[128x136]@0, Qlo@17408, K bufs @34816 (2x8704),
// V bufs @52224 (2x20480). total 93184 halves = 186368 B.
#define SQHI 0
#define SQLO 17408
#define SK0  34816
#define SV0  52224
#define KBUF 8704
#define VBUF 20480
#define SM_BYTES 186368

__global__ __launch_bounds__(256, 1) void flash_kernel(
    const float* __restrict__ xin, const float* __restrict__ gamma_p,
    float* __restrict__ yout)
{
    extern __shared__ __nv_bfloat16 sm[];
    const uint32_t sb = smem_u32(sm);
    const int t = threadIdx.x, lane = t & 31, wid = t >> 5;
    const int qt = blockIdx.x, b = blockIdx.y;
    const int n0 = qt * BM;
    const int lg = lane >> 3, lr = lane & 7;
    const uint32_t qa_base = (uint32_t)((16 * wid + lr + (lg & 1) * 8) * LDQ + (lg >> 1) * 8);
    const uint32_t kb_base = (uint32_t)(lr * LDQ + lg * 8);
    const uint32_t vb_base = (uint32_t)(lr * LDV + lg * 8);

    const uint4* kimg = (const uint4*)(g_kimg + (size_t)b * 128 * (2 * BN * LDQ));
    const uint4* vimg = (const uint4*)(g_vimg + (size_t)b * 128 * (2 * DV * LDV));

    // Q tile: 4352 uint4 linear copy
    {
        const uint4* src = (const uint4*)(g_qimg + (size_t)(b * 32 + qt) * (2 * BM * LDQ));
        uint4* dst = (uint4*)sm;
#pragma unroll
        for (int i = 0; i < 17; i++) dst[t + i * 256] = src[t + i * 256];
    }

    // prefetch tile 0
    {
        uint32_t kd = sb + 2 * SK0;
        uint32_t vd = sb + 2 * SV0;
        const uint4* ks = kimg;
        const uint4* vs = vimg;
#pragma unroll
        for (int i = 0; i < 5; i++) {
            int j = t + i * 256;
            if (j < 1088) cp16(kd + 16 * j, ks + j);
        }
#pragma unroll
        for (int i = 0; i < 10; i++) {
            int j = t + i * 256;
            cp16(vd + 16 * j, vs + j);
        }
        CP_COMMIT();
    }

    float oacc[32][4];
#pragma unroll
    for (int nf = 0; nf < 32; nf++)
#pragma unroll
        for (int e = 0; e < 4; e++) oacc[nf][e] = 0.f;
    float lsum0 = 0.f, lsum1 = 0.f;

    for (int kt = 0; kt < NKT; kt++) {
        const int buf = kt & 1;
        if (kt + 1 < NKT) {   // prefetch next into other buffer
            uint32_t kd = sb + 2 * (SK0 + (buf ^ 1) * KBUF);
            uint32_t vd = sb + 2 * (SV0 + (buf ^ 1) * VBUF);
            const uint4* ks = kimg + (size_t)(kt + 1) * 1088;
            const uint4* vs = vimg + (size_t)(kt + 1) * 2560;
#pragma unroll
            for (int i = 0; i < 5; i++) {
                int j = t + i * 256;
                if (j < 1088) cp16(kd + 16 * j, ks + j);
            }
#pragma unroll
            for (int i = 0; i < 10; i++) {
                int j = t + i * 256;
                cp16(vd + 16 * j, vs + j);
            }
            CP_COMMIT();
            CP_WAIT(1);
        } else {
            CP_WAIT(0);
        }
        __syncthreads();

        const uint32_t khi = SK0 + buf * KBUF;
        const uint32_t klo = khi + 32 * LDQ;
        const uint32_t vhi = SV0 + buf * VBUF;
        const uint32_t vlo = vhi + DV * LDV;

        // ---- S = Q K^T (3-term split) ----
        float sacc[4][4];
#pragma unroll
        for (int nn = 0; nn < 4; nn++)
#pragma unroll
            for (int e = 0; e < 4; e++) sacc[nn][e] = 0.f;
#pragma unroll
        for (int kkp = 0; kkp < 4; kkp++) {
            uint32_t qh0[4], qh1[4], ql0[4], ql1[4];
            ldsm_x4(qh0, sb + 2 * (SQHI + qa_base + 32 * kkp));
            ldsm_x4(qh1, sb + 2 * (SQHI + qa_base + 32 * kkp + 16));
            ldsm_x4(ql0, sb + 2 * (SQLO + qa_base + 32 * kkp));
            ldsm_x4(ql1, sb + 2 * (SQLO + qa_base + 32 * kkp + 16));
#pragma unroll
            for (int nn = 0; nn < 4; nn++) {
                uint32_t kh[4], kl[4];
                ldsm_x4(kh, sb + 2 * (khi + kb_base + nn * 8 * LDQ + 32 * kkp));
                ldsm_x4(kl, sb + 2 * (klo + kb_base + nn * 8 * LDQ + 32 * kkp));
                mma_bf16(sacc[nn], qh0, kh);
                mma_bf16(sacc[nn], qh1, kh + 2);
                mma_bf16(sacc[nn], qh0, kl);
                mma_bf16(sacc[nn], qh1, kl + 2);
                mma_bf16(sacc[nn], ql0, kh);
                mma_bf16(sacc[nn], ql1, kh + 2);
            }
        }

        // ---- P = exp(S), row sums, pack A-frags ----
        float pex[4][4];
#pragma unroll
        for (int nn = 0; nn < 4; nn++) {
#pragma unroll
            for (int e = 0; e < 4; e++) pex[nn][e] = __expf(sacc[nn][e]);
            lsum0 += pex[nn][0] + pex[nn][1];
            lsum1 += pex[nn][2] + pex[nn][3];
        }
        uint32_t phi[2][4], plo[2][4];
#pragma unroll
        for (int kk = 0; kk < 2; kk++)
#pragma unroll
            for (int half = 0; half < 2; half++) {
                const float* p = pex[2 * kk + half];
                __nv_bfloat16 h0 = __float2bfloat16(p[0]);
                __nv_bfloat16 h1 = __float2bfloat16(p[1]);
                __nv_bfloat16 h2 = __float2bfloat16(p[2]);
                __nv_bfloat16 h3 = __float2bfloat16(p[3]);
                phi[kk][2 * half + 0] = packbf2(h0, h1);
                phi[kk][2 * half + 1] = packbf2(h2, h3);
                plo[kk][2 * half + 0] = packbf2(
                    __float2bfloat16(p[0] - __bfloat162float(h0)),
                    __float2bfloat16(p[1] - __bfloat162float(h1)));
                plo[kk][2 * half + 1] = packbf2(
                    __float2bfloat16(p[2] - __bfloat162float(h2)),
                    __float2bfloat16(p[3] - __bfloat162float(h3)));
            }

        // ---- O += P V (3-term split), all 256 channels ----
#pragma unroll
        for (int nf = 0; nf < 32; nf++) {
            uint32_t vh[4], vl[4];
            ldsm_x4(vh, sb + 2 * (vhi + vb_base + nf * 8 * LDV));
            ldsm_x4(vl, sb + 2 * (vlo + vb_base + nf * 8 * LDV));
#pragma unroll
            for (int kk = 0; kk < 2; kk++) {
                mma_bf16(oacc[nf], phi[kk], vh + 2 * kk);
                mma_bf16(oacc[nf], phi[kk], vl + 2 * kk);
                mma_bf16(oacc[nf], plo[kk], vh + 2 * kk);
            }
        }
        __syncthreads();   // everyone done reading buf before it is refilled
    }

    // ---- epilogue: y = gamma*(O/l) + x (flat [b][c][n]) ----
    lsum0 += __shfl_xor_sync(0xffffffffu, lsum0, 1);
    lsum0 += __shfl_xor_sync(0xffffffffu, lsum0, 2);
    lsum1 += __shfl_xor_sync(0xffffffffu, lsum1, 1);
    lsum1 += __shfl_xor_sync(0xffffffffu, lsum1, 2);
    const float g = gamma_p[0];
    const float s0 = g / lsum0, s1 = g / lsum1;
    const float* xb = xin  + (size_t)b * DV * NTOK;
    float*       yb = yout + (size_t)b * DV * NTOK;
    const int r0 = n0 + 16 * wid + (lane >> 2);
#pragma unroll
    for (int nf = 0; nf < 32; nf++) {
        const int c = nf * 8 + 2 * (lane & 3);
        size_t i00 = (size_t)c * NTOK + r0;          // (c,   r0)
        size_t i10 = i00 + NTOK;                      // (c+1, r0)
        yb[i00]     = oacc[nf][0] * s0 + xb[i00];
        yb[i10]     = oacc[nf][1] * s0 + xb[i10];
        yb[i00 + 8] = oacc[nf][2] * s1 + xb[i00 + 8];   // (c,   r0+8)
        yb[i10 + 8] = oacc[nf][3] * s1 + xb[i10 + 8];   // (c+1, r0+8)
    }
}

// ---------------- launch ----------------
extern "C" void kernel_launch(void* const* d_in, const int* in_sizes, int n_in,
                              void* d_out, int out_size)
{
    const float* x     = (const float*)d_in[0];
    const float* Wq    = (const float*)d_in[1];
    const float* bq    = (const float*)d_in[2];
    const float* Wk    = (const float*)d_in[3];
    const float* bk    = (const float*)d_in[4];
    const float* Wv    = (const float*)d_in[5];
    const float* bv    = (const float*)d_in[6];
    const float* gamma = (const float*)d_in[7];
    float* out = (float*)d_out;

    float *qbuf, *kbuf;
    __nv_bfloat16 *qimg, *kimg;
    cudaGetSymbolAddress((void**)&qbuf, g_q);
    cudaGetSymbolAddress((void**)&kbuf, g_k);
    cudaGetSymbolAddress((void**)&qimg, g_qimg);
    cudaGetSymbolAddress((void**)&kimg, g_kimg);

    // 1) operand prep for projection GEMM
    prep_x_kernel<<<BATCH * NTOK * 256 / 512, 256>>>(x);
    prep_w_kernel<<<512, 256>>>(Wq, bq, Wk, bk, Wv, bv);

    // 2) fused tensorized projections q|k|v
    cudaFuncSetAttribute(gemm_tensor_kernel,
                         cudaFuncAttributeMaxDynamicSharedMemorySize, GSM_BYTES);
    gemm_tensor_kernel<<<dim3(4, BATCH * NTOK / 128), 256, GSM_BYTES>>>();

    // 3) flash tile images
    prep_qk_kernel<<<dim3(32, BATCH), 128>>>(qbuf, qimg, BM, 32);
    prep_qk_kernel<<<dim3(128, BATCH), 128>>>(kbuf, kimg, BN, 128);
    prep_v_kernel<<<dim3(128, BATCH), 256>>>();

    // 4) flash attention + fused residual
    cudaFuncSetAttribute(flash_kernel,
                         cudaFuncAttributeMaxDynamicSharedMemorySize, SM_BYTES);
    flash_kernel<<<dim3(NTOK / BM, BATCH), 256, SM_BYTES>>>(x, gamma, out);
}

// round 5
// speedup vs baseline: 3.0071x; 1.1106x over previous
#include <cuda_runtime.h>
#include <cuda_bf16.h>
#include <cstdint>

// B=4, N=4096 tok/batch, d_qk=128, d_v=256.  All reference reshapes are flat
// reinterprets => attention indexes flat projection buffers as [c][n]; output
// stored [b][c][n] flat makes the final reshape+residual elementwise.
//
// Round-5 changes (vs 723us):
//  * tile ingest via cp.async.bulk + mbarrier (cp.async 16B was issue-bound at
//    ~8B/cyc/SM and dominated the flash kernel)
//  * projection GEMM operands re-laid-out as padded linear tiles -> bulk copies
//  * S accumulator split into 2 banks (shorter MMA dependency chains)
//  * coalesced prep_qk (smem transpose) and flash epilogue (smem transpose)

#define NTOK  4096
#define DQK   128
#define DV    256
#define BATCH 4
#define BM    128
#define BN    32
#define NKT   (NTOK / BN)
#define LDQ   136
#define LDV   40

// -------- device scratch (no allocations allowed) --------
__device__ float g_q[BATCH * NTOK * DQK];
__device__ float g_k[BATCH * NTOK * DQK];
__device__ float g_v[BATCH * NTOK * DV];
// projection GEMM operand images: padded rows of 72 halves (64 data + 8 pad),
// grouped per 64-ch k-step so each tile is one linear bulk copy.
__device__ __align__(16) __nv_bfloat16 g_xhi[4 * BATCH * NTOK * 72];
__device__ __align__(16) __nv_bfloat16 g_xlo[4 * BATCH * NTOK * 72];
__device__ __align__(16) __nv_bfloat16 g_whi[4 * 512 * 72];
__device__ __align__(16) __nv_bfloat16 g_wlo[4 * 512 * 72];
__device__ float g_bias[512];
// flash images (padded linear; one bulk copy per tile)
__device__ __align__(16) __nv_bfloat16 g_qimg[BATCH * 32 * 2 * BM * LDQ];
__device__ __align__(16) __nv_bfloat16 g_kimg[BATCH * 128 * 2 * BN * LDQ];
__device__ __align__(16) __nv_bfloat16 g_vimg[BATCH * 128 * 2 * DV * LDV];

// ---------------- wrappers ----------------
__device__ __forceinline__ uint32_t smem_u32(const void* p) {
    uint32_t a;
    asm("{ .reg .u64 t; cvta.to.shared.u64 t, %1; cvt.u32.u64 %0, t; }" : "=r"(a) : "l"(p));
    return a;
}
__device__ __forceinline__ void ldsm_x4(uint32_t* r, uint32_t saddr) {
    asm volatile("ldmatrix.sync.aligned.m8n8.x4.shared.b16 {%0,%1,%2,%3}, [%4];"
        : "=r"(r[0]), "=r"(r[1]), "=r"(r[2]), "=r"(r[3]) : "r"(saddr));
}
__device__ __forceinline__ void mma_bf16(float* d, const uint32_t* a, const uint32_t* b) {
    asm volatile("mma.sync.aligned.m16n8k16.row.col.f32.bf16.bf16.f32 "
        "{%0,%1,%2,%3}, {%4,%5,%6,%7}, {%8,%9}, {%0,%1,%2,%3};"
        : "+f"(d[0]), "+f"(d[1]), "+f"(d[2]), "+f"(d[3])
        : "r"(a[0]), "r"(a[1]), "r"(a[2]), "r"(a[3]), "r"(b[0]), "r"(b[1]));
}
__device__ __forceinline__ uint32_t packbf2(__nv_bfloat16 x, __nv_bfloat16 y) {
    __nv_bfloat162 t; t.x = x; t.y = y;
    return *reinterpret_cast<uint32_t*>(&t);
}
__device__ __forceinline__ void bulk_cp(uint32_t dst, const void* src,
                                        uint32_t bytes, uint32_t mbar) {
    asm volatile(
        "cp.async.bulk.shared::cta.global.mbarrier::complete_tx::bytes [%0], [%1], %2, [%3];"
        :: "r"(dst), "l"(src), "r"(bytes), "r"(mbar) : "memory");
}
__device__ __forceinline__ void expect_tx(uint32_t mbar, uint32_t bytes) {
    asm volatile("mbarrier.arrive.expect_tx.shared.b64 _, [%0], %1;"
        :: "r"(mbar), "r"(bytes) : "memory");
}
#define MBARRIER_INIT(mbar, cnt) \
    asm volatile("mbarrier.init.shared.b64 [%0], %1;" :: "r"((uint32_t)(mbar)), "r"((uint32_t)(cnt)) : "memory")
#define MBARRIER_WAIT_PARITY(mbar, parity) do { \
    uint32_t _m = (uint32_t)(mbar); uint32_t _p = (uint32_t)(parity); uint32_t _d; \
    asm volatile("{\n\t.reg .pred p;\n\t" \
        "mbarrier.try_wait.parity.acquire.cta.shared::cta.b64 p, [%1], %2;\n\t" \
        "selp.b32 %0, 1, 0, p;\n\t}" : "=r"(_d) : "r"(_m), "r"(_p) : "memory"); \
    if (!_d) { \
        asm volatile("{\n\t.reg .pred P1;\n\t" \
            "WL_%=:\n\t" \
            "mbarrier.try_wait.parity.acquire.cta.shared::cta.b64 P1, [%0], %1, 0x989680;\n\t" \
            "@P1 bra.uni WD_%=;\n\t" \
            "bra.uni WL_%=;\n\t" \
            "WD_%=:\n\t}" :: "r"(_m), "r"(_p) : "memory"); \
    } } while (0)

// ---------------- prep_x: x fp32 -> hi/lo padded k-step images ----------------
__global__ __launch_bounds__(256) void prep_x_kernel(const float* __restrict__ x) {
    size_t i = (size_t)blockIdx.x * 256 + threadIdx.x;    // element index
    int c = (int)(i & 255);
    size_t n = i >> 8;
    float v = x[i];
    __nv_bfloat16 hi = __float2bfloat16(v);
    size_t off = ((size_t)(c >> 6) * (BATCH * NTOK) + n) * 72 + (c & 63);
    g_xhi[off] = hi;
    g_xlo[off] = __float2bfloat16(v - __bfloat162float(hi));
}

// ---------------- prep_w: transpose+split weights, concat bias ----------------
__global__ __launch_bounds__(256) void prep_w_kernel(
    const float* __restrict__ Wq, const float* __restrict__ bq,
    const float* __restrict__ Wk, const float* __restrict__ bk,
    const float* __restrict__ Wv, const float* __restrict__ bv)
{
    const int d = blockIdx.x, c = threadIdx.x;   // d<512, c<256
    float w;
    if (d < 128)      w = Wq[c * 128 + d];
    else if (d < 256) w = Wk[c * 128 + (d - 128)];
    else              w = Wv[c * 256 + (d - 256)];
    __nv_bfloat16 hi = __float2bfloat16(w);
    size_t off = ((size_t)(c >> 6) * 512 + d) * 72 + (c & 63);
    g_whi[off] = hi;
    g_wlo[off] = __float2bfloat16(w - __bfloat162float(hi));
    if (c == 0)
        g_bias[d] = (d < 128) ? bq[d] : (d < 256) ? bk[d - 128] : bv[d - 256];
}

// ---------------- tensorized projection GEMM ----------------
// [16384,256] @ [256,512] + bias.  BM=128 tokens, BN=128 out-ch, BK=64.
// smem tiles filled via 4 bulk copies of 18432 B each (padded rows of 72).
#define GLDA 72
#define GSAHI 0
#define GSALO 9216
#define GSBHI 18432
#define GSBLO 27648
#define GMBAR 73728
#define GSM_BYTES 73760

__global__ __launch_bounds__(256, 2) void gemm_tensor_kernel() {
    extern __shared__ __nv_bfloat16 sg[];
    const uint32_t sb = smem_u32(sg);
    const uint32_t mbar = sb + GMBAR;
    const int t = threadIdx.x, lane = t & 31, wid = t >> 5;
    const int nt = blockIdx.x;
    const int m0 = blockIdx.y * 128;
    const int n0 = nt * 128;
    const int lg = lane >> 3, lr = lane & 7;
    const uint32_t a_base = (uint32_t)((16 * wid + lr + (lg & 1) * 8) * GLDA + (lg >> 1) * 8);
    const uint32_t b_base = (uint32_t)(lr * GLDA + lg * 8);

    if (t == 0) MBARRIER_INIT(mbar, 1);
    __syncthreads();

    float acc[16][4];
#pragma unroll
    for (int nf = 0; nf < 16; nf++)
#pragma unroll
        for (int e = 0; e < 4; e++) acc[nf][e] = 0.f;

    for (int kb = 0; kb < 4; kb++) {
        if (t == 0) {
            expect_tx(mbar, 4 * 18432);
            const size_t aoff = ((size_t)kb * (BATCH * NTOK) + m0) * 72;
            const size_t boff = ((size_t)kb * 512 + n0) * 72;
            bulk_cp(sb + 2 * GSAHI, g_xhi + aoff, 18432, mbar);
            bulk_cp(sb + 2 * GSALO, g_xlo + aoff, 18432, mbar);
            bulk_cp(sb + 2 * GSBHI, g_whi + boff, 18432, mbar);
            bulk_cp(sb + 2 * GSBLO, g_wlo + boff, 18432, mbar);
        }
        MBARRIER_WAIT_PARITY(mbar, kb & 1);
#pragma unroll
        for (int kkp = 0; kkp < 2; kkp++) {
            uint32_t qh0[4], qh1[4], ql0[4], ql1[4];
            ldsm_x4(qh0, sb + 2 * (GSAHI + a_base + 32 * kkp));
            ldsm_x4(qh1, sb + 2 * (GSAHI + a_base + 32 * kkp + 16));
            ldsm_x4(ql0, sb + 2 * (GSALO + a_base + 32 * kkp));
            ldsm_x4(ql1, sb + 2 * (GSALO + a_base + 32 * kkp + 16));
#pragma unroll
            for (int nf = 0; nf < 16; nf++) {
                uint32_t bh[4], bl[4];
                ldsm_x4(bh, sb + 2 * (GSBHI + b_base + nf * 8 * GLDA + 32 * kkp));
                ldsm_x4(bl, sb + 2 * (GSBLO + b_base + nf * 8 * GLDA + 32 * kkp));
                mma_bf16(acc[nf], qh0, bh);
                mma_bf16(acc[nf], qh1, bh + 2);
                mma_bf16(acc[nf], qh0, bl);
                mma_bf16(acc[nf], qh1, bl + 2);
                mma_bf16(acc[nf], ql0, bh);
                mma_bf16(acc[nf], ql1, bh + 2);
            }
        }
        __syncthreads();   // reads done before next bulk overwrites
    }

    float* dst; int doff, Dd;
    if (nt == 0)      { dst = g_q; doff = 0;   Dd = 128; }
    else if (nt == 1) { dst = g_k; doff = 0;   Dd = 128; }
    else              { dst = g_v; doff = (nt - 2) * 128; Dd = 256; }
    const int r0 = m0 + 16 * wid + (lane >> 2);
#pragma unroll
    for (int nf = 0; nf < 16; nf++) {
        const int cg = nf * 8 + 2 * (lane & 3);
        const float b0 = g_bias[n0 + cg], b1 = g_bias[n0 + cg + 1];
        const int dd = doff + cg;
        float2 v0 = {acc[nf][0] + b0, acc[nf][1] + b1};
        float2 v1 = {acc[nf][2] + b0, acc[nf][3] + b1};
        *(float2*)(dst + (size_t)r0 * Dd + dd) = v0;
        *(float2*)(dst + (size_t)(r0 + 8) * Dd + dd) = v1;
    }
}

// ---------------- prep: fp32 -> split bf16 padded images (coalesced) ----------------
__global__ __launch_bounds__(256) void prep_qk_kernel(
    const float* __restrict__ buf, __nv_bfloat16* __restrict__ img, int R, int T)
{
    __shared__ float st[128 * 33];
    const int tile = blockIdx.x, b = blockIdx.y;
    const float* src = buf + (size_t)b * NTOK * DQK;
    __nv_bfloat16* dst = img + (size_t)(b * T + tile) * (2 * R * LDQ);
    const int n0 = tile * R;
    for (int q0 = 0; q0 < R; q0 += 32) {
        __syncthreads();
        for (int i = threadIdx.x; i < 4096; i += 256) {
            int c = i >> 5, m = i & 31;
            st[c * 33 + m] = src[(size_t)c * NTOK + n0 + q0 + m];
        }
        __syncthreads();
        for (int e = threadIdx.x; e < 4096; e += 256) {
            int q = e >> 7, c = e & 127;
            float v = st[c * 33 + q];
            __nv_bfloat16 hi = __float2bfloat16(v);
            dst[(q0 + q) * LDQ + c] = hi;
            dst[R * LDQ + (q0 + q) * LDQ + c] = __float2bfloat16(v - __bfloat162float(hi));
        }
    }
}
__global__ __launch_bounds__(256) void prep_v_kernel()
{
    const int tile = blockIdx.x, b = blockIdx.y, t = threadIdx.x;
    const int m = t & 31;
    const float* src = g_v + (size_t)b * NTOK * DV;
    __nv_bfloat16* dst = g_vimg + (size_t)(b * 128 + tile) * (2 * DV * LDV);
    const int n0 = tile * BN;
    for (int c = (t >> 5); c < DV; c += 8) {
        float v = src[(size_t)c * NTOK + n0 + m];
        __nv_bfloat16 hi = __float2bfloat16(v);
        dst[c * LDV + m] = hi;
        dst[DV * LDV + c * LDV + m] = __float2bfloat16(v - __bfloat162float(hi));
    }
}

// ---------------- flash kernel ----------------
// smem (halves): Qhi[128x136]@0, Qlo@17408, K bufs @34816 (2x8704),
// V bufs @52224 (2x20480).  bytes: mbars @186368, lrow @186432.
// epilogue O transpose reuses [0,135168).
#define SQHI 0
#define SQLO 17408
#define SK0  34816
#define SV0  52224
#define KBUF 8704
#define VBUF 20480
#define MBAR_OFF 186368
#define LROW_OFF 186432
#define OSM_LD 132
#define SM_BYTES 186944
#define TILE_BYTES (2 * KBUF + 2 * VBUF)   // 58368

__global__ __launch_bounds__(256, 1) void flash_kernel(
    const float* __restrict__ xin, const float* __restrict__ gamma_p,
    float* __restrict__ yout)
{
    extern __shared__ __nv_bfloat16 sm[];
    const uint32_t sb = smem_u32(sm);
    const uint32_t mb0 = sb + MBAR_OFF, mb1 = sb + MBAR_OFF + 8;
    const int t = threadIdx.x, lane = t & 31, wid = t >> 5;
    const int qt = blockIdx.x, b = blockIdx.y;
    const int n0 = qt * BM;
    const int lg = lane >> 3, lr = lane & 7;
    const uint32_t qa_base = (uint32_t)((16 * wid + lr + (lg & 1) * 8) * LDQ + (lg >> 1) * 8);
    const uint32_t kb_base = (uint32_t)(lr * LDQ + lg * 8);
    const uint32_t vb_base = (uint32_t)(lr * LDV + lg * 8);

    const __nv_bfloat16* kimg = g_kimg + (size_t)b * 128 * (size_t)(2 * BN * LDQ);
    const __nv_bfloat16* vimg = g_vimg + (size_t)b * 128 * (size_t)(2 * DV * LDV);

    if (t == 0) { MBARRIER_INIT(mb0, 1); MBARRIER_INIT(mb1, 1); }
    __syncthreads();
    if (t == 0) {
        // tile 0 (+ Q image) on mb0
        expect_tx(mb0, TILE_BYTES + 2 * 2 * BM * LDQ);
        bulk_cp(sb, g_qimg + (size_t)(b * 32 + qt) * (2 * BM * LDQ),
                2 * 2 * BM * LDQ, mb0);
        bulk_cp(sb + 2 * SK0, kimg, 2 * KBUF, mb0);
        bulk_cp(sb + 2 * SV0, vimg, 2 * VBUF, mb0);
        // tile 1 on mb1
        expect_tx(mb1, TILE_BYTES);
        bulk_cp(sb + 2 * (SK0 + KBUF), kimg + KBUF, 2 * KBUF, mb1);
        bulk_cp(sb + 2 * (SV0 + VBUF), vimg + VBUF, 2 * VBUF, mb1);
    }

    float oacc[32][4];
#pragma unroll
    for (int nf = 0; nf < 32; nf++)
#pragma unroll
        for (int e = 0; e < 4; e++) oacc[nf][e] = 0.f;
    float lsum0 = 0.f, lsum1 = 0.f;

    for (int kt = 0; kt < NKT; kt++) {
        const int buf = kt & 1;
        MBARRIER_WAIT_PARITY(buf ? mb1 : mb0, (kt >> 1) & 1);

        const uint32_t khi = SK0 + buf * KBUF;
        const uint32_t klo = khi + 32 * LDQ;
        const uint32_t vhi = SV0 + buf * VBUF;
        const uint32_t vlo = vhi + DV * LDV;

        // ---- S = Q K^T (3-term split, 2 accumulator banks) ----
        float sa[4][4], sc[4][4];
#pragma unroll
        for (int nn = 0; nn < 4; nn++)
#pragma unroll
            for (int e = 0; e < 4; e++) { sa[nn][e] = 0.f; sc[nn][e] = 0.f; }
#pragma unroll
        for (int kkp = 0; kkp < 4; kkp++) {
            uint32_t qh0[4], qh1[4], ql0[4], ql1[4];
            ldsm_x4(qh0, sb + 2 * (SQHI + qa_base + 32 * kkp));
            ldsm_x4(qh1, sb + 2 * (SQHI + qa_base + 32 * kkp + 16));
            ldsm_x4(ql0, sb + 2 * (SQLO + qa_base + 32 * kkp));
            ldsm_x4(ql1, sb + 2 * (SQLO + qa_base + 32 * kkp + 16));
#pragma unroll
            for (int nn = 0; nn < 4; nn++) {
                uint32_t kh[4], kl[4];
                ldsm_x4(kh, sb + 2 * (khi + kb_base + nn * 8 * LDQ + 32 * kkp));
                ldsm_x4(kl, sb + 2 * (klo + kb_base + nn * 8 * LDQ + 32 * kkp));
                mma_bf16(sa[nn], qh0, kh);       // hi*hi bank
                mma_bf16(sa[nn], qh1, kh + 2);
                mma_bf16(sc[nn], qh0, kl);       // correction bank
                mma_bf16(sc[nn], qh1, kl + 2);
                mma_bf16(sc[nn], ql0, kh);
                mma_bf16(sc[nn], ql1, kh + 2);
            }
        }

        // ---- P = exp(S), row sums, pack A-frags ----
        float pex[4][4];
#pragma unroll
        for (int nn = 0; nn < 4; nn++) {
#pragma unroll
            for (int e = 0; e < 4; e++) pex[nn][e] = __expf(sa[nn][e] + sc[nn][e]);
            lsum0 += pex[nn][0] + pex[nn][1];
            lsum1 += pex[nn][2] + pex[nn][3];
        }
        uint32_t phi[2][4], plo[2][4];
#pragma unroll
        for (int kk = 0; kk < 2; kk++)
#pragma unroll
            for (int half = 0; half < 2; half++) {
                const float* p = pex[2 * kk + half];
                __nv_bfloat16 h0 = __float2bfloat16(p[0]);
                __nv_bfloat16 h1 = __float2bfloat16(p[1]);
                __nv_bfloat16 h2 = __float2bfloat16(p[2]);
                __nv_bfloat16 h3 = __float2bfloat16(p[3]);
                phi[kk][2 * half + 0] = packbf2(h0, h1);
                phi[kk][2 * half + 1] = packbf2(h2, h3);
                plo[kk][2 * half + 0] = packbf2(
                    __float2bfloat16(p[0] - __bfloat162float(h0)),
                    __float2bfloat16(p[1] - __bfloat162float(h1)));
                plo[kk][2 * half + 1] = packbf2(
                    __float2bfloat16(p[2] - __bfloat162float(h2)),
                    __float2bfloat16(p[3] - __bfloat162float(h3)));
            }

        // ---- O += P V (3-term split), all 256 channels ----
#pragma unroll
        for (int nf = 0; nf < 32; nf++) {
            uint32_t vh[4], vl[4];
            ldsm_x4(vh, sb + 2 * (vhi + vb_base + nf * 8 * LDV));
            ldsm_x4(vl, sb + 2 * (vlo + vb_base + nf * 8 * LDV));
#pragma unroll
            for (int kk = 0; kk < 2; kk++) {
                mma_bf16(oacc[nf], phi[kk], vh + 2 * kk);
                mma_bf16(oacc[nf], phi[kk], vl + 2 * kk);
                mma_bf16(oacc[nf], plo[kk], vh + 2 * kk);
            }
        }
        __syncthreads();   // all reads of buf done before refill
        if (t == 0 && kt + 2 < NKT) {
            const uint32_t mb = buf ? mb1 : mb0;
            expect_tx(mb, TILE_BYTES);
            bulk_cp(sb + 2 * (SK0 + buf * KBUF),
                    kimg + (size_t)(kt + 2) * KBUF, 2 * KBUF, mb);
            bulk_cp(sb + 2 * (SV0 + buf * VBUF),
                    vimg + (size_t)(kt + 2) * VBUF, 2 * VBUF, mb);
        }
    }

    // ---- epilogue: transpose O through smem, y = gamma*(O/l) + x ----
    lsum0 += __shfl_xor_sync(0xffffffffu, lsum0, 1);
    lsum0 += __shfl_xor_sync(0xffffffffu, lsum0, 2);
    lsum1 += __shfl_xor_sync(0xffffffffu, lsum1, 1);
    lsum1 += __shfl_xor_sync(0xffffffffu, lsum1, 2);
    float* Osm = (float*)sm;
    float* lrow = (float*)((char*)sm + LROW_OFF);
    const int rloc = 16 * wid + (lane >> 2);
    if ((lane & 3) == 0) { lrow[rloc] = lsum0; lrow[rloc + 8] = lsum1; }
#pragma unroll
    for (int nf = 0; nf < 32; nf++) {
        const int c = nf * 8 + 2 * (lane & 3);
        Osm[c * OSM_LD + rloc] = oacc[nf][0];
        Osm[(c + 1) * OSM_LD + rloc] = oacc[nf][1];
        Osm[c * OSM_LD + rloc + 8] = oacc[nf][2];
        Osm[(c + 1) * OSM_LD + rloc + 8] = oacc[nf][3];
    }
    __syncthreads();
    if (t < 128) lrow[t] = gamma_p[0] / lrow[t];
    __syncthreads();
    const float* xb = xin  + (size_t)b * DV * NTOK;
    float*       yb = yout + (size_t)b * DV * NTOK;
    for (int i = t; i < 256 * 32; i += 256) {
        const int c = i >> 5, nn = (i & 31) << 2;
        float4 o = *(float4*)&Osm[c * OSM_LD + nn];
        size_t gi = (size_t)c * NTOK + n0 + nn;
        float4 xv = *(const float4*)(xb + gi);
        float4 y;
        y.x = o.x * lrow[nn + 0] + xv.x;
        y.y = o.y * lrow[nn + 1] + xv.y;
        y.z = o.z * lrow[nn + 2] + xv.z;
        y.w = o.w * lrow[nn + 3] + xv.w;
        *(float4*)(yb + gi) = y;
    }
}

// ---------------- launch ----------------
extern "C" void kernel_launch(void* const* d_in, const int* in_sizes, int n_in,
                              void* d_out, int out_size)
{
    const float* x     = (const float*)d_in[0];
    const float* Wq    = (const float*)d_in[1];
    const float* bq    = (const float*)d_in[2];
    const float* Wk    = (const float*)d_in[3];
    const float* bk    = (const float*)d_in[4];
    const float* Wv    = (const float*)d_in[5];
    const float* bv    = (const float*)d_in[6];
    const float* gamma = (const float*)d_in[7];
    float* out = (float*)d_out;

    float *qbuf, *kbuf;
    __nv_bfloat16 *qimg, *kimg;
    cudaGetSymbolAddress((void**)&qbuf, g_q);
    cudaGetSymbolAddress((void**)&kbuf, g_k);
    cudaGetSymbolAddress((void**)&qimg, g_qimg);
    cudaGetSymbolAddress((void**)&kimg, g_kimg);

    prep_x_kernel<<<BATCH * NTOK, 256>>>(x);
    prep_w_kernel<<<512, 256>>>(Wq, bq, Wk, bk, Wv, bv);

    cudaFuncSetAttribute(gemm_tensor_kernel,
                         cudaFuncAttributeMaxDynamicSharedMemorySize, GSM_BYTES);
    gemm_tensor_kernel<<<dim3(4, BATCH * NTOK / 128), 256, GSM_BYTES>>>();

    prep_qk_kernel<<<dim3(32, BATCH), 256>>>(qbuf, qimg, BM, 32);
    prep_qk_kernel<<<dim3(128, BATCH), 256>>>(kbuf, kimg, BN, 128);
    prep_v_kernel<<<dim3(128, BATCH), 256>>>();

    cudaFuncSetAttribute(flash_kernel,
                         cudaFuncAttributeMaxDynamicSharedMemorySize, SM_BYTES);
    flash_kernel<<<dim3(NTOK / BM, BATCH), 256, SM_BYTES>>>(x, gamma, out);
}

// round 7
// speedup vs baseline: 4.3463x; 1.4454x over previous
#include <cuda_runtime.h>
#include <cuda_bf16.h>
#include <cstdint>

// B=4, N=4096 tok/batch, d_qk=128, d_v=256.
// IMPORTANT semantics note (round-6 lesson): the reference's reshape is a flat
// reinterpret of TOKEN-MAJOR projection buffers: pq[c][n] = q_flat[c*4096+n],
// i.e. attention channel c = token>>5 and attention position mixes token&31
// with proj channel. The prep kernels below implement that mapping by reading
// src[c*NTOK + n] from token-major q/k/v. Do NOT fuse image writes into the
// projection GEMM epilogue (attention tiles span 32 GEMM CTAs).
//
// Round-7 (vs 651us round-5 baseline, which this reverts to):
//  * PV uses 2-term split (phi*Vhi + plo*Vhi): V-lo image deleted.
//    -22% MMAs, -29% ldsm, V smem/traffic halved. Costs ~3e-4 rel_err
//    (V bf16 quantization), still well under 1e-3. S keeps 3 terms.

#define NTOK  4096
#define DQK   128
#define DV    256
#define BATCH 4
#define BM    128
#define BN    32
#define NKT   (NTOK / BN)
#define LDQ   136
#define LDV   40

// -------- device scratch (no allocations allowed) --------
__device__ float g_q[BATCH * NTOK * DQK];
__device__ float g_k[BATCH * NTOK * DQK];
__device__ float g_v[BATCH * NTOK * DV];
__device__ __align__(16) __nv_bfloat16 g_xhi[4 * BATCH * NTOK * 72];
__device__ __align__(16) __nv_bfloat16 g_xlo[4 * BATCH * NTOK * 72];
__device__ __align__(16) __nv_bfloat16 g_whi[4 * 512 * 72];
__device__ __align__(16) __nv_bfloat16 g_wlo[4 * 512 * 72];
__device__ float g_bias[512];
__device__ __align__(16) __nv_bfloat16 g_qimg[BATCH * 32 * 2 * BM * LDQ];
__device__ __align__(16) __nv_bfloat16 g_kimg[BATCH * 128 * 2 * BN * LDQ];
__device__ __align__(16) __nv_bfloat16 g_vimg[BATCH * 128 * DV * LDV];   // hi only

// ---------------- wrappers ----------------
__device__ __forceinline__ uint32_t smem_u32(const void* p) {
    uint32_t a;
    asm("{ .reg .u64 t; cvta.to.shared.u64 t, %1; cvt.u32.u64 %0, t; }" : "=r"(a) : "l"(p));
    return a;
}
__device__ __forceinline__ void ldsm_x4(uint32_t* r, uint32_t saddr) {
    asm volatile("ldmatrix.sync.aligned.m8n8.x4.shared.b16 {%0,%1,%2,%3}, [%4];"
        : "=r"(r[0]), "=r"(r[1]), "=r"(r[2]), "=r"(r[3]) : "r"(saddr));
}
__device__ __forceinline__ void mma_bf16(float* d, const uint32_t* a, const uint32_t* b) {
    asm volatile("mma.sync.aligned.m16n8k16.row.col.f32.bf16.bf16.f32 "
        "{%0,%1,%2,%3}, {%4,%5,%6,%7}, {%8,%9}, {%0,%1,%2,%3};"
        : "+f"(d[0]), "+f"(d[1]), "+f"(d[2]), "+f"(d[3])
        : "r"(a[0]), "r"(a[1]), "r"(a[2]), "r"(a[3]), "r"(b[0]), "r"(b[1]));
}
__device__ __forceinline__ uint32_t packbf2(__nv_bfloat16 x, __nv_bfloat16 y) {
    __nv_bfloat162 t; t.x = x; t.y = y;
    return *reinterpret_cast<uint32_t*>(&t);
}
__device__ __forceinline__ void bulk_cp(uint32_t dst, const void* src,
                                        uint32_t bytes, uint32_t mbar) {
    asm volatile(
        "cp.async.bulk.shared::cta.global.mbarrier::complete_tx::bytes [%0], [%1], %2, [%3];"
        :: "r"(dst), "l"(src), "r"(bytes), "r"(mbar) : "memory");
}
__device__ __forceinline__ void expect_tx(uint32_t mbar, uint32_t bytes) {
    asm volatile("mbarrier.arrive.expect_tx.shared.b64 _, [%0], %1;"
        :: "r"(mbar), "r"(bytes) : "memory");
}
#define MBARRIER_INIT(mbar, cnt) \
    asm volatile("mbarrier.init.shared.b64 [%0], %1;" :: "r"((uint32_t)(mbar)), "r"((uint32_t)(cnt)) : "memory")
#define MBARRIER_WAIT_PARITY(mbar, parity) do { \
    uint32_t _m = (uint32_t)(mbar); uint32_t _p = (uint32_t)(parity); uint32_t _d; \
    asm volatile("{\n\t.reg .pred p;\n\t" \
        "mbarrier.try_wait.parity.acquire.cta.shared::cta.b64 p, [%1], %2;\n\t" \
        "selp.b32 %0, 1, 0, p;\n\t}" : "=r"(_d) : "r"(_m), "r"(_p) : "memory"); \
    if (!_d) { \
        asm volatile("{\n\t.reg .pred P1;\n\t" \
            "WL_%=:\n\t" \
            "mbarrier.try_wait.parity.acquire.cta.shared::cta.b64 P1, [%0], %1, 0x989680;\n\t" \
            "@P1 bra.uni WD_%=;\n\t" \
            "bra.uni WL_%=;\n\t" \
            "WD_%=:\n\t}" :: "r"(_m), "r"(_p) : "memory"); \
    } } while (0)

// ---------------- prep_x ----------------
__global__ __launch_bounds__(256) void prep_x_kernel(const float* __restrict__ x) {
    size_t i = (size_t)blockIdx.x * 256 + threadIdx.x;
    int c = (int)(i & 255);
    size_t n = i >> 8;
    float v = x[i];
    __nv_bfloat16 hi = __float2bfloat16(v);
    size_t off = ((size_t)(c >> 6) * (BATCH * NTOK) + n) * 72 + (c & 63);
    g_xhi[off] = hi;
    g_xlo[off] = __float2bfloat16(v - __bfloat162float(hi));
}

// ---------------- prep_w ----------------
__global__ __launch_bounds__(256) void prep_w_kernel(
    const float* __restrict__ Wq, const float* __restrict__ bq,
    const float* __restrict__ Wk, const float* __restrict__ bk,
    const float* __restrict__ Wv, const float* __restrict__ bv)
{
    const int d = blockIdx.x, c = threadIdx.x;
    float w;
    if (d < 128)      w = Wq[c * 128 + d];
    else if (d < 256) w = Wk[c * 128 + (d - 128)];
    else              w = Wv[c * 256 + (d - 256)];
    __nv_bfloat16 hi = __float2bfloat16(w);
    size_t off = ((size_t)(c >> 6) * 512 + d) * 72 + (c & 63);
    g_whi[off] = hi;
    g_wlo[off] = __float2bfloat16(w - __bfloat162float(hi));
    if (c == 0)
        g_bias[d] = (d < 128) ? bq[d] : (d < 256) ? bk[d - 128] : bv[d - 256];
}

// ---------------- tensorized projection GEMM ----------------
#define GLDA 72
#define GSAHI 0
#define GSALO 9216
#define GSBHI 18432
#define GSBLO 27648
#define GMBAR 73728
#define GSM_BYTES 73760

__global__ __launch_bounds__(256, 2) void gemm_tensor_kernel() {
    extern __shared__ __nv_bfloat16 sg[];
    const uint32_t sb = smem_u32(sg);
    const uint32_t mbar = sb + GMBAR;
    const int t = threadIdx.x, lane = t & 31, wid = t >> 5;
    const int nt = blockIdx.x;
    const int m0 = blockIdx.y * 128;
    const int n0 = nt * 128;
    const int lg = lane >> 3, lr = lane & 7;
    const uint32_t a_base = (uint32_t)((16 * wid + lr + (lg & 1) * 8) * GLDA + (lg >> 1) * 8);
    const uint32_t b_base = (uint32_t)(lr * GLDA + lg * 8);

    if (t == 0) MBARRIER_INIT(mbar, 1);
    __syncthreads();

    float acc[16][4];
#pragma unroll
    for (int nf = 0; nf < 16; nf++)
#pragma unroll
        for (int e = 0; e < 4; e++) acc[nf][e] = 0.f;

    for (int kb = 0; kb < 4; kb++) {
        if (t == 0) {
            expect_tx(mbar, 4 * 18432);
            const size_t aoff = ((size_t)kb * (BATCH * NTOK) + m0) * 72;
            const size_t boff = ((size_t)kb * 512 + n0) * 72;
            bulk_cp(sb + 2 * GSAHI, g_xhi + aoff, 18432, mbar);
            bulk_cp(sb + 2 * GSALO, g_xlo + aoff, 18432, mbar);
            bulk_cp(sb + 2 * GSBHI, g_whi + boff, 18432, mbar);
            bulk_cp(sb + 2 * GSBLO, g_wlo + boff, 18432, mbar);
        }
        MBARRIER_WAIT_PARITY(mbar, kb & 1);
#pragma unroll
        for (int kkp = 0; kkp < 2; kkp++) {
            uint32_t qh0[4], qh1[4], ql0[4], ql1[4];
            ldsm_x4(qh0, sb + 2 * (GSAHI + a_base + 32 * kkp));
            ldsm_x4(qh1, sb + 2 * (GSAHI + a_base + 32 * kkp + 16));
            ldsm_x4(ql0, sb + 2 * (GSALO + a_base + 32 * kkp));
            ldsm_x4(ql1, sb + 2 * (GSALO + a_base + 32 * kkp + 16));
#pragma unroll
            for (int nf = 0; nf < 16; nf++) {
                uint32_t bh[4], bl[4];
                ldsm_x4(bh, sb + 2 * (GSBHI + b_base + nf * 8 * GLDA + 32 * kkp));
                ldsm_x4(bl, sb + 2 * (GSBLO + b_base + nf * 8 * GLDA + 32 * kkp));
                mma_bf16(acc[nf], qh0, bh);
                mma_bf16(acc[nf], qh1, bh + 2);
                mma_bf16(acc[nf], qh0, bl);
                mma_bf16(acc[nf], qh1, bl + 2);
                mma_bf16(acc[nf], ql0, bh);
                mma_bf16(acc[nf], ql1, bh + 2);
            }
        }
        __syncthreads();
    }

    float* dst; int doff, Dd;
    if (nt == 0)      { dst = g_q; doff = 0;   Dd = 128; }
    else if (nt == 1) { dst = g_k; doff = 0;   Dd = 128; }
    else              { dst = g_v; doff = (nt - 2) * 128; Dd = 256; }
    const int r0 = m0 + 16 * wid + (lane >> 2);
#pragma unroll
    for (int nf = 0; nf < 16; nf++) {
        const int cg = nf * 8 + 2 * (lane & 3);
        const float b0 = g_bias[n0 + cg], b1 = g_bias[n0 + cg + 1];
        const int dd = doff + cg;
        float2 v0 = {acc[nf][0] + b0, acc[nf][1] + b1};
        float2 v1 = {acc[nf][2] + b0, acc[nf][3] + b1};
        *(float2*)(dst + (size_t)r0 * Dd + dd) = v0;
        *(float2*)(dst + (size_t)(r0 + 8) * Dd + dd) = v1;
    }
}

// ---------------- preps: flat-remap fp32 -> split bf16 images ----------------
__global__ __launch_bounds__(256) void prep_qk_kernel(
    const float* __restrict__ buf, __nv_bfloat16* __restrict__ img, int R, int T)
{
    __shared__ float st[128 * 33];
    const int tile = blockIdx.x, b = blockIdx.y;
    const float* src = buf + (size_t)b * NTOK * DQK;
    __nv_bfloat16* dst = img + (size_t)(b * T + tile) * (2 * R * LDQ);
    const int n0 = tile * R;
    for (int q0 = 0; q0 < R; q0 += 32) {
        __syncthreads();
        for (int i = threadIdx.x; i < 4096; i += 256) {
            int c = i >> 5, m = i & 31;
            st[c * 33 + m] = src[(size_t)c * NTOK + n0 + q0 + m];
        }
        __syncthreads();
        for (int e = threadIdx.x; e < 4096; e += 256) {
            int q = e >> 7, c = e & 127;
            float v = st[c * 33 + q];
            __nv_bfloat16 hi = __float2bfloat16(v);
            dst[(q0 + q) * LDQ + c] = hi;
            dst[R * LDQ + (q0 + q) * LDQ + c] = __float2bfloat16(v - __bfloat162float(hi));
        }
    }
}
__global__ __launch_bounds__(256) void prep_v_kernel()
{
    const int tile = blockIdx.x, b = blockIdx.y, t = threadIdx.x;
    const int m = t & 31;
    const float* src = g_v + (size_t)b * NTOK * DV;
    __nv_bfloat16* dst = g_vimg + (size_t)(b * 128 + tile) * (DV * LDV);
    const int n0 = tile * BN;
    for (int c = (t >> 5); c < DV; c += 8) {
        float v = src[(size_t)c * NTOK + n0 + m];
        dst[c * LDV + m] = __float2bfloat16(v);   // hi only
    }
}

// ---------------- flash kernel ----------------
// smem (halves): Qhi[128x136]@0, Qlo@17408, K bufs @34816 (2x8704 hi+lo),
// V bufs @52224 (2x10240, hi only).  bytes: mbars @145408, lrow @145472.
#define SQHI 0
#define SQLO 17408
#define SK0  34816
#define SV0  52224
#define KBUF 8704
#define VBUF 10240
#define MBAR_OFF 145408
#define LROW_OFF 145472
#define OSM_LD 132
#define SM_BYTES 145984
#define TILE_BYTES (2 * KBUF + 2 * VBUF)   // 37888 bytes (K hi+lo, V hi)

__global__ __launch_bounds__(256, 1) void flash_kernel(
    const float* __restrict__ xin, const float* __restrict__ gamma_p,
    float* __restrict__ yout)
{
    extern __shared__ __nv_bfloat16 sm[];
    const uint32_t sb = smem_u32(sm);
    const uint32_t mb0 = sb + MBAR_OFF, mb1 = sb + MBAR_OFF + 8;
    const int t = threadIdx.x, lane = t & 31, wid = t >> 5;
    const int qt = blockIdx.x, b = blockIdx.y;
    const int n0 = qt * BM;
    const int lg = lane >> 3, lr = lane & 7;
    const uint32_t qa_base = (uint32_t)((16 * wid + lr + (lg & 1) * 8) * LDQ + (lg >> 1) * 8);
    const uint32_t kb_base = (uint32_t)(lr * LDQ + lg * 8);
    const uint32_t vb_base = (uint32_t)(lr * LDV + lg * 8);

    const __nv_bfloat16* kimg = g_kimg + (size_t)b * 128 * (size_t)(2 * BN * LDQ);
    const __nv_bfloat16* vimg = g_vimg + (size_t)b * 128 * (size_t)(DV * LDV);

    if (t == 0) { MBARRIER_INIT(mb0, 1); MBARRIER_INIT(mb1, 1); }
    __syncthreads();
    if (t == 0) {
        expect_tx(mb0, TILE_BYTES + 2 * 2 * BM * LDQ);
        bulk_cp(sb, g_qimg + (size_t)(b * 32 + qt) * (2 * BM * LDQ),
                2 * 2 * BM * LDQ, mb0);
        bulk_cp(sb + 2 * SK0, kimg, 2 * KBUF, mb0);
        bulk_cp(sb + 2 * SV0, vimg, 2 * VBUF, mb0);
        expect_tx(mb1, TILE_BYTES);
        bulk_cp(sb + 2 * (SK0 + KBUF), kimg + KBUF, 2 * KBUF, mb1);
        bulk_cp(sb + 2 * (SV0 + VBUF), vimg + VBUF, 2 * VBUF, mb1);
    }

    float oacc[32][4];
#pragma unroll
    for (int nf = 0; nf < 32; nf++)
#pragma unroll
        for (int e = 0; e < 4; e++) oacc[nf][e] = 0.f;
    float lsum0 = 0.f, lsum1 = 0.f;

    for (int kt = 0; kt < NKT; kt++) {
        const int buf = kt & 1;
        MBARRIER_WAIT_PARITY(buf ? mb1 : mb0, (kt >> 1) & 1);

        const uint32_t khi = SK0 + buf * KBUF;
        const uint32_t klo = khi + 32 * LDQ;
        const uint32_t vhi = SV0 + buf * VBUF;

        // ---- S = Q K^T (3-term split, 2 accumulator banks) ----
        float sa[4][4], sc[4][4];
#pragma unroll
        for (int nn = 0; nn < 4; nn++)
#pragma unroll
            for (int e = 0; e < 4; e++) { sa[nn][e] = 0.f; sc[nn][e] = 0.f; }
#pragma unroll
        for (int kkp = 0; kkp < 4; kkp++) {
            uint32_t qh0[4], qh1[4], ql0[4], ql1[4];
            ldsm_x4(qh0, sb + 2 * (SQHI + qa_base + 32 * kkp));
            ldsm_x4(qh1, sb + 2 * (SQHI + qa_base + 32 * kkp + 16));
            ldsm_x4(ql0, sb + 2 * (SQLO + qa_base + 32 * kkp));
            ldsm_x4(ql1, sb + 2 * (SQLO + qa_base + 32 * kkp + 16));
#pragma unroll
            for (int nn = 0; nn < 4; nn++) {
                uint32_t kh[4], kl[4];
                ldsm_x4(kh, sb + 2 * (khi + kb_base + nn * 8 * LDQ + 32 * kkp));
                ldsm_x4(kl, sb + 2 * (klo + kb_base + nn * 8 * LDQ + 32 * kkp));
                mma_bf16(sa[nn], qh0, kh);
                mma_bf16(sa[nn], qh1, kh + 2);
                mma_bf16(sc[nn], qh0, kl);
                mma_bf16(sc[nn], qh1, kl + 2);
                mma_bf16(sc[nn], ql0, kh);
                mma_bf16(sc[nn], ql1, kh + 2);
            }
        }

        // ---- P = exp(S) (fp32 exact row sums), pack A-frags hi/lo ----
        float pex[4][4];
#pragma unroll
        for (int nn = 0; nn < 4; nn++) {
#pragma unroll
            for (int e = 0; e < 4; e++) pex[nn][e] = __expf(sa[nn][e] + sc[nn][e]);
            lsum0 += pex[nn][0] + pex[nn][1];
            lsum1 += pex[nn][2] + pex[nn][3];
        }
        uint32_t phi[2][4], plo[2][4];
#pragma unroll
        for (int kk = 0; kk < 2; kk++)
#pragma unroll
            for (int half = 0; half < 2; half++) {
                const float* p = pex[2 * kk + half];
                __nv_bfloat16 h0 = __float2bfloat16(p[0]);
                __nv_bfloat16 h1 = __float2bfloat16(p[1]);
                __nv_bfloat16 h2 = __float2bfloat16(p[2]);
                __nv_bfloat16 h3 = __float2bfloat16(p[3]);
                phi[kk][2 * half + 0] = packbf2(h0, h1);
                phi[kk][2 * half + 1] = packbf2(h2, h3);
                plo[kk][2 * half + 0] = packbf2(
                    __float2bfloat16(p[0] - __bfloat162float(h0)),
                    __float2bfloat16(p[1] - __bfloat162float(h1)));
                plo[kk][2 * half + 1] = packbf2(
                    __float2bfloat16(p[2] - __bfloat162float(h2)),
                    __float2bfloat16(p[3] - __bfloat162float(h3)));
            }

        // ---- O += P V (2-term: P hi/lo x V hi), all 256 channels ----
#pragma unroll
        for (int nf = 0; nf < 32; nf++) {
            uint32_t vh[4];
            ldsm_x4(vh, sb + 2 * (vhi + vb_base + nf * 8 * LDV));
#pragma unroll
            for (int kk = 0; kk < 2; kk++) {
                mma_bf16(oacc[nf], phi[kk], vh + 2 * kk);
                mma_bf16(oacc[nf], plo[kk], vh + 2 * kk);
            }
        }
        __syncthreads();
        if (t == 0 && kt + 2 < NKT) {
            const uint32_t mb = buf ? mb1 : mb0;
            expect_tx(mb, TILE_BYTES);
            bulk_cp(sb + 2 * (SK0 + buf * KBUF),
                    kimg + (size_t)(kt + 2) * KBUF, 2 * KBUF, mb);
            bulk_cp(sb + 2 * (SV0 + buf * VBUF),
                    vimg + (size_t)(kt + 2) * VBUF, 2 * VBUF, mb);
        }
    }

    // ---- epilogue: transpose O through smem, y = gamma*(O/l) + x ----
    lsum0 += __shfl_xor_sync(0xffffffffu, lsum0, 1);
    lsum0 += __shfl_xor_sync(0xffffffffu, lsum0, 2);
    lsum1 += __shfl_xor_sync(0xffffffffu, lsum1, 1);
    lsum1 += __shfl_xor_sync(0xffffffffu, lsum1, 2);
    float* Osm = (float*)sm;
    float* lrow = (float*)((char*)sm + LROW_OFF);
    const int rloc = 16 * wid + (lane >> 2);
    if ((lane & 3) == 0) { lrow[rloc] = lsum0; lrow[rloc + 8] = lsum1; }
#pragma unroll
    for (int nf = 0; nf < 32; nf++) {
        const int c = nf * 8 + 2 * (lane & 3);
        Osm[c * OSM_LD + rloc] = oacc[nf][0];
        Osm[(c + 1) * OSM_LD + rloc] = oacc[nf][1];
        Osm[c * OSM_LD + rloc + 8] = oacc[nf][2];
        Osm[(c + 1) * OSM_LD + rloc + 8] = oacc[nf][3];
    }
    __syncthreads();
    if (t < 128) lrow[t] = gamma_p[0] / lrow[t];
    __syncthreads();
    const float* xb = xin  + (size_t)b * DV * NTOK;
    float*       yb = yout + (size_t)b * DV * NTOK;
    for (int i = t; i < 256 * 32; i += 256) {
        const int c = i >> 5, nn = (i & 31) << 2;
        float4 o = *(float4*)&Osm[c * OSM_LD + nn];
        size_t gi = (size_t)c * NTOK + n0 + nn;
        float4 xv = *(const float4*)(xb + gi);
        float4 y;
        y.x = o.x * lrow[nn + 0] + xv.x;
        y.y = o.y * lrow[nn + 1] + xv.y;
        y.z = o.z * lrow[nn + 2] + xv.z;
        y.w = o.w * lrow[nn + 3] + xv.w;
        *(float4*)(yb + gi) = y;
    }
}

// ---------------- launch ----------------
extern "C" void kernel_launch(void* const* d_in, const int* in_sizes, int n_in,
                              void* d_out, int out_size)
{
    const float* x     = (const float*)d_in[0];
    const float* Wq    = (const float*)d_in[1];
    const float* bq    = (const float*)d_in[2];
    const float* Wk    = (const float*)d_in[3];
    const float* bk    = (const float*)d_in[4];
    const float* Wv    = (const float*)d_in[5];
    const float* bv    = (const float*)d_in[6];
    const float* gamma = (const float*)d_in[7];
    float* out = (float*)d_out;

    float *qbuf, *kbuf;
    __nv_bfloat16 *qimg, *kimg;
    cudaGetSymbolAddress((void**)&qbuf, g_q);
    cudaGetSymbolAddress((void**)&kbuf, g_k);
    cudaGetSymbolAddress((void**)&qimg, g_qimg);
    cudaGetSymbolAddress((void**)&kimg, g_kimg);

    prep_x_kernel<<<BATCH * NTOK, 256>>>(x);
    prep_w_kernel<<<512, 256>>>(Wq, bq, Wk, bk, Wv, bv);

    cudaFuncSetAttribute(gemm_tensor_kernel,
                         cudaFuncAttributeMaxDynamicSharedMemorySize, GSM_BYTES);
    gemm_tensor_kernel<<<dim3(4, BATCH * NTOK / 128), 256, GSM_BYTES>>>();

    prep_qk_kernel<<<dim3(32, BATCH), 256>>>(qbuf, qimg, BM, 32);
    prep_qk_kernel<<<dim3(128, BATCH), 256>>>(kbuf, kimg, BN, 128);
    prep_v_kernel<<<dim3(128, BATCH), 256>>>();

    cudaFuncSetAttribute(flash_kernel,
                         cudaFuncAttributeMaxDynamicSharedMemorySize, SM_BYTES);
    flash_kernel<<<dim3(NTOK / BM, BATCH), 256, SM_BYTES>>>(x, gamma, out);
}

// round 8
// speedup vs baseline: 4.9030x; 1.1281x over previous
#include <cuda_runtime.h>
#include <cuda_bf16.h>
#include <cuda_fp16.h>
#include <cstdint>

// B=4, N=4096 tok/batch, d_qk=128, d_v=256.
// Reference reshapes are flat reinterprets of TOKEN-major projection buffers:
// pq[c][n] = q_flat[c*4096+n]; the prep kernels implement that axis-mixing
// (do NOT fuse image writes into the GEMM epilogue — tiles span 32 GEMM CTAs).
//
// Round-8 (vs 450us):
//  * flash adds running row-max normalization => P = exp(S-m) in (0,1] fits
//    fp16. PV becomes single-term fp16 x fp16 (64 MMAs/warp/iter, was 128
//    bf16). V image is fp16 (8x less quantization error than bf16).
//    S path unchanged (3-term bf16). lsum sums the ROUNDED P (convex weights).
//  * prep_qk slab-split: Q prep grid 128 -> 512 blocks.

#define NTOK  4096
#define DQK   128
#define DV    256
#define BATCH 4
#define BM    128
#define BN    32
#define NKT   (NTOK / BN)
#define LDQ   136
#define LDV   40

// -------- device scratch (no allocations allowed) --------
__device__ float g_q[BATCH * NTOK * DQK];
__device__ float g_k[BATCH * NTOK * DQK];
__device__ float g_v[BATCH * NTOK * DV];
__device__ __align__(16) __nv_bfloat16 g_xhi[4 * BATCH * NTOK * 72];
__device__ __align__(16) __nv_bfloat16 g_xlo[4 * BATCH * NTOK * 72];
__device__ __align__(16) __nv_bfloat16 g_whi[4 * 512 * 72];
__device__ __align__(16) __nv_bfloat16 g_wlo[4 * 512 * 72];
__device__ float g_bias[512];
__device__ __align__(16) __nv_bfloat16 g_qimg[BATCH * 32 * 2 * BM * LDQ];
__device__ __align__(16) __nv_bfloat16 g_kimg[BATCH * 128 * 2 * BN * LDQ];
__device__ __align__(16) __half       g_vimg[BATCH * 128 * DV * LDV];   // fp16 hi

// ---------------- wrappers ----------------
__device__ __forceinline__ uint32_t smem_u32(const void* p) {
    uint32_t a;
    asm("{ .reg .u64 t; cvta.to.shared.u64 t, %1; cvt.u32.u64 %0, t; }" : "=r"(a) : "l"(p));
    return a;
}
__device__ __forceinline__ void ldsm_x4(uint32_t* r, uint32_t saddr) {
    asm volatile("ldmatrix.sync.aligned.m8n8.x4.shared.b16 {%0,%1,%2,%3}, [%4];"
        : "=r"(r[0]), "=r"(r[1]), "=r"(r[2]), "=r"(r[3]) : "r"(saddr));
}
__device__ __forceinline__ void mma_bf16(float* d, const uint32_t* a, const uint32_t* b) {
    asm volatile("mma.sync.aligned.m16n8k16.row.col.f32.bf16.bf16.f32 "
        "{%0,%1,%2,%3}, {%4,%5,%6,%7}, {%8,%9}, {%0,%1,%2,%3};"
        : "+f"(d[0]), "+f"(d[1]), "+f"(d[2]), "+f"(d[3])
        : "r"(a[0]), "r"(a[1]), "r"(a[2]), "r"(a[3]), "r"(b[0]), "r"(b[1]));
}
__device__ __forceinline__ void mma_f16(float* d, const uint32_t* a, const uint32_t* b) {
    asm volatile("mma.sync.aligned.m16n8k16.row.col.f32.f16.f16.f32 "
        "{%0,%1,%2,%3}, {%4,%5,%6,%7}, {%8,%9}, {%0,%1,%2,%3};"
        : "+f"(d[0]), "+f"(d[1]), "+f"(d[2]), "+f"(d[3])
        : "r"(a[0]), "r"(a[1]), "r"(a[2]), "r"(a[3]), "r"(b[0]), "r"(b[1]));
}
__device__ __forceinline__ uint32_t packh2(__half x, __half y) {
    __half2 t; t.x = x; t.y = y;
    return *reinterpret_cast<uint32_t*>(&t);
}
__device__ __forceinline__ void bulk_cp(uint32_t dst, const void* src,
                                        uint32_t bytes, uint32_t mbar) {
    asm volatile(
        "cp.async.bulk.shared::cta.global.mbarrier::complete_tx::bytes [%0], [%1], %2, [%3];"
        :: "r"(dst), "l"(src), "r"(bytes), "r"(mbar) : "memory");
}
__device__ __forceinline__ void expect_tx(uint32_t mbar, uint32_t bytes) {
    asm volatile("mbarrier.arrive.expect_tx.shared.b64 _, [%0], %1;"
        :: "r"(mbar), "r"(bytes) : "memory");
}
#define MBARRIER_INIT(mbar, cnt) \
    asm volatile("mbarrier.init.shared.b64 [%0], %1;" :: "r"((uint32_t)(mbar)), "r"((uint32_t)(cnt)) : "memory")
#define MBARRIER_WAIT_PARITY(mbar, parity) do { \
    uint32_t _m = (uint32_t)(mbar); uint32_t _p = (uint32_t)(parity); uint32_t _d; \
    asm volatile("{\n\t.reg .pred p;\n\t" \
        "mbarrier.try_wait.parity.acquire.cta.shared::cta.b64 p, [%1], %2;\n\t" \
        "selp.b32 %0, 1, 0, p;\n\t}" : "=r"(_d) : "r"(_m), "r"(_p) : "memory"); \
    if (!_d) { \
        asm volatile("{\n\t.reg .pred P1;\n\t" \
            "WL_%=:\n\t" \
            "mbarrier.try_wait.parity.acquire.cta.shared::cta.b64 P1, [%0], %1, 0x989680;\n\t" \
            "@P1 bra.uni WD_%=;\n\t" \
            "bra.uni WL_%=;\n\t" \
            "WD_%=:\n\t}" :: "r"(_m), "r"(_p) : "memory"); \
    } } while (0)

// ---------------- prep_x ----------------
__global__ __launch_bounds__(256) void prep_x_kernel(const float* __restrict__ x) {
    size_t i = (size_t)blockIdx.x * 256 + threadIdx.x;
    int c = (int)(i & 255);
    size_t n = i >> 8;
    float v = x[i];
    __nv_bfloat16 hi = __float2bfloat16(v);
    size_t off = ((size_t)(c >> 6) * (BATCH * NTOK) + n) * 72 + (c & 63);
    g_xhi[off] = hi;
    g_xlo[off] = __float2bfloat16(v - __bfloat162float(hi));
}

// ---------------- prep_w ----------------
__global__ __launch_bounds__(256) void prep_w_kernel(
    const float* __restrict__ Wq, const float* __restrict__ bq,
    const float* __restrict__ Wk, const float* __restrict__ bk,
    const float* __restrict__ Wv, const float* __restrict__ bv)
{
    const int d = blockIdx.x, c = threadIdx.x;
    float w;
    if (d < 128)      w = Wq[c * 128 + d];
    else if (d < 256) w = Wk[c * 128 + (d - 128)];
    else              w = Wv[c * 256 + (d - 256)];
    __nv_bfloat16 hi = __float2bfloat16(w);
    size_t off = ((size_t)(c >> 6) * 512 + d) * 72 + (c & 63);
    g_whi[off] = hi;
    g_wlo[off] = __float2bfloat16(w - __bfloat162float(hi));
    if (c == 0)
        g_bias[d] = (d < 128) ? bq[d] : (d < 256) ? bk[d - 128] : bv[d - 256];
}

// ---------------- tensorized projection GEMM ----------------
#define GLDA 72
#define GSAHI 0
#define GSALO 9216
#define GSBHI 18432
#define GSBLO 27648
#define GMBAR 73728
#define GSM_BYTES 73760

__global__ __launch_bounds__(256, 2) void gemm_tensor_kernel() {
    extern __shared__ __nv_bfloat16 sg[];
    const uint32_t sb = smem_u32(sg);
    const uint32_t mbar = sb + GMBAR;
    const int t = threadIdx.x, lane = t & 31, wid = t >> 5;
    const int nt = blockIdx.x;
    const int m0 = blockIdx.y * 128;
    const int n0 = nt * 128;
    const int lg = lane >> 3, lr = lane & 7;
    const uint32_t a_base = (uint32_t)((16 * wid + lr + (lg & 1) * 8) * GLDA + (lg >> 1) * 8);
    const uint32_t b_base = (uint32_t)(lr * GLDA + lg * 8);

    if (t == 0) MBARRIER_INIT(mbar, 1);
    __syncthreads();

    float acc[16][4];
#pragma unroll
    for (int nf = 0; nf < 16; nf++)
#pragma unroll
        for (int e = 0; e < 4; e++) acc[nf][e] = 0.f;

    for (int kb = 0; kb < 4; kb++) {
        if (t == 0) {
            expect_tx(mbar, 4 * 18432);
            const size_t aoff = ((size_t)kb * (BATCH * NTOK) + m0) * 72;
            const size_t boff = ((size_t)kb * 512 + n0) * 72;
            bulk_cp(sb + 2 * GSAHI, g_xhi + aoff, 18432, mbar);
            bulk_cp(sb + 2 * GSALO, g_xlo + aoff, 18432, mbar);
            bulk_cp(sb + 2 * GSBHI, g_whi + boff, 18432, mbar);
            bulk_cp(sb + 2 * GSBLO, g_wlo + boff, 18432, mbar);
        }
        MBARRIER_WAIT_PARITY(mbar, kb & 1);
#pragma unroll
        for (int kkp = 0; kkp < 2; kkp++) {
            uint32_t qh0[4], qh1[4], ql0[4], ql1[4];
            ldsm_x4(qh0, sb + 2 * (GSAHI + a_base + 32 * kkp));
            ldsm_x4(qh1, sb + 2 * (GSAHI + a_base + 32 * kkp + 16));
            ldsm_x4(ql0, sb + 2 * (GSALO + a_base + 32 * kkp));
            ldsm_x4(ql1, sb + 2 * (GSALO + a_base + 32 * kkp + 16));
#pragma unroll
            for (int nf = 0; nf < 16; nf++) {
                uint32_t bh[4], bl[4];
                ldsm_x4(bh, sb + 2 * (GSBHI + b_base + nf * 8 * GLDA + 32 * kkp));
                ldsm_x4(bl, sb + 2 * (GSBLO + b_base + nf * 8 * GLDA + 32 * kkp));
                mma_bf16(acc[nf], qh0, bh);
                mma_bf16(acc[nf], qh1, bh + 2);
                mma_bf16(acc[nf], qh0, bl);
                mma_bf16(acc[nf], qh1, bl + 2);
                mma_bf16(acc[nf], ql0, bh);
                mma_bf16(acc[nf], ql1, bh + 2);
            }
        }
        __syncthreads();
    }

    float* dst; int doff, Dd;
    if (nt == 0)      { dst = g_q; doff = 0;   Dd = 128; }
    else if (nt == 1) { dst = g_k; doff = 0;   Dd = 128; }
    else              { dst = g_v; doff = (nt - 2) * 128; Dd = 256; }
    const int r0 = m0 + 16 * wid + (lane >> 2);
#pragma unroll
    for (int nf = 0; nf < 16; nf++) {
        const int cg = nf * 8 + 2 * (lane & 3);
        const float b0 = g_bias[n0 + cg], b1 = g_bias[n0 + cg + 1];
        const int dd = doff + cg;
        float2 v0 = {acc[nf][0] + b0, acc[nf][1] + b1};
        float2 v1 = {acc[nf][2] + b0, acc[nf][3] + b1};
        *(float2*)(dst + (size_t)r0 * Dd + dd) = v0;
        *(float2*)(dst + (size_t)(r0 + 8) * Dd + dd) = v1;
    }
}

// ---------------- preps: flat-remap fp32 -> operand images ----------------
// one block per 32-row slab of one tile (Q: R=128 -> 4 slabs; K: R=32 -> 1)
__global__ __launch_bounds__(256) void prep_qk_kernel(
    const float* __restrict__ buf, __nv_bfloat16* __restrict__ img, int R, int T)
{
    __shared__ float st[128 * 33];
    const int slabs = R >> 5;
    const int tile = blockIdx.x / slabs;
    const int q0 = (blockIdx.x - tile * slabs) * 32;
    const int b = blockIdx.y;
    const float* src = buf + (size_t)b * NTOK * DQK;
    __nv_bfloat16* dst = img + (size_t)(b * T + tile) * (2 * R * LDQ);
    const int n0 = tile * R;
    for (int i = threadIdx.x; i < 4096; i += 256) {
        int c = i >> 5, m = i & 31;
        st[c * 33 + m] = src[(size_t)c * NTOK + n0 + q0 + m];
    }
    __syncthreads();
    for (int e = threadIdx.x; e < 4096; e += 256) {
        int q = e >> 7, c = e & 127;
        float v = st[c * 33 + q];
        __nv_bfloat16 hi = __float2bfloat16(v);
        dst[(q0 + q) * LDQ + c] = hi;
        dst[R * LDQ + (q0 + q) * LDQ + c] = __float2bfloat16(v - __bfloat162float(hi));
    }
}
__global__ __launch_bounds__(256) void prep_v_kernel()
{
    const int tile = blockIdx.x, b = blockIdx.y, t = threadIdx.x;
    const int m = t & 31;
    const float* src = g_v + (size_t)b * NTOK * DV;
    __half* dst = g_vimg + (size_t)(b * 128 + tile) * (DV * LDV);
    const int n0 = tile * BN;
    for (int c = (t >> 5); c < DV; c += 8) {
        float v = src[(size_t)c * NTOK + n0 + m];
        dst[c * LDV + m] = __float2half_rn(v);
    }
}

// ---------------- flash kernel ----------------
// smem (halves): Qhi[128x136]@0, Qlo@17408, K bufs @34816 (2x8704 hi+lo),
// V bufs @52224 (2x10240 fp16).  bytes: mbars @145408, lrow @145472.
#define SQHI 0
#define SQLO 17408
#define SK0  34816
#define SV0  52224
#define KBUF 8704
#define VBUF 10240
#define MBAR_OFF 145408
#define LROW_OFF 145472
#define OSM_LD 132
#define SM_BYTES 145984
#define TILE_BYTES (2 * KBUF + 2 * VBUF)   // 37888 bytes

__global__ __launch_bounds__(256, 1) void flash_kernel(
    const float* __restrict__ xin, const float* __restrict__ gamma_p,
    float* __restrict__ yout)
{
    extern __shared__ __nv_bfloat16 sm[];
    const uint32_t sb = smem_u32(sm);
    const uint32_t mb0 = sb + MBAR_OFF, mb1 = sb + MBAR_OFF + 8;
    const int t = threadIdx.x, lane = t & 31, wid = t >> 5;
    const int qt = blockIdx.x, b = blockIdx.y;
    const int n0 = qt * BM;
    const int lg = lane >> 3, lr = lane & 7;
    const uint32_t qa_base = (uint32_t)((16 * wid + lr + (lg & 1) * 8) * LDQ + (lg >> 1) * 8);
    const uint32_t kb_base = (uint32_t)(lr * LDQ + lg * 8);
    const uint32_t vb_base = (uint32_t)(lr * LDV + lg * 8);

    const __nv_bfloat16* kimg = g_kimg + (size_t)b * 128 * (size_t)(2 * BN * LDQ);
    const __half* vimg = g_vimg + (size_t)b * 128 * (size_t)(DV * LDV);

    if (t == 0) { MBARRIER_INIT(mb0, 1); MBARRIER_INIT(mb1, 1); }
    __syncthreads();
    if (t == 0) {
        expect_tx(mb0, TILE_BYTES + 2 * 2 * BM * LDQ);
        bulk_cp(sb, g_qimg + (size_t)(b * 32 + qt) * (2 * BM * LDQ),
                2 * 2 * BM * LDQ, mb0);
        bulk_cp(sb + 2 * SK0, kimg, 2 * KBUF, mb0);
        bulk_cp(sb + 2 * SV0, vimg, 2 * VBUF, mb0);
        expect_tx(mb1, TILE_BYTES);
        bulk_cp(sb + 2 * (SK0 + KBUF), kimg + KBUF, 2 * KBUF, mb1);
        bulk_cp(sb + 2 * (SV0 + VBUF), vimg + VBUF, 2 * VBUF, mb1);
    }

    float oacc[32][4];
#pragma unroll
    for (int nf = 0; nf < 32; nf++)
#pragma unroll
        for (int e = 0; e < 4; e++) oacc[nf][e] = 0.f;
    float lsum0 = 0.f, lsum1 = 0.f;
    float m0 = -1e30f, m1 = -1e30f;       // running row maxima

    for (int kt = 0; kt < NKT; kt++) {
        const int buf = kt & 1;
        MBARRIER_WAIT_PARITY(buf ? mb1 : mb0, (kt >> 1) & 1);

        const uint32_t khi = SK0 + buf * KBUF;
        const uint32_t klo = khi + 32 * LDQ;
        const uint32_t vhi = SV0 + buf * VBUF;

        // ---- S = Q K^T (3-term bf16 split, 2 accumulator banks) ----
        float sa[4][4], sc[4][4];
#pragma unroll
        for (int nn = 0; nn < 4; nn++)
#pragma unroll
            for (int e = 0; e < 4; e++) { sa[nn][e] = 0.f; sc[nn][e] = 0.f; }
#pragma unroll
        for (int kkp = 0; kkp < 4; kkp++) {
            uint32_t qh0[4], qh1[4], ql0[4], ql1[4];
            ldsm_x4(qh0, sb + 2 * (SQHI + qa_base + 32 * kkp));
            ldsm_x4(qh1, sb + 2 * (SQHI + qa_base + 32 * kkp + 16));
            ldsm_x4(ql0, sb + 2 * (SQLO + qa_base + 32 * kkp));
            ldsm_x4(ql1, sb + 2 * (SQLO + qa_base + 32 * kkp + 16));
#pragma unroll
            for (int nn = 0; nn < 4; nn++) {
                uint32_t kh[4], kl[4];
                ldsm_x4(kh, sb + 2 * (khi + kb_base + nn * 8 * LDQ + 32 * kkp));
                ldsm_x4(kl, sb + 2 * (klo + kb_base + nn * 8 * LDQ + 32 * kkp));
                mma_bf16(sa[nn], qh0, kh);
                mma_bf16(sa[nn], qh1, kh + 2);
                mma_bf16(sc[nn], qh0, kl);
                mma_bf16(sc[nn], qh1, kl + 2);
                mma_bf16(sc[nn], ql0, kh);
                mma_bf16(sc[nn], ql1, kh + 2);
            }
        }

        // ---- online softmax with running max (P in (0,1] -> fp16) ----
        float sv[4][4];
#pragma unroll
        for (int nn = 0; nn < 4; nn++)
#pragma unroll
            for (int e = 0; e < 4; e++) sv[nn][e] = sa[nn][e] + sc[nn][e];

        float tm0 = -1e30f, tm1 = -1e30f;
#pragma unroll
        for (int nn = 0; nn < 4; nn++) {
            tm0 = fmaxf(tm0, fmaxf(sv[nn][0], sv[nn][1]));
            tm1 = fmaxf(tm1, fmaxf(sv[nn][2], sv[nn][3]));
        }
        tm0 = fmaxf(tm0, __shfl_xor_sync(0xffffffffu, tm0, 1));
        tm0 = fmaxf(tm0, __shfl_xor_sync(0xffffffffu, tm0, 2));
        tm1 = fmaxf(tm1, __shfl_xor_sync(0xffffffffu, tm1, 1));
        tm1 = fmaxf(tm1, __shfl_xor_sync(0xffffffffu, tm1, 2));
        const float mn0 = fmaxf(m0, tm0), mn1 = fmaxf(m1, tm1);
        const float sc0 = __expf(m0 - mn0), sc1 = __expf(m1 - mn1);
        m0 = mn0; m1 = mn1;
        if (sc0 < 1.f) {
            lsum0 *= sc0;
#pragma unroll
            for (int nf = 0; nf < 32; nf++) { oacc[nf][0] *= sc0; oacc[nf][1] *= sc0; }
        }
        if (sc1 < 1.f) {
            lsum1 *= sc1;
#pragma unroll
            for (int nf = 0; nf < 32; nf++) { oacc[nf][2] *= sc1; oacc[nf][3] *= sc1; }
        }

        // P = exp(S - m), fp16 single-term; lsum sums ROUNDED P (convex weights)
        uint32_t phi[2][4];
#pragma unroll
        for (int kk = 0; kk < 2; kk++)
#pragma unroll
            for (int half = 0; half < 2; half++) {
                const float* p = sv[2 * kk + half];
                __half h0 = __float2half_rn(__expf(p[0] - mn0));
                __half h1 = __float2half_rn(__expf(p[1] - mn0));
                __half h2 = __float2half_rn(__expf(p[2] - mn1));
                __half h3 = __float2half_rn(__expf(p[3] - mn1));
                phi[kk][2 * half + 0] = packh2(h0, h1);
                phi[kk][2 * half + 1] = packh2(h2, h3);
                lsum0 += __half2float(h0) + __half2float(h1);
                lsum1 += __half2float(h2) + __half2float(h3);
            }

        // ---- O += P V (single-term fp16), all 256 channels ----
#pragma unroll
        for (int nf = 0; nf < 32; nf++) {
            uint32_t vh[4];
            ldsm_x4(vh, sb + 2 * (vhi + vb_base + nf * 8 * LDV));
            mma_f16(oacc[nf], phi[0], vh);
            mma_f16(oacc[nf], phi[1], vh + 2);
        }
        __syncthreads();
        if (t == 0 && kt + 2 < NKT) {
            const uint32_t mb = buf ? mb1 : mb0;
            expect_tx(mb, TILE_BYTES);
            bulk_cp(sb + 2 * (SK0 + buf * KBUF),
                    kimg + (size_t)(kt + 2) * KBUF, 2 * KBUF, mb);
            bulk_cp(sb + 2 * (SV0 + buf * VBUF),
                    vimg + (size_t)(kt + 2) * VBUF, 2 * VBUF, mb);
        }
    }

    // ---- epilogue: transpose O through smem, y = gamma*(O/l) + x ----
    lsum0 += __shfl_xor_sync(0xffffffffu, lsum0, 1);
    lsum0 += __shfl_xor_sync(0xffffffffu, lsum0, 2);
    lsum1 += __shfl_xor_sync(0xffffffffu, lsum1, 1);
    lsum1 += __shfl_xor_sync(0xffffffffu, lsum1, 2);
    float* Osm = (float*)sm;
    float* lrow = (float*)((char*)sm + LROW_OFF);
    const int rloc = 16 * wid + (lane >> 2);
    if ((lane & 3) == 0) { lrow[rloc] = lsum0; lrow[rloc + 8] = lsum1; }
#pragma unroll
    for (int nf = 0; nf < 32; nf++) {
        const int c = nf * 8 + 2 * (lane & 3);
        Osm[c * OSM_LD + rloc] = oacc[nf][0];
        Osm[(c + 1) * OSM_LD + rloc] = oacc[nf][1];
        Osm[c * OSM_LD + rloc + 8] = oacc[nf][2];
        Osm[(c + 1) * OSM_LD + rloc + 8] = oacc[nf][3];
    }
    __syncthreads();
    if (t < 128) lrow[t] = gamma_p[0] / lrow[t];
    __syncthreads();
    const float* xb = xin  + (size_t)b * DV * NTOK;
    float*       yb = yout + (size_t)b * DV * NTOK;
    for (int i = t; i < 256 * 32; i += 256) {
        const int c = i >> 5, nn = (i & 31) << 2;
        float4 o = *(float4*)&Osm[c * OSM_LD + nn];
        size_t gi = (size_t)c * NTOK + n0 + nn;
        float4 xv = *(const float4*)(xb + gi);
        float4 y;
        y.x = o.x * lrow[nn + 0] + xv.x;
        y.y = o.y * lrow[nn + 1] + xv.y;
        y.z = o.z * lrow[nn + 2] + xv.z;
        y.w = o.w * lrow[nn + 3] + xv.w;
        *(float4*)(yb + gi) = y;
    }
}

// ---------------- launch ----------------
extern "C" void kernel_launch(void* const* d_in, const int* in_sizes, int n_in,
                              void* d_out, int out_size)
{
    const float* x     = (const float*)d_in[0];
    const float* Wq    = (const float*)d_in[1];
    const float* bq    = (const float*)d_in[2];
    const float* Wk    = (const float*)d_in[3];
    const float* bk    = (const float*)d_in[4];
    const float* Wv    = (const float*)d_in[5];
    const float* bv    = (const float*)d_in[6];
    const float* gamma = (const float*)d_in[7];
    float* out = (float*)d_out;

    float *qbuf, *kbuf;
    __nv_bfloat16 *qimg, *kimg;
    cudaGetSymbolAddress((void**)&qbuf, g_q);
    cudaGetSymbolAddress((void**)&kbuf, g_k);
    cudaGetSymbolAddress((void**)&qimg, g_qimg);
    cudaGetSymbolAddress((void**)&kimg, g_kimg);

    prep_x_kernel<<<BATCH * NTOK, 256>>>(x);
    prep_w_kernel<<<512, 256>>>(Wq, bq, Wk, bk, Wv, bv);

    cudaFuncSetAttribute(gemm_tensor_kernel,
                         cudaFuncAttributeMaxDynamicSharedMemorySize, GSM_BYTES);
    gemm_tensor_kernel<<<dim3(4, BATCH * NTOK / 128), 256, GSM_BYTES>>>();

    prep_qk_kernel<<<dim3(32 * 4, BATCH), 256>>>(qbuf, qimg, BM, 32);
    prep_qk_kernel<<<dim3(128, BATCH), 256>>>(kbuf, kimg, BN, 128);
    prep_v_kernel<<<dim3(128, BATCH), 256>>>();

    cudaFuncSetAttribute(flash_kernel,
                         cudaFuncAttributeMaxDynamicSharedMemorySize, SM_BYTES);
    flash_kernel<<<dim3(NTOK / BM, BATCH), 256, SM_BYTES>>>(x, gamma, out);
}

// round 9
// speedup vs baseline: 5.7253x; 1.1677x over previous
#include <cuda_runtime.h>
#include <cuda_bf16.h>
#include <cuda_fp16.h>
#include <cstdint>

// B=4, N=4096 tok/batch, d_qk=128, d_v=256.
// Reference reshapes are flat reinterprets of TOKEN-major projection buffers:
// pq[c][n] = q_flat[c*4096+n]; the prep kernels implement that axis-mixing
// (do NOT fuse image writes into the GEMM epilogue — tiles span 32 GEMM CTAs).
//
// Round-9 (vs 399.5us):
//  * S path goes fp16: Q hi/lo (2-term), K SINGLE fp16 plane.
//    S MMAs 96->64 per warp/iter, K ldsm halved, K tile bytes halved.
//  * projection GEMM goes fp16: x hi/lo, W single fp16. 6->4 MMAs per frag,
//    W-lo image + bulk copy deleted.
//  * PV unchanged from round 8 (P fp16 single-term x V fp16).
// Error model (RSS of K-quant, W-quant paths + existing): ~2.8e-4 < 1e-3.

#define NTOK  4096
#define DQK   128
#define DV    256
#define BATCH 4
#define BM    128
#define BN    32
#define NKT   (NTOK / BN)
#define LDQ   136
#define LDV   40

// -------- device scratch (no allocations allowed) --------
__device__ float g_q[BATCH * NTOK * DQK];
__device__ float g_k[BATCH * NTOK * DQK];
__device__ float g_v[BATCH * NTOK * DV];
__device__ __align__(16) __half g_xhi[4 * BATCH * NTOK * 72];
__device__ __align__(16) __half g_xlo[4 * BATCH * NTOK * 72];
__device__ __align__(16) __half g_whi[4 * 512 * 72];
__device__ float g_bias[512];
__device__ __align__(16) __half g_qimg[BATCH * 32 * 2 * BM * LDQ];   // hi/lo
__device__ __align__(16) __half g_kimg[BATCH * 128 * BN * LDQ];      // hi only
__device__ __align__(16) __half g_vimg[BATCH * 128 * DV * LDV];      // hi only

// ---------------- wrappers ----------------
__device__ __forceinline__ uint32_t smem_u32(const void* p) {
    uint32_t a;
    asm("{ .reg .u64 t; cvta.to.shared.u64 t, %1; cvt.u32.u64 %0, t; }" : "=r"(a) : "l"(p));
    return a;
}
__device__ __forceinline__ void ldsm_x4(uint32_t* r, uint32_t saddr) {
    asm volatile("ldmatrix.sync.aligned.m8n8.x4.shared.b16 {%0,%1,%2,%3}, [%4];"
        : "=r"(r[0]), "=r"(r[1]), "=r"(r[2]), "=r"(r[3]) : "r"(saddr));
}
__device__ __forceinline__ void mma_f16(float* d, const uint32_t* a, const uint32_t* b) {
    asm volatile("mma.sync.aligned.m16n8k16.row.col.f32.f16.f16.f32 "
        "{%0,%1,%2,%3}, {%4,%5,%6,%7}, {%8,%9}, {%0,%1,%2,%3};"
        : "+f"(d[0]), "+f"(d[1]), "+f"(d[2]), "+f"(d[3])
        : "r"(a[0]), "r"(a[1]), "r"(a[2]), "r"(a[3]), "r"(b[0]), "r"(b[1]));
}
__device__ __forceinline__ uint32_t packh2(__half x, __half y) {
    __half2 t; t.x = x; t.y = y;
    return *reinterpret_cast<uint32_t*>(&t);
}
__device__ __forceinline__ void bulk_cp(uint32_t dst, const void* src,
                                        uint32_t bytes, uint32_t mbar) {
    asm volatile(
        "cp.async.bulk.shared::cta.global.mbarrier::complete_tx::bytes [%0], [%1], %2, [%3];"
        :: "r"(dst), "l"(src), "r"(bytes), "r"(mbar) : "memory");
}
__device__ __forceinline__ void expect_tx(uint32_t mbar, uint32_t bytes) {
    asm volatile("mbarrier.arrive.expect_tx.shared.b64 _, [%0], %1;"
        :: "r"(mbar), "r"(bytes) : "memory");
}
#define MBARRIER_INIT(mbar, cnt) \
    asm volatile("mbarrier.init.shared.b64 [%0], %1;" :: "r"((uint32_t)(mbar)), "r"((uint32_t)(cnt)) : "memory")
#define MBARRIER_WAIT_PARITY(mbar, parity) do { \
    uint32_t _m = (uint32_t)(mbar); uint32_t _p = (uint32_t)(parity); uint32_t _d; \
    asm volatile("{\n\t.reg .pred p;\n\t" \
        "mbarrier.try_wait.parity.acquire.cta.shared::cta.b64 p, [%1], %2;\n\t" \
        "selp.b32 %0, 1, 0, p;\n\t}" : "=r"(_d) : "r"(_m), "r"(_p) : "memory"); \
    if (!_d) { \
        asm volatile("{\n\t.reg .pred P1;\n\t" \
            "WL_%=:\n\t" \
            "mbarrier.try_wait.parity.acquire.cta.shared::cta.b64 P1, [%0], %1, 0x989680;\n\t" \
            "@P1 bra.uni WD_%=;\n\t" \
            "bra.uni WL_%=;\n\t" \
            "WD_%=:\n\t}" :: "r"(_m), "r"(_p) : "memory"); \
    } } while (0)

// ---------------- prep_x: x fp32 -> fp16 hi/lo padded k-step images ----------------
__global__ __launch_bounds__(256) void prep_x_kernel(const float* __restrict__ x) {
    size_t i = (size_t)blockIdx.x * 256 + threadIdx.x;
    int c = (int)(i & 255);
    size_t n = i >> 8;
    float v = x[i];
    __half hi = __float2half_rn(v);
    size_t off = ((size_t)(c >> 6) * (BATCH * NTOK) + n) * 72 + (c & 63);
    g_xhi[off] = hi;
    g_xlo[off] = __float2half_rn(v - __half2float(hi));
}

// ---------------- prep_w: transpose weights -> single fp16, concat bias ----------------
__global__ __launch_bounds__(256) void prep_w_kernel(
    const float* __restrict__ Wq, const float* __restrict__ bq,
    const float* __restrict__ Wk, const float* __restrict__ bk,
    const float* __restrict__ Wv, const float* __restrict__ bv)
{
    const int d = blockIdx.x, c = threadIdx.x;
    float w;
    if (d < 128)      w = Wq[c * 128 + d];
    else if (d < 256) w = Wk[c * 128 + (d - 128)];
    else              w = Wv[c * 256 + (d - 256)];
    size_t off = ((size_t)(c >> 6) * 512 + d) * 72 + (c & 63);
    g_whi[off] = __float2half_rn(w);
    if (c == 0)
        g_bias[d] = (d < 128) ? bq[d] : (d < 256) ? bk[d - 128] : bv[d - 256];
}

// ---------------- tensorized projection GEMM (fp16 2-term) ----------------
#define GLDA 72
#define GSAHI 0
#define GSALO 9216
#define GSBHI 18432
#define GMBAR 55296
#define GSM_BYTES 55328

__global__ __launch_bounds__(256, 2) void gemm_tensor_kernel() {
    extern __shared__ __half sg[];
    const uint32_t sb = smem_u32(sg);
    const uint32_t mbar = sb + GMBAR;
    const int t = threadIdx.x, lane = t & 31, wid = t >> 5;
    const int nt = blockIdx.x;
    const int m0 = blockIdx.y * 128;
    const int n0 = nt * 128;
    const int lg = lane >> 3, lr = lane & 7;
    const uint32_t a_base = (uint32_t)((16 * wid + lr + (lg & 1) * 8) * GLDA + (lg >> 1) * 8);
    const uint32_t b_base = (uint32_t)(lr * GLDA + lg * 8);

    if (t == 0) MBARRIER_INIT(mbar, 1);
    __syncthreads();

    float acc[16][4];
#pragma unroll
    for (int nf = 0; nf < 16; nf++)
#pragma unroll
        for (int e = 0; e < 4; e++) acc[nf][e] = 0.f;

    for (int kb = 0; kb < 4; kb++) {
        if (t == 0) {
            expect_tx(mbar, 3 * 18432);
            const size_t aoff = ((size_t)kb * (BATCH * NTOK) + m0) * 72;
            const size_t boff = ((size_t)kb * 512 + n0) * 72;
            bulk_cp(sb + 2 * GSAHI, g_xhi + aoff, 18432, mbar);
            bulk_cp(sb + 2 * GSALO, g_xlo + aoff, 18432, mbar);
            bulk_cp(sb + 2 * GSBHI, g_whi + boff, 18432, mbar);
        }
        MBARRIER_WAIT_PARITY(mbar, kb & 1);
#pragma unroll
        for (int kkp = 0; kkp < 2; kkp++) {
            uint32_t qh0[4], qh1[4], ql0[4], ql1[4];
            ldsm_x4(qh0, sb + 2 * (GSAHI + a_base + 32 * kkp));
            ldsm_x4(qh1, sb + 2 * (GSAHI + a_base + 32 * kkp + 16));
            ldsm_x4(ql0, sb + 2 * (GSALO + a_base + 32 * kkp));
            ldsm_x4(ql1, sb + 2 * (GSALO + a_base + 32 * kkp + 16));
#pragma unroll
            for (int nf = 0; nf < 16; nf++) {
                uint32_t bh[4];
                ldsm_x4(bh, sb + 2 * (GSBHI + b_base + nf * 8 * GLDA + 32 * kkp));
                mma_f16(acc[nf], qh0, bh);
                mma_f16(acc[nf], qh1, bh + 2);
                mma_f16(acc[nf], ql0, bh);
                mma_f16(acc[nf], ql1, bh + 2);
            }
        }
        __syncthreads();
    }

    float* dst; int doff, Dd;
    if (nt == 0)      { dst = g_q; doff = 0;   Dd = 128; }
    else if (nt == 1) { dst = g_k; doff = 0;   Dd = 128; }
    else              { dst = g_v; doff = (nt - 2) * 128; Dd = 256; }
    const int r0 = m0 + 16 * wid + (lane >> 2);
#pragma unroll
    for (int nf = 0; nf < 16; nf++) {
        const int cg = nf * 8 + 2 * (lane & 3);
        const float b0 = g_bias[n0 + cg], b1 = g_bias[n0 + cg + 1];
        const int dd = doff + cg;
        float2 v0 = {acc[nf][0] + b0, acc[nf][1] + b1};
        float2 v1 = {acc[nf][2] + b0, acc[nf][3] + b1};
        *(float2*)(dst + (size_t)r0 * Dd + dd) = v0;
        *(float2*)(dst + (size_t)(r0 + 8) * Dd + dd) = v1;
    }
}

// ---------------- preps: flat-remap fp32 -> fp16 operand images ----------------
// one block per 32-row slab of one tile. two=1: hi+lo planes (Q); two=0: hi only (K).
__global__ __launch_bounds__(256) void prep_qk_kernel(
    const float* __restrict__ buf, __half* __restrict__ img, int R, int T, int two)
{
    __shared__ float st[128 * 33];
    const int slabs = R >> 5;
    const int tile = blockIdx.x / slabs;
    const int q0 = (blockIdx.x - tile * slabs) * 32;
    const int b = blockIdx.y;
    const float* src = buf + (size_t)b * NTOK * DQK;
    __half* dst = img + (size_t)(b * T + tile) * ((two ? 2 : 1) * R * LDQ);
    const int n0 = tile * R;
    for (int i = threadIdx.x; i < 4096; i += 256) {
        int c = i >> 5, m = i & 31;
        st[c * 33 + m] = src[(size_t)c * NTOK + n0 + q0 + m];
    }
    __syncthreads();
    for (int e = threadIdx.x; e < 4096; e += 256) {
        int q = e >> 7, c = e & 127;
        float v = st[c * 33 + q];
        __half hi = __float2half_rn(v);
        dst[(q0 + q) * LDQ + c] = hi;
        if (two)
            dst[R * LDQ + (q0 + q) * LDQ + c] = __float2half_rn(v - __half2float(hi));
    }
}
__global__ __launch_bounds__(256) void prep_v_kernel()
{
    const int tile = blockIdx.x, b = blockIdx.y, t = threadIdx.x;
    const int m = t & 31;
    const float* src = g_v + (size_t)b * NTOK * DV;
    __half* dst = g_vimg + (size_t)(b * 128 + tile) * (DV * LDV);
    const int n0 = tile * BN;
    for (int c = (t >> 5); c < DV; c += 8) {
        float v = src[(size_t)c * NTOK + n0 + m];
        dst[c * LDV + m] = __float2half_rn(v);
    }
}

// ---------------- flash kernel ----------------
// smem (halves): Qhi[128x136]@0, Qlo@17408, K bufs @34816 (2x4352 fp16 hi),
// V bufs @43520 (2x10240 fp16).  bytes: Osm reuse [0,135168), mbars @135168,
// lrow @135232.
#define SQHI 0
#define SQLO 17408
#define SK0  34816
#define SV0  43520
#define KBUF 4352
#define VBUF 10240
#define MBAR_OFF 135168
#define LROW_OFF 135232
#define OSM_LD 132
#define SM_BYTES 135744
#define TILE_BYTES (2 * KBUF + 2 * VBUF)   // 29184 bytes

__global__ __launch_bounds__(256, 1) void flash_kernel(
    const float* __restrict__ xin, const float* __restrict__ gamma_p,
    float* __restrict__ yout)
{
    extern __shared__ __half sm[];
    const uint32_t sb = smem_u32(sm);
    const uint32_t mb0 = sb + MBAR_OFF, mb1 = sb + MBAR_OFF + 8;
    const int t = threadIdx.x, lane = t & 31, wid = t >> 5;
    const int qt = blockIdx.x, b = blockIdx.y;
    const int n0 = qt * BM;
    const int lg = lane >> 3, lr = lane & 7;
    const uint32_t qa_base = (uint32_t)((16 * wid + lr + (lg & 1) * 8) * LDQ + (lg >> 1) * 8);
    const uint32_t kb_base = (uint32_t)(lr * LDQ + lg * 8);
    const uint32_t vb_base = (uint32_t)(lr * LDV + lg * 8);

    const __half* kimg = g_kimg + (size_t)b * 128 * (size_t)(BN * LDQ);
    const __half* vimg = g_vimg + (size_t)b * 128 * (size_t)(DV * LDV);

    if (t == 0) { MBARRIER_INIT(mb0, 1); MBARRIER_INIT(mb1, 1); }
    __syncthreads();
    if (t == 0) {
        expect_tx(mb0, TILE_BYTES + 2 * 2 * BM * LDQ);
        bulk_cp(sb, g_qimg + (size_t)(b * 32 + qt) * (2 * BM * LDQ),
                2 * 2 * BM * LDQ, mb0);
        bulk_cp(sb + 2 * SK0, kimg, 2 * KBUF, mb0);
        bulk_cp(sb + 2 * SV0, vimg, 2 * VBUF, mb0);
        expect_tx(mb1, TILE_BYTES);
        bulk_cp(sb + 2 * (SK0 + KBUF), kimg + KBUF, 2 * KBUF, mb1);
        bulk_cp(sb + 2 * (SV0 + VBUF), vimg + VBUF, 2 * VBUF, mb1);
    }

    float oacc[32][4];
#pragma unroll
    for (int nf = 0; nf < 32; nf++)
#pragma unroll
        for (int e = 0; e < 4; e++) oacc[nf][e] = 0.f;
    float lsum0 = 0.f, lsum1 = 0.f;
    float m0 = -1e30f, m1 = -1e30f;

    for (int kt = 0; kt < NKT; kt++) {
        const int buf = kt & 1;
        MBARRIER_WAIT_PARITY(buf ? mb1 : mb0, (kt >> 1) & 1);

        const uint32_t khi = SK0 + buf * KBUF;
        const uint32_t vhi = SV0 + buf * VBUF;

        // ---- S = Q K^T (fp16: Q hi/lo 2-term, K single), 2 banks ----
        float sa[4][4], sc[4][4];
#pragma unroll
        for (int nn = 0; nn < 4; nn++)
#pragma unroll
            for (int e = 0; e < 4; e++) { sa[nn][e] = 0.f; sc[nn][e] = 0.f; }
#pragma unroll
        for (int kkp = 0; kkp < 4; kkp++) {
            uint32_t qh0[4], qh1[4], ql0[4], ql1[4];
            ldsm_x4(qh0, sb + 2 * (SQHI + qa_base + 32 * kkp));
            ldsm_x4(qh1, sb + 2 * (SQHI + qa_base + 32 * kkp + 16));
            ldsm_x4(ql0, sb + 2 * (SQLO + qa_base + 32 * kkp));
            ldsm_x4(ql1, sb + 2 * (SQLO + qa_base + 32 * kkp + 16));
#pragma unroll
            for (int nn = 0; nn < 4; nn++) {
                uint32_t kh[4];
                ldsm_x4(kh, sb + 2 * (khi + kb_base + nn * 8 * LDQ + 32 * kkp));
                mma_f16(sa[nn], qh0, kh);
                mma_f16(sa[nn], qh1, kh + 2);
                mma_f16(sc[nn], ql0, kh);
                mma_f16(sc[nn], ql1, kh + 2);
            }
        }

        // ---- online softmax with running max ----
        float sv[4][4];
#pragma unroll
        for (int nn = 0; nn < 4; nn++)
#pragma unroll
            for (int e = 0; e < 4; e++) sv[nn][e] = sa[nn][e] + sc[nn][e];

        float tm0 = -1e30f, tm1 = -1e30f;
#pragma unroll
        for (int nn = 0; nn < 4; nn++) {
            tm0 = fmaxf(tm0, fmaxf(sv[nn][0], sv[nn][1]));
            tm1 = fmaxf(tm1, fmaxf(sv[nn][2], sv[nn][3]));
        }
        tm0 = fmaxf(tm0, __shfl_xor_sync(0xffffffffu, tm0, 1));
        tm0 = fmaxf(tm0, __shfl_xor_sync(0xffffffffu, tm0, 2));
        tm1 = fmaxf(tm1, __shfl_xor_sync(0xffffffffu, tm1, 1));
        tm1 = fmaxf(tm1, __shfl_xor_sync(0xffffffffu, tm1, 2));
        const float mn0 = fmaxf(m0, tm0), mn1 = fmaxf(m1, tm1);
        const float sc0 = __expf(m0 - mn0), sc1 = __expf(m1 - mn1);
        m0 = mn0; m1 = mn1;
        if (sc0 < 1.f) {
            lsum0 *= sc0;
#pragma unroll
            for (int nf = 0; nf < 32; nf++) { oacc[nf][0] *= sc0; oacc[nf][1] *= sc0; }
        }
        if (sc1 < 1.f) {
            lsum1 *= sc1;
#pragma unroll
            for (int nf = 0; nf < 32; nf++) { oacc[nf][2] *= sc1; oacc[nf][3] *= sc1; }
        }

        uint32_t phi[2][4];
#pragma unroll
        for (int kk = 0; kk < 2; kk++)
#pragma unroll
            for (int half = 0; half < 2; half++) {
                const float* p = sv[2 * kk + half];
                __half h0 = __float2half_rn(__expf(p[0] - mn0));
                __half h1 = __float2half_rn(__expf(p[1] - mn0));
                __half h2 = __float2half_rn(__expf(p[2] - mn1));
                __half h3 = __float2half_rn(__expf(p[3] - mn1));
                phi[kk][2 * half + 0] = packh2(h0, h1);
                phi[kk][2 * half + 1] = packh2(h2, h3);
                lsum0 += __half2float(h0) + __half2float(h1);
                lsum1 += __half2float(h2) + __half2float(h3);
            }

        // ---- O += P V (single-term fp16), all 256 channels ----
#pragma unroll
        for (int nf = 0; nf < 32; nf++) {
            uint32_t vh[4];
            ldsm_x4(vh, sb + 2 * (vhi + vb_base + nf * 8 * LDV));
            mma_f16(oacc[nf], phi[0], vh);
            mma_f16(oacc[nf], phi[1], vh + 2);
        }
        __syncthreads();
        if (t == 0 && kt + 2 < NKT) {
            const uint32_t mb = buf ? mb1 : mb0;
            expect_tx(mb, TILE_BYTES);
            bulk_cp(sb + 2 * (SK0 + buf * KBUF),
                    kimg + (size_t)(kt + 2) * KBUF, 2 * KBUF, mb);
            bulk_cp(sb + 2 * (SV0 + buf * VBUF),
                    vimg + (size_t)(kt + 2) * VBUF, 2 * VBUF, mb);
        }
    }

    // ---- epilogue: transpose O through smem, y = gamma*(O/l) + x ----
    lsum0 += __shfl_xor_sync(0xffffffffu, lsum0, 1);
    lsum0 += __shfl_xor_sync(0xffffffffu, lsum0, 2);
    lsum1 += __shfl_xor_sync(0xffffffffu, lsum1, 1);
    lsum1 += __shfl_xor_sync(0xffffffffu, lsum1, 2);
    float* Osm = (float*)sm;
    float* lrow = (float*)((char*)sm + LROW_OFF);
    const int rloc = 16 * wid + (lane >> 2);
    if ((lane & 3) == 0) { lrow[rloc] = lsum0; lrow[rloc + 8] = lsum1; }
#pragma unroll
    for (int nf = 0; nf < 32; nf++) {
        const int c = nf * 8 + 2 * (lane & 3);
        Osm[c * OSM_LD + rloc] = oacc[nf][0];
        Osm[(c + 1) * OSM_LD + rloc] = oacc[nf][1];
        Osm[c * OSM_LD + rloc + 8] = oacc[nf][2];
        Osm[(c + 1) * OSM_LD + rloc + 8] = oacc[nf][3];
    }
    __syncthreads();
    if (t < 128) lrow[t] = gamma_p[0] / lrow[t];
    __syncthreads();
    const float* xb = xin  + (size_t)b * DV * NTOK;
    float*       yb = yout + (size_t)b * DV * NTOK;
    for (int i = t; i < 256 * 32; i += 256) {
        const int c = i >> 5, nn = (i & 31) << 2;
        float4 o = *(float4*)&Osm[c * OSM_LD + nn];
        size_t gi = (size_t)c * NTOK + n0 + nn;
        float4 xv = *(const float4*)(xb + gi);
        float4 y;
        y.x = o.x * lrow[nn + 0] + xv.x;
        y.y = o.y * lrow[nn + 1] + xv.y;
        y.z = o.z * lrow[nn + 2] + xv.z;
        y.w = o.w * lrow[nn + 3] + xv.w;
        *(float4*)(yb + gi) = y;
    }
}

// ---------------- launch ----------------
extern "C" void kernel_launch(void* const* d_in, const int* in_sizes, int n_in,
                              void* d_out, int out_size)
{
    const float* x     = (const float*)d_in[0];
    const float* Wq    = (const float*)d_in[1];
    const float* bq    = (const float*)d_in[2];
    const float* Wk    = (const float*)d_in[3];
    const float* bk    = (const float*)d_in[4];
    const float* Wv    = (const float*)d_in[5];
    const float* bv    = (const float*)d_in[6];
    const float* gamma = (const float*)d_in[7];
    float* out = (float*)d_out;

    float *qbuf, *kbuf;
    __half *qimg, *kimg;
    cudaGetSymbolAddress((void**)&qbuf, g_q);
    cudaGetSymbolAddress((void**)&kbuf, g_k);
    cudaGetSymbolAddress((void**)&qimg, g_qimg);
    cudaGetSymbolAddress((void**)&kimg, g_kimg);

    prep_x_kernel<<<BATCH * NTOK, 256>>>(x);
    prep_w_kernel<<<512, 256>>>(Wq, bq, Wk, bk, Wv, bv);

    cudaFuncSetAttribute(gemm_tensor_kernel,
                         cudaFuncAttributeMaxDynamicSharedMemorySize, GSM_BYTES);
    gemm_tensor_kernel<<<dim3(4, BATCH * NTOK / 128), 256, GSM_BYTES>>>();

    prep_qk_kernel<<<dim3(32 * 4, BATCH), 256>>>(qbuf, qimg, BM, 32, 1);
    prep_qk_kernel<<<dim3(128, BATCH), 256>>>(kbuf, kimg, BN, 128, 0);
    prep_v_kernel<<<dim3(128, BATCH), 256>>>();

    cudaFuncSetAttribute(flash_kernel,
                         cudaFuncAttributeMaxDynamicSharedMemorySize, SM_BYTES);
    flash_kernel<<<dim3(NTOK / BM, BATCH), 256, SM_BYTES>>>(x, gamma, out);
}

// round 10
// speedup vs baseline: 6.2901x; 1.0987x over previous
#include <cuda_runtime.h>
#include <cuda_bf16.h>
#include <cuda_fp16.h>
#include <cstdint>

// B=4, N=4096 tok/batch, d_qk=128, d_v=256.
// Reference reshapes are flat reinterprets of TOKEN-major projection buffers:
// pq[c][n] = q_flat[c*4096+n]; the prep kernels implement that axis-mixing
// (do NOT fuse image writes into the GEMM epilogue — tiles span 32 GEMM CTAs).
//
// Round-10 (vs 342.1us):
//  * S path fully single-term fp16: Q-lo plane dropped (symmetric to the
//    K-lo drop measured at +~2e-4 rel_err). S MMAs 64->32, Q ldsm halved,
//    Q image halved. Flash MMA+crossbar both -25%.
//  * GEMM stays x hi/lo 2-term fp16 x W single (error-per-us too poor to cut).
// Error model: RSS(3.36e-4, ~2e-4) ~ 3.9e-4 < 1e-3.

#define NTOK  4096
#define DQK   128
#define DV    256
#define BATCH 4
#define BM    128
#define BN    32
#define NKT   (NTOK / BN)
#define LDQ   136
#define LDV   40

// -------- device scratch (no allocations allowed) --------
__device__ float g_q[BATCH * NTOK * DQK];
__device__ float g_k[BATCH * NTOK * DQK];
__device__ float g_v[BATCH * NTOK * DV];
__device__ __align__(16) __half g_xhi[4 * BATCH * NTOK * 72];
__device__ __align__(16) __half g_xlo[4 * BATCH * NTOK * 72];
__device__ __align__(16) __half g_whi[4 * 512 * 72];
__device__ float g_bias[512];
__device__ __align__(16) __half g_qimg[BATCH * 32 * BM * LDQ];       // hi only
__device__ __align__(16) __half g_kimg[BATCH * 128 * BN * LDQ];      // hi only
__device__ __align__(16) __half g_vimg[BATCH * 128 * DV * LDV];      // hi only

// ---------------- wrappers ----------------
__device__ __forceinline__ uint32_t smem_u32(const void* p) {
    uint32_t a;
    asm("{ .reg .u64 t; cvta.to.shared.u64 t, %1; cvt.u32.u64 %0, t; }" : "=r"(a) : "l"(p));
    return a;
}
__device__ __forceinline__ void ldsm_x4(uint32_t* r, uint32_t saddr) {
    asm volatile("ldmatrix.sync.aligned.m8n8.x4.shared.b16 {%0,%1,%2,%3}, [%4];"
        : "=r"(r[0]), "=r"(r[1]), "=r"(r[2]), "=r"(r[3]) : "r"(saddr));
}
__device__ __forceinline__ void mma_f16(float* d, const uint32_t* a, const uint32_t* b) {
    asm volatile("mma.sync.aligned.m16n8k16.row.col.f32.f16.f16.f32 "
        "{%0,%1,%2,%3}, {%4,%5,%6,%7}, {%8,%9}, {%0,%1,%2,%3};"
        : "+f"(d[0]), "+f"(d[1]), "+f"(d[2]), "+f"(d[3])
        : "r"(a[0]), "r"(a[1]), "r"(a[2]), "r"(a[3]), "r"(b[0]), "r"(b[1]));
}
__device__ __forceinline__ uint32_t packh2(__half x, __half y) {
    __half2 t; t.x = x; t.y = y;
    return *reinterpret_cast<uint32_t*>(&t);
}
__device__ __forceinline__ void bulk_cp(uint32_t dst, const void* src,
                                        uint32_t bytes, uint32_t mbar) {
    asm volatile(
        "cp.async.bulk.shared::cta.global.mbarrier::complete_tx::bytes [%0], [%1], %2, [%3];"
        :: "r"(dst), "l"(src), "r"(bytes), "r"(mbar) : "memory");
}
__device__ __forceinline__ void expect_tx(uint32_t mbar, uint32_t bytes) {
    asm volatile("mbarrier.arrive.expect_tx.shared.b64 _, [%0], %1;"
        :: "r"(mbar), "r"(bytes) : "memory");
}
#define MBARRIER_INIT(mbar, cnt) \
    asm volatile("mbarrier.init.shared.b64 [%0], %1;" :: "r"((uint32_t)(mbar)), "r"((uint32_t)(cnt)) : "memory")
#define MBARRIER_WAIT_PARITY(mbar, parity) do { \
    uint32_t _m = (uint32_t)(mbar); uint32_t _p = (uint32_t)(parity); uint32_t _d; \
    asm volatile("{\n\t.reg .pred p;\n\t" \
        "mbarrier.try_wait.parity.acquire.cta.shared::cta.b64 p, [%1], %2;\n\t" \
        "selp.b32 %0, 1, 0, p;\n\t}" : "=r"(_d) : "r"(_m), "r"(_p) : "memory"); \
    if (!_d) { \
        asm volatile("{\n\t.reg .pred P1;\n\t" \
            "WL_%=:\n\t" \
            "mbarrier.try_wait.parity.acquire.cta.shared::cta.b64 P1, [%0], %1, 0x989680;\n\t" \
            "@P1 bra.uni WD_%=;\n\t" \
            "bra.uni WL_%=;\n\t" \
            "WD_%=:\n\t}" :: "r"(_m), "r"(_p) : "memory"); \
    } } while (0)

// ---------------- prep_x: x fp32 -> fp16 hi/lo padded k-step images ----------------
__global__ __launch_bounds__(256) void prep_x_kernel(const float* __restrict__ x) {
    size_t i = (size_t)blockIdx.x * 256 + threadIdx.x;
    int c = (int)(i & 255);
    size_t n = i >> 8;
    float v = x[i];
    __half hi = __float2half_rn(v);
    size_t off = ((size_t)(c >> 6) * (BATCH * NTOK) + n) * 72 + (c & 63);
    g_xhi[off] = hi;
    g_xlo[off] = __float2half_rn(v - __half2float(hi));
}

// ---------------- prep_w: transpose weights -> single fp16, concat bias ----------------
__global__ __launch_bounds__(256) void prep_w_kernel(
    const float* __restrict__ Wq, const float* __restrict__ bq,
    const float* __restrict__ Wk, const float* __restrict__ bk,
    const float* __restrict__ Wv, const float* __restrict__ bv)
{
    const int d = blockIdx.x, c = threadIdx.x;
    float w;
    if (d < 128)      w = Wq[c * 128 + d];
    else if (d < 256) w = Wk[c * 128 + (d - 128)];
    else              w = Wv[c * 256 + (d - 256)];
    size_t off = ((size_t)(c >> 6) * 512 + d) * 72 + (c & 63);
    g_whi[off] = __float2half_rn(w);
    if (c == 0)
        g_bias[d] = (d < 128) ? bq[d] : (d < 256) ? bk[d - 128] : bv[d - 256];
}

// ---------------- tensorized projection GEMM (fp16, x 2-term) ----------------
#define GLDA 72
#define GSAHI 0
#define GSALO 9216
#define GSBHI 18432
#define GMBAR 55296
#define GSM_BYTES 55328

__global__ __launch_bounds__(256, 2) void gemm_tensor_kernel() {
    extern __shared__ __half sg[];
    const uint32_t sb = smem_u32(sg);
    const uint32_t mbar = sb + GMBAR;
    const int t = threadIdx.x, lane = t & 31, wid = t >> 5;
    const int nt = blockIdx.x;
    const int m0 = blockIdx.y * 128;
    const int n0 = nt * 128;
    const int lg = lane >> 3, lr = lane & 7;
    const uint32_t a_base = (uint32_t)((16 * wid + lr + (lg & 1) * 8) * GLDA + (lg >> 1) * 8);
    const uint32_t b_base = (uint32_t)(lr * GLDA + lg * 8);

    if (t == 0) MBARRIER_INIT(mbar, 1);
    __syncthreads();

    float acc[16][4];
#pragma unroll
    for (int nf = 0; nf < 16; nf++)
#pragma unroll
        for (int e = 0; e < 4; e++) acc[nf][e] = 0.f;

    for (int kb = 0; kb < 4; kb++) {
        if (t == 0) {
            expect_tx(mbar, 3 * 18432);
            const size_t aoff = ((size_t)kb * (BATCH * NTOK) + m0) * 72;
            const size_t boff = ((size_t)kb * 512 + n0) * 72;
            bulk_cp(sb + 2 * GSAHI, g_xhi + aoff, 18432, mbar);
            bulk_cp(sb + 2 * GSALO, g_xlo + aoff, 18432, mbar);
            bulk_cp(sb + 2 * GSBHI, g_whi + boff, 18432, mbar);
        }
        MBARRIER_WAIT_PARITY(mbar, kb & 1);
#pragma unroll
        for (int kkp = 0; kkp < 2; kkp++) {
            uint32_t qh0[4], qh1[4], ql0[4], ql1[4];
            ldsm_x4(qh0, sb + 2 * (GSAHI + a_base + 32 * kkp));
            ldsm_x4(qh1, sb + 2 * (GSAHI + a_base + 32 * kkp + 16));
            ldsm_x4(ql0, sb + 2 * (GSALO + a_base + 32 * kkp));
            ldsm_x4(ql1, sb + 2 * (GSALO + a_base + 32 * kkp + 16));
#pragma unroll
            for (int nf = 0; nf < 16; nf++) {
                uint32_t bh[4];
                ldsm_x4(bh, sb + 2 * (GSBHI + b_base + nf * 8 * GLDA + 32 * kkp));
                mma_f16(acc[nf], qh0, bh);
                mma_f16(acc[nf], qh1, bh + 2);
                mma_f16(acc[nf], ql0, bh);
                mma_f16(acc[nf], ql1, bh + 2);
            }
        }
        __syncthreads();
    }

    float* dst; int doff, Dd;
    if (nt == 0)      { dst = g_q; doff = 0;   Dd = 128; }
    else if (nt == 1) { dst = g_k; doff = 0;   Dd = 128; }
    else              { dst = g_v; doff = (nt - 2) * 128; Dd = 256; }
    const int r0 = m0 + 16 * wid + (lane >> 2);
#pragma unroll
    for (int nf = 0; nf < 16; nf++) {
        const int cg = nf * 8 + 2 * (lane & 3);
        const float b0 = g_bias[n0 + cg], b1 = g_bias[n0 + cg + 1];
        const int dd = doff + cg;
        float2 v0 = {acc[nf][0] + b0, acc[nf][1] + b1};
        float2 v1 = {acc[nf][2] + b0, acc[nf][3] + b1};
        *(float2*)(dst + (size_t)r0 * Dd + dd) = v0;
        *(float2*)(dst + (size_t)(r0 + 8) * Dd + dd) = v1;
    }
}

// ---------------- preps: flat-remap fp32 -> fp16 operand images (hi only) ----------------
// one block per 32-row slab of one tile.
__global__ __launch_bounds__(256) void prep_qk_kernel(
    const float* __restrict__ buf, __half* __restrict__ img, int R, int T)
{
    __shared__ float st[128 * 33];
    const int slabs = R >> 5;
    const int tile = blockIdx.x / slabs;
    const int q0 = (blockIdx.x - tile * slabs) * 32;
    const int b = blockIdx.y;
    const float* src = buf + (size_t)b * NTOK * DQK;
    __half* dst = img + (size_t)(b * T + tile) * (R * LDQ);
    const int n0 = tile * R;
    for (int i = threadIdx.x; i < 4096; i += 256) {
        int c = i >> 5, m = i & 31;
        st[c * 33 + m] = src[(size_t)c * NTOK + n0 + q0 + m];
    }
    __syncthreads();
    for (int e = threadIdx.x; e < 4096; e += 256) {
        int q = e >> 7, c = e & 127;
        dst[(q0 + q) * LDQ + c] = __float2half_rn(st[c * 33 + q]);
    }
}
__global__ __launch_bounds__(256) void prep_v_kernel()
{
    const int tile = blockIdx.x, b = blockIdx.y, t = threadIdx.x;
    const int m = t & 31;
    const float* src = g_v + (size_t)b * NTOK * DV;
    __half* dst = g_vimg + (size_t)(b * 128 + tile) * (DV * LDV);
    const int n0 = tile * BN;
    for (int c = (t >> 5); c < DV; c += 8) {
        float v = src[(size_t)c * NTOK + n0 + m];
        dst[c * LDV + m] = __float2half_rn(v);
    }
}

// ---------------- flash kernel ----------------
// smem (halves): Qhi[128x136]@0 (17408), K bufs @17408 (2x4352),
// V bufs @26112 (2x10240) -> 46592 halves = 93184 B live in mainloop.
// epilogue Osm reuses [0,135168) B; mbars @135168, lrow @135232.
#define SQHI 0
#define SK0  17408
#define SV0  26112
#define KBUF 4352
#define VBUF 10240
#define MBAR_OFF 135168
#define LROW_OFF 135232
#define OSM_LD 132
#define SM_BYTES 135744
#define TILE_BYTES (2 * KBUF + 2 * VBUF)   // 29184 bytes

__global__ __launch_bounds__(256, 1) void flash_kernel(
    const float* __restrict__ xin, const float* __restrict__ gamma_p,
    float* __restrict__ yout)
{
    extern __shared__ __half sm[];
    const uint32_t sb = smem_u32(sm);
    const uint32_t mb0 = sb + MBAR_OFF, mb1 = sb + MBAR_OFF + 8;
    const int t = threadIdx.x, lane = t & 31, wid = t >> 5;
    const int qt = blockIdx.x, b = blockIdx.y;
    const int n0 = qt * BM;
    const int lg = lane >> 3, lr = lane & 7;
    const uint32_t qa_base = (uint32_t)((16 * wid + lr + (lg & 1) * 8) * LDQ + (lg >> 1) * 8);
    const uint32_t kb_base = (uint32_t)(lr * LDQ + lg * 8);
    const uint32_t vb_base = (uint32_t)(lr * LDV + lg * 8);

    const __half* kimg = g_kimg + (size_t)b * 128 * (size_t)(BN * LDQ);
    const __half* vimg = g_vimg + (size_t)b * 128 * (size_t)(DV * LDV);

    if (t == 0) { MBARRIER_INIT(mb0, 1); MBARRIER_INIT(mb1, 1); }
    __syncthreads();
    if (t == 0) {
        expect_tx(mb0, TILE_BYTES + 2 * BM * LDQ);
        bulk_cp(sb, g_qimg + (size_t)(b * 32 + qt) * (BM * LDQ),
                2 * BM * LDQ, mb0);
        bulk_cp(sb + 2 * SK0, kimg, 2 * KBUF, mb0);
        bulk_cp(sb + 2 * SV0, vimg, 2 * VBUF, mb0);
        expect_tx(mb1, TILE_BYTES);
        bulk_cp(sb + 2 * (SK0 + KBUF), kimg + KBUF, 2 * KBUF, mb1);
        bulk_cp(sb + 2 * (SV0 + VBUF), vimg + VBUF, 2 * VBUF, mb1);
    }

    float oacc[32][4];
#pragma unroll
    for (int nf = 0; nf < 32; nf++)
#pragma unroll
        for (int e = 0; e < 4; e++) oacc[nf][e] = 0.f;
    float lsum0 = 0.f, lsum1 = 0.f;
    float m0 = -1e30f, m1 = -1e30f;

    for (int kt = 0; kt < NKT; kt++) {
        const int buf = kt & 1;
        MBARRIER_WAIT_PARITY(buf ? mb1 : mb0, (kt >> 1) & 1);

        const uint32_t khi = SK0 + buf * KBUF;
        const uint32_t vhi = SV0 + buf * VBUF;

        // ---- S = Q K^T (single-term fp16), 2 accumulator banks for ILP ----
        float sa[4][4], sc[4][4];
#pragma unroll
        for (int nn = 0; nn < 4; nn++)
#pragma unroll
            for (int e = 0; e < 4; e++) { sa[nn][e] = 0.f; sc[nn][e] = 0.f; }
#pragma unroll
        for (int kkp = 0; kkp < 4; kkp++) {
            uint32_t qh0[4], qh1[4];
            ldsm_x4(qh0, sb + 2 * (SQHI + qa_base + 32 * kkp));
            ldsm_x4(qh1, sb + 2 * (SQHI + qa_base + 32 * kkp + 16));
#pragma unroll
            for (int nn = 0; nn < 4; nn++) {
                uint32_t kh[4];
                ldsm_x4(kh, sb + 2 * (khi + kb_base + nn * 8 * LDQ + 32 * kkp));
                mma_f16(sa[nn], qh0, kh);       // k-cols 0..15
                mma_f16(sc[nn], qh1, kh + 2);   // k-cols 16..31
            }
        }

        // ---- online softmax with running max ----
        float sv[4][4];
#pragma unroll
        for (int nn = 0; nn < 4; nn++)
#pragma unroll
            for (int e = 0; e < 4; e++) sv[nn][e] = sa[nn][e] + sc[nn][e];

        float tm0 = -1e30f, tm1 = -1e30f;
#pragma unroll
        for (int nn = 0; nn < 4; nn++) {
            tm0 = fmaxf(tm0, fmaxf(sv[nn][0], sv[nn][1]));
            tm1 = fmaxf(tm1, fmaxf(sv[nn][2], sv[nn][3]));
        }
        tm0 = fmaxf(tm0, __shfl_xor_sync(0xffffffffu, tm0, 1));
        tm0 = fmaxf(tm0, __shfl_xor_sync(0xffffffffu, tm0, 2));
        tm1 = fmaxf(tm1, __shfl_xor_sync(0xffffffffu, tm1, 1));
        tm1 = fmaxf(tm1, __shfl_xor_sync(0xffffffffu, tm1, 2));
        const float mn0 = fmaxf(m0, tm0), mn1 = fmaxf(m1, tm1);
        const float sc0 = __expf(m0 - mn0), sc1 = __expf(m1 - mn1);
        m0 = mn0; m1 = mn1;
        if (sc0 < 1.f) {
            lsum0 *= sc0;
#pragma unroll
            for (int nf = 0; nf < 32; nf++) { oacc[nf][0] *= sc0; oacc[nf][1] *= sc0; }
        }
        if (sc1 < 1.f) {
            lsum1 *= sc1;
#pragma unroll
            for (int nf = 0; nf < 32; nf++) { oacc[nf][2] *= sc1; oacc[nf][3] *= sc1; }
        }

        uint32_t phi[2][4];
#pragma unroll
        for (int kk = 0; kk < 2; kk++)
#pragma unroll
            for (int half = 0; half < 2; half++) {
                const float* p = sv[2 * kk + half];
                __half h0 = __float2half_rn(__expf(p[0] - mn0));
                __half h1 = __float2half_rn(__expf(p[1] - mn0));
                __half h2 = __float2half_rn(__expf(p[2] - mn1));
                __half h3 = __float2half_rn(__expf(p[3] - mn1));
                phi[kk][2 * half + 0] = packh2(h0, h1);
                phi[kk][2 * half + 1] = packh2(h2, h3);
                lsum0 += __half2float(h0) + __half2float(h1);
                lsum1 += __half2float(h2) + __half2float(h3);
            }

        // ---- O += P V (single-term fp16), all 256 channels ----
#pragma unroll
        for (int nf = 0; nf < 32; nf++) {
            uint32_t vh[4];
            ldsm_x4(vh, sb + 2 * (vhi + vb_base + nf * 8 * LDV));
            mma_f16(oacc[nf], phi[0], vh);
            mma_f16(oacc[nf], phi[1], vh + 2);
        }
        __syncthreads();
        if (t == 0 && kt + 2 < NKT) {
            const uint32_t mb = buf ? mb1 : mb0;
            expect_tx(mb, TILE_BYTES);
            bulk_cp(sb + 2 * (SK0 + buf * KBUF),
                    kimg + (size_t)(kt + 2) * KBUF, 2 * KBUF, mb);
            bulk_cp(sb + 2 * (SV0 + buf * VBUF),
                    vimg + (size_t)(kt + 2) * VBUF, 2 * VBUF, mb);
        }
    }

    // ---- epilogue: transpose O through smem, y = gamma*(O/l) + x ----
    lsum0 += __shfl_xor_sync(0xffffffffu, lsum0, 1);
    lsum0 += __shfl_xor_sync(0xffffffffu, lsum0, 2);
    lsum1 += __shfl_xor_sync(0xffffffffu, lsum1, 1);
    lsum1 += __shfl_xor_sync(0xffffffffu, lsum1, 2);
    float* Osm = (float*)sm;
    float* lrow = (float*)((char*)sm + LROW_OFF);
    const int rloc = 16 * wid + (lane >> 2);
    if ((lane & 3) == 0) { lrow[rloc] = lsum0; lrow[rloc + 8] = lsum1; }
#pragma unroll
    for (int nf = 0; nf < 32; nf++) {
        const int c = nf * 8 + 2 * (lane & 3);
        Osm[c * OSM_LD + rloc] = oacc[nf][0];
        Osm[(c + 1) * OSM_LD + rloc] = oacc[nf][1];
        Osm[c * OSM_LD + rloc + 8] = oacc[nf][2];
        Osm[(c + 1) * OSM_LD + rloc + 8] = oacc[nf][3];
    }
    __syncthreads();
    if (t < 128) lrow[t] = gamma_p[0] / lrow[t];
    __syncthreads();
    const float* xb = xin  + (size_t)b * DV * NTOK;
    float*       yb = yout + (size_t)b * DV * NTOK;
    for (int i = t; i < 256 * 32; i += 256) {
        const int c = i >> 5, nn = (i & 31) << 2;
        float4 o = *(float4*)&Osm[c * OSM_LD + nn];
        size_t gi = (size_t)c * NTOK + n0 + nn;
        float4 xv = *(const float4*)(xb + gi);
        float4 y;
        y.x = o.x * lrow[nn + 0] + xv.x;
        y.y = o.y * lrow[nn + 1] + xv.y;
        y.z = o.z * lrow[nn + 2] + xv.z;
        y.w = o.w * lrow[nn + 3] + xv.w;
        *(float4*)(yb + gi) = y;
    }
}

// ---------------- launch ----------------
extern "C" void kernel_launch(void* const* d_in, const int* in_sizes, int n_in,
                              void* d_out, int out_size)
{
    const float* x     = (const float*)d_in[0];
    const float* Wq    = (const float*)d_in[1];
    const float* bq    = (const float*)d_in[2];
    const float* Wk    = (const float*)d_in[3];
    const float* bk    = (const float*)d_in[4];
    const float* Wv    = (const float*)d_in[5];
    const float* bv    = (const float*)d_in[6];
    const float* gamma = (const float*)d_in[7];
    float* out = (float*)d_out;

    float *qbuf, *kbuf;
    __half *qimg, *kimg;
    cudaGetSymbolAddress((void**)&qbuf, g_q);
    cudaGetSymbolAddress((void**)&kbuf, g_k);
    cudaGetSymbolAddress((void**)&qimg, g_qimg);
    cudaGetSymbolAddress((void**)&kimg, g_kimg);

    prep_x_kernel<<<BATCH * NTOK, 256>>>(x);
    prep_w_kernel<<<512, 256>>>(Wq, bq, Wk, bk, Wv, bv);

    cudaFuncSetAttribute(gemm_tensor_kernel,
                         cudaFuncAttributeMaxDynamicSharedMemorySize, GSM_BYTES);
    gemm_tensor_kernel<<<dim3(4, BATCH * NTOK / 128), 256, GSM_BYTES>>>();

    prep_qk_kernel<<<dim3(32 * 4, BATCH), 256>>>(qbuf, qimg, BM, 32);
    prep_qk_kernel<<<dim3(128, BATCH), 256>>>(kbuf, kimg, BN, 128);
    prep_v_kernel<<<dim3(128, BATCH), 256>>>();

    cudaFuncSetAttribute(flash_kernel,
                         cudaFuncAttributeMaxDynamicSharedMemorySize, SM_BYTES);
    flash_kernel<<<dim3(NTOK / BM, BATCH), 256, SM_BYTES>>>(x, gamma, out);
}

// round 11
// speedup vs baseline: 6.7240x; 1.0690x over previous
#include <cuda_runtime.h>
#include <cuda_bf16.h>
#include <cuda_fp16.h>
#include <cstdint>

// B=4, N=4096 tok/batch, d_qk=128, d_v=256.
// Reference reshapes are flat reinterprets of TOKEN-major projection buffers:
// pq[c][n] = q_flat[c*4096+n]; the prep kernels implement that axis-mixing
// (do NOT fuse image writes into the GEMM epilogue — tiles span 32 GEMM CTAs).
//
// Round-11 (vs 311.4us):
//  * GEMM single-term fp16 (x-lo dropped; per validated calibration ~+2e-4
//    per S path, +1e-4 v path => RSS ~4.7e-4 < 1e-3). MMAs halved.
//  * GEMM writes fp16 q/k/v directly (identical numerics to old fp32->prep
//    rounding; kills 25MB fp32 round trip).
//  * 3 prep kernels merged into one launch (grid.z = role) — they were
//    latency-bound at ~10% occupancy; concurrent execution fills the chip.
//  * flash kernel byte-identical to the 311us version.

#define NTOK  4096
#define DQK   128
#define DV    256
#define BATCH 4
#define BM    128
#define BN    32
#define NKT   (NTOK / BN)
#define LDQ   136
#define LDV   40

// -------- device scratch (no allocations allowed) --------
__device__ __align__(16) __half g_qh[BATCH * NTOK * DQK];   // token-major fp16
__device__ __align__(16) __half g_kh[BATCH * NTOK * DQK];
__device__ __align__(16) __half g_vh[BATCH * NTOK * DV];
__device__ __align__(16) __half g_xhi[4 * BATCH * NTOK * 72];
__device__ __align__(16) __half g_whi[4 * 512 * 72];
__device__ float g_bias[512];
__device__ __align__(16) __half g_qimg[BATCH * 32 * BM * LDQ];
__device__ __align__(16) __half g_kimg[BATCH * 128 * BN * LDQ];
__device__ __align__(16) __half g_vimg[BATCH * 128 * DV * LDV];

// ---------------- wrappers ----------------
__device__ __forceinline__ uint32_t smem_u32(const void* p) {
    uint32_t a;
    asm("{ .reg .u64 t; cvta.to.shared.u64 t, %1; cvt.u32.u64 %0, t; }" : "=r"(a) : "l"(p));
    return a;
}
__device__ __forceinline__ void ldsm_x4(uint32_t* r, uint32_t saddr) {
    asm volatile("ldmatrix.sync.aligned.m8n8.x4.shared.b16 {%0,%1,%2,%3}, [%4];"
        : "=r"(r[0]), "=r"(r[1]), "=r"(r[2]), "=r"(r[3]) : "r"(saddr));
}
__device__ __forceinline__ void mma_f16(float* d, const uint32_t* a, const uint32_t* b) {
    asm volatile("mma.sync.aligned.m16n8k16.row.col.f32.f16.f16.f32 "
        "{%0,%1,%2,%3}, {%4,%5,%6,%7}, {%8,%9}, {%0,%1,%2,%3};"
        : "+f"(d[0]), "+f"(d[1]), "+f"(d[2]), "+f"(d[3])
        : "r"(a[0]), "r"(a[1]), "r"(a[2]), "r"(a[3]), "r"(b[0]), "r"(b[1]));
}
__device__ __forceinline__ uint32_t packh2(__half x, __half y) {
    __half2 t; t.x = x; t.y = y;
    return *reinterpret_cast<uint32_t*>(&t);
}
__device__ __forceinline__ void bulk_cp(uint32_t dst, const void* src,
                                        uint32_t bytes, uint32_t mbar) {
    asm volatile(
        "cp.async.bulk.shared::cta.global.mbarrier::complete_tx::bytes [%0], [%1], %2, [%3];"
        :: "r"(dst), "l"(src), "r"(bytes), "r"(mbar) : "memory");
}
__device__ __forceinline__ void expect_tx(uint32_t mbar, uint32_t bytes) {
    asm volatile("mbarrier.arrive.expect_tx.shared.b64 _, [%0], %1;"
        :: "r"(mbar), "r"(bytes) : "memory");
}
#define MBARRIER_INIT(mbar, cnt) \
    asm volatile("mbarrier.init.shared.b64 [%0], %1;" :: "r"((uint32_t)(mbar)), "r"((uint32_t)(cnt)) : "memory")
#define MBARRIER_WAIT_PARITY(mbar, parity) do { \
    uint32_t _m = (uint32_t)(mbar); uint32_t _p = (uint32_t)(parity); uint32_t _d; \
    asm volatile("{\n\t.reg .pred p;\n\t" \
        "mbarrier.try_wait.parity.acquire.cta.shared::cta.b64 p, [%1], %2;\n\t" \
        "selp.b32 %0, 1, 0, p;\n\t}" : "=r"(_d) : "r"(_m), "r"(_p) : "memory"); \
    if (!_d) { \
        asm volatile("{\n\t.reg .pred P1;\n\t" \
            "WL_%=:\n\t" \
            "mbarrier.try_wait.parity.acquire.cta.shared::cta.b64 P1, [%0], %1, 0x989680;\n\t" \
            "@P1 bra.uni WD_%=;\n\t" \
            "bra.uni WL_%=;\n\t" \
            "WD_%=:\n\t}" :: "r"(_m), "r"(_p) : "memory"); \
    } } while (0)

// ---------------- prep_x: x fp32 -> fp16 padded k-step image (hi only) ----------------
__global__ __launch_bounds__(256) void prep_x_kernel(const float* __restrict__ x) {
    size_t i = (size_t)blockIdx.x * 256 + threadIdx.x;
    int c = (int)(i & 255);
    size_t n = i >> 8;
    size_t off = ((size_t)(c >> 6) * (BATCH * NTOK) + n) * 72 + (c & 63);
    g_xhi[off] = __float2half_rn(x[i]);
}

// ---------------- prep_w: transpose weights -> fp16, concat bias ----------------
__global__ __launch_bounds__(256) void prep_w_kernel(
    const float* __restrict__ Wq, const float* __restrict__ bq,
    const float* __restrict__ Wk, const float* __restrict__ bk,
    const float* __restrict__ Wv, const float* __restrict__ bv)
{
    const int d = blockIdx.x, c = threadIdx.x;
    float w;
    if (d < 128)      w = Wq[c * 128 + d];
    else if (d < 256) w = Wk[c * 128 + (d - 128)];
    else              w = Wv[c * 256 + (d - 256)];
    size_t off = ((size_t)(c >> 6) * 512 + d) * 72 + (c & 63);
    g_whi[off] = __float2half_rn(w);
    if (c == 0)
        g_bias[d] = (d < 128) ? bq[d] : (d < 256) ? bk[d - 128] : bv[d - 256];
}

// ---------------- tensorized projection GEMM (single-term fp16) ----------------
#define GLDA 72
#define GSAHI 0
#define GSBHI 9216
#define GMBAR 36864
#define GSM_BYTES 36896

__global__ __launch_bounds__(256, 2) void gemm_tensor_kernel() {
    extern __shared__ __half sg[];
    const uint32_t sb = smem_u32(sg);
    const uint32_t mbar = sb + GMBAR;
    const int t = threadIdx.x, lane = t & 31, wid = t >> 5;
    const int nt = blockIdx.x;
    const int m0 = blockIdx.y * 128;
    const int n0 = nt * 128;
    const int lg = lane >> 3, lr = lane & 7;
    const uint32_t a_base = (uint32_t)((16 * wid + lr + (lg & 1) * 8) * GLDA + (lg >> 1) * 8);
    const uint32_t b_base = (uint32_t)(lr * GLDA + lg * 8);

    if (t == 0) MBARRIER_INIT(mbar, 1);
    __syncthreads();

    float acc[16][4];
#pragma unroll
    for (int nf = 0; nf < 16; nf++)
#pragma unroll
        for (int e = 0; e < 4; e++) acc[nf][e] = 0.f;

    for (int kb = 0; kb < 4; kb++) {
        if (t == 0) {
            expect_tx(mbar, 2 * 18432);
            const size_t aoff = ((size_t)kb * (BATCH * NTOK) + m0) * 72;
            const size_t boff = ((size_t)kb * 512 + n0) * 72;
            bulk_cp(sb + 2 * GSAHI, g_xhi + aoff, 18432, mbar);
            bulk_cp(sb + 2 * GSBHI, g_whi + boff, 18432, mbar);
        }
        MBARRIER_WAIT_PARITY(mbar, kb & 1);
#pragma unroll
        for (int kkp = 0; kkp < 2; kkp++) {
            uint32_t qh0[4], qh1[4];
            ldsm_x4(qh0, sb + 2 * (GSAHI + a_base + 32 * kkp));
            ldsm_x4(qh1, sb + 2 * (GSAHI + a_base + 32 * kkp + 16));
#pragma unroll
            for (int nf = 0; nf < 16; nf++) {
                uint32_t bh[4];
                ldsm_x4(bh, sb + 2 * (GSBHI + b_base + nf * 8 * GLDA + 32 * kkp));
                mma_f16(acc[nf], qh0, bh);
                mma_f16(acc[nf], qh1, bh + 2);
            }
        }
        __syncthreads();
    }

    // epilogue: +bias, round to fp16, store token-major
    __half* dst; int doff, Dd;
    if (nt == 0)      { dst = g_qh; doff = 0;   Dd = 128; }
    else if (nt == 1) { dst = g_kh; doff = 0;   Dd = 128; }
    else              { dst = g_vh; doff = (nt - 2) * 128; Dd = 256; }
    const int r0 = m0 + 16 * wid + (lane >> 2);
#pragma unroll
    for (int nf = 0; nf < 16; nf++) {
        const int cg = nf * 8 + 2 * (lane & 3);
        const float b0 = g_bias[n0 + cg], b1 = g_bias[n0 + cg + 1];
        const int dd = doff + cg;
        *(uint32_t*)(dst + (size_t)r0 * Dd + dd) =
            packh2(__float2half_rn(acc[nf][0] + b0), __float2half_rn(acc[nf][1] + b1));
        *(uint32_t*)(dst + (size_t)(r0 + 8) * Dd + dd) =
            packh2(__float2half_rn(acc[nf][2] + b0), __float2half_rn(acc[nf][3] + b1));
    }
}

// ---------------- unified prep: flat-remap fp16 -> operand images ----------------
// grid (128, BATCH, 3): z=0 Q (32 tiles x 4 slabs), z=1 K (128 tiles), z=2 V.
__device__ __forceinline__ void prep_qk_body(
    const __half* __restrict__ src, __half* __restrict__ img,
    int R, int T, int bx, int b, __half* st)
{
    const int slabs = R >> 5;
    const int tile = bx / slabs;
    const int q0 = (bx - tile * slabs) * 32;
    __half* dst = img + (size_t)(b * T + tile) * (R * LDQ);
    const int n0 = tile * R;
    for (int i = threadIdx.x; i < 4096; i += 256) {
        int c = i >> 5, m = i & 31;
        st[c * 33 + m] = src[(size_t)c * NTOK + n0 + q0 + m];
    }
    __syncthreads();
    for (int e = threadIdx.x; e < 4096; e += 256) {
        int q = e >> 7, c = e & 127;
        dst[(q0 + q) * LDQ + c] = st[c * 33 + q];
    }
}

__global__ __launch_bounds__(256) void prep_all_kernel()
{
    __shared__ __half st[128 * 33];
    const int bx = blockIdx.x, b = blockIdx.y, role = blockIdx.z;
    if (role == 0) {
        prep_qk_body(g_qh + (size_t)b * NTOK * DQK, g_qimg, BM, 32, bx, b, st);
    } else if (role == 1) {
        prep_qk_body(g_kh + (size_t)b * NTOK * DQK, g_kimg, BN, 128, bx, b, st);
    } else {
        const int t = threadIdx.x, m = t & 31;
        const __half* src = g_vh + (size_t)b * NTOK * DV;
        __half* dst = g_vimg + (size_t)(b * 128 + bx) * (DV * LDV);
        const int n0 = bx * BN;
        for (int c = (t >> 5); c < DV; c += 8)
            dst[c * LDV + m] = src[(size_t)c * NTOK + n0 + m];
    }
}

// ---------------- flash kernel (byte-identical to 311us version) ----------------
#define SQHI 0
#define SK0  17408
#define SV0  26112
#define KBUF 4352
#define VBUF 10240
#define MBAR_OFF 135168
#define LROW_OFF 135232
#define OSM_LD 132
#define SM_BYTES 135744
#define TILE_BYTES (2 * KBUF + 2 * VBUF)   // 29184 bytes

__global__ __launch_bounds__(256, 1) void flash_kernel(
    const float* __restrict__ xin, const float* __restrict__ gamma_p,
    float* __restrict__ yout)
{
    extern __shared__ __half sm[];
    const uint32_t sb = smem_u32(sm);
    const uint32_t mb0 = sb + MBAR_OFF, mb1 = sb + MBAR_OFF + 8;
    const int t = threadIdx.x, lane = t & 31, wid = t >> 5;
    const int qt = blockIdx.x, b = blockIdx.y;
    const int n0 = qt * BM;
    const int lg = lane >> 3, lr = lane & 7;
    const uint32_t qa_base = (uint32_t)((16 * wid + lr + (lg & 1) * 8) * LDQ + (lg >> 1) * 8);
    const uint32_t kb_base = (uint32_t)(lr * LDQ + lg * 8);
    const uint32_t vb_base = (uint32_t)(lr * LDV + lg * 8);

    const __half* kimg = g_kimg + (size_t)b * 128 * (size_t)(BN * LDQ);
    const __half* vimg = g_vimg + (size_t)b * 128 * (size_t)(DV * LDV);

    if (t == 0) { MBARRIER_INIT(mb0, 1); MBARRIER_INIT(mb1, 1); }
    __syncthreads();
    if (t == 0) {
        expect_tx(mb0, TILE_BYTES + 2 * BM * LDQ);
        bulk_cp(sb, g_qimg + (size_t)(b * 32 + qt) * (BM * LDQ),
                2 * BM * LDQ, mb0);
        bulk_cp(sb + 2 * SK0, kimg, 2 * KBUF, mb0);
        bulk_cp(sb + 2 * SV0, vimg, 2 * VBUF, mb0);
        expect_tx(mb1, TILE_BYTES);
        bulk_cp(sb + 2 * (SK0 + KBUF), kimg + KBUF, 2 * KBUF, mb1);
        bulk_cp(sb + 2 * (SV0 + VBUF), vimg + VBUF, 2 * VBUF, mb1);
    }

    float oacc[32][4];
#pragma unroll
    for (int nf = 0; nf < 32; nf++)
#pragma unroll
        for (int e = 0; e < 4; e++) oacc[nf][e] = 0.f;
    float lsum0 = 0.f, lsum1 = 0.f;
    float m0 = -1e30f, m1 = -1e30f;

    for (int kt = 0; kt < NKT; kt++) {
        const int buf = kt & 1;
        MBARRIER_WAIT_PARITY(buf ? mb1 : mb0, (kt >> 1) & 1);

        const uint32_t khi = SK0 + buf * KBUF;
        const uint32_t vhi = SV0 + buf * VBUF;

        // ---- S = Q K^T (single-term fp16), 2 accumulator banks for ILP ----
        float sa[4][4], sc[4][4];
#pragma unroll
        for (int nn = 0; nn < 4; nn++)
#pragma unroll
            for (int e = 0; e < 4; e++) { sa[nn][e] = 0.f; sc[nn][e] = 0.f; }
#pragma unroll
        for (int kkp = 0; kkp < 4; kkp++) {
            uint32_t qh0[4], qh1[4];
            ldsm_x4(qh0, sb + 2 * (SQHI + qa_base + 32 * kkp));
            ldsm_x4(qh1, sb + 2 * (SQHI + qa_base + 32 * kkp + 16));
#pragma unroll
            for (int nn = 0; nn < 4; nn++) {
                uint32_t kh[4];
                ldsm_x4(kh, sb + 2 * (khi + kb_base + nn * 8 * LDQ + 32 * kkp));
                mma_f16(sa[nn], qh0, kh);
                mma_f16(sc[nn], qh1, kh + 2);
            }
        }

        // ---- online softmax with running max ----
        float sv[4][4];
#pragma unroll
        for (int nn = 0; nn < 4; nn++)
#pragma unroll
            for (int e = 0; e < 4; e++) sv[nn][e] = sa[nn][e] + sc[nn][e];

        float tm0 = -1e30f, tm1 = -1e30f;
#pragma unroll
        for (int nn = 0; nn < 4; nn++) {
            tm0 = fmaxf(tm0, fmaxf(sv[nn][0], sv[nn][1]));
            tm1 = fmaxf(tm1, fmaxf(sv[nn][2], sv[nn][3]));
        }
        tm0 = fmaxf(tm0, __shfl_xor_sync(0xffffffffu, tm0, 1));
        tm0 = fmaxf(tm0, __shfl_xor_sync(0xffffffffu, tm0, 2));
        tm1 = fmaxf(tm1, __shfl_xor_sync(0xffffffffu, tm1, 1));
        tm1 = fmaxf(tm1, __shfl_xor_sync(0xffffffffu, tm1, 2));
        const float mn0 = fmaxf(m0, tm0), mn1 = fmaxf(m1, tm1);
        const float sc0 = __expf(m0 - mn0), sc1 = __expf(m1 - mn1);
        m0 = mn0; m1 = mn1;
        if (sc0 < 1.f) {
            lsum0 *= sc0;
#pragma unroll
            for (int nf = 0; nf < 32; nf++) { oacc[nf][0] *= sc0; oacc[nf][1] *= sc0; }
        }
        if (sc1 < 1.f) {
            lsum1 *= sc1;
#pragma unroll
            for (int nf = 0; nf < 32; nf++) { oacc[nf][2] *= sc1; oacc[nf][3] *= sc1; }
        }

        uint32_t phi[2][4];
#pragma unroll
        for (int kk = 0; kk < 2; kk++)
#pragma unroll
            for (int half = 0; half < 2; half++) {
                const float* p = sv[2 * kk + half];
                __half h0 = __float2half_rn(__expf(p[0] - mn0));
                __half h1 = __float2half_rn(__expf(p[1] - mn0));
                __half h2 = __float2half_rn(__expf(p[2] - mn1));
                __half h3 = __float2half_rn(__expf(p[3] - mn1));
                phi[kk][2 * half + 0] = packh2(h0, h1);
                phi[kk][2 * half + 1] = packh2(h2, h3);
                lsum0 += __half2float(h0) + __half2float(h1);
                lsum1 += __half2float(h2) + __half2float(h3);
            }

        // ---- O += P V (single-term fp16), all 256 channels ----
#pragma unroll
        for (int nf = 0; nf < 32; nf++) {
            uint32_t vh[4];
            ldsm_x4(vh, sb + 2 * (vhi + vb_base + nf * 8 * LDV));
            mma_f16(oacc[nf], phi[0], vh);
            mma_f16(oacc[nf], phi[1], vh + 2);
        }
        __syncthreads();
        if (t == 0 && kt + 2 < NKT) {
            const uint32_t mb = buf ? mb1 : mb0;
            expect_tx(mb, TILE_BYTES);
            bulk_cp(sb + 2 * (SK0 + buf * KBUF),
                    kimg + (size_t)(kt + 2) * KBUF, 2 * KBUF, mb);
            bulk_cp(sb + 2 * (SV0 + buf * VBUF),
                    vimg + (size_t)(kt + 2) * VBUF, 2 * VBUF, mb);
        }
    }

    // ---- epilogue: transpose O through smem, y = gamma*(O/l) + x ----
    lsum0 += __shfl_xor_sync(0xffffffffu, lsum0, 1);
    lsum0 += __shfl_xor_sync(0xffffffffu, lsum0, 2);
    lsum1 += __shfl_xor_sync(0xffffffffu, lsum1, 1);
    lsum1 += __shfl_xor_sync(0xffffffffu, lsum1, 2);
    float* Osm = (float*)sm;
    float* lrow = (float*)((char*)sm + LROW_OFF);
    const int rloc = 16 * wid + (lane >> 2);
    if ((lane & 3) == 0) { lrow[rloc] = lsum0; lrow[rloc + 8] = lsum1; }
#pragma unroll
    for (int nf = 0; nf < 32; nf++) {
        const int c = nf * 8 + 2 * (lane & 3);
        Osm[c * OSM_LD + rloc] = oacc[nf][0];
        Osm[(c + 1) * OSM_LD + rloc] = oacc[nf][1];
        Osm[c * OSM_LD + rloc + 8] = oacc[nf][2];
        Osm[(c + 1) * OSM_LD + rloc + 8] = oacc[nf][3];
    }
    __syncthreads();
    if (t < 128) lrow[t] = gamma_p[0] / lrow[t];
    __syncthreads();
    const float* xb = xin  + (size_t)b * DV * NTOK;
    float*       yb = yout + (size_t)b * DV * NTOK;
    for (int i = t; i < 256 * 32; i += 256) {
        const int c = i >> 5, nn = (i & 31) << 2;
        float4 o = *(float4*)&Osm[c * OSM_LD + nn];
        size_t gi = (size_t)c * NTOK + n0 + nn;
        float4 xv = *(const float4*)(xb + gi);
        float4 y;
        y.x = o.x * lrow[nn + 0] + xv.x;
        y.y = o.y * lrow[nn + 1] + xv.y;
        y.z = o.z * lrow[nn + 2] + xv.z;
        y.w = o.w * lrow[nn + 3] + xv.w;
        *(float4*)(yb + gi) = y;
    }
}

// ---------------- launch ----------------
extern "C" void kernel_launch(void* const* d_in, const int* in_sizes, int n_in,
                              void* d_out, int out_size)
{
    const float* x     = (const float*)d_in[0];
    const float* Wq    = (const float*)d_in[1];
    const float* bq    = (const float*)d_in[2];
    const float* Wk    = (const float*)d_in[3];
    const float* bk    = (const float*)d_in[4];
    const float* Wv    = (const float*)d_in[5];
    const float* bv    = (const float*)d_in[6];
    const float* gamma = (const float*)d_in[7];
    float* out = (float*)d_out;

    prep_x_kernel<<<BATCH * NTOK, 256>>>(x);
    prep_w_kernel<<<512, 256>>>(Wq, bq, Wk, bk, Wv, bv);

    cudaFuncSetAttribute(gemm_tensor_kernel,
                         cudaFuncAttributeMaxDynamicSharedMemorySize, GSM_BYTES);
    gemm_tensor_kernel<<<dim3(4, BATCH * NTOK / 128), 256, GSM_BYTES>>>();

    prep_all_kernel<<<dim3(128, BATCH, 3), 256>>>();

    cudaFuncSetAttribute(flash_kernel,
                         cudaFuncAttributeMaxDynamicSharedMemorySize, SM_BYTES);
    flash_kernel<<<dim3(NTOK / BM, BATCH), 256, SM_BYTES>>>(x, gamma, out);
}

// round 12
// speedup vs baseline: 7.1825x; 1.0682x over previous
#include <cuda_runtime.h>
#include <cuda_bf16.h>
#include <cuda_fp16.h>
#include <cstdint>

// B=4, N=4096 tok/batch, d_qk=128, d_v=256.
// Reference reshapes are flat reinterprets of TOKEN-major projection buffers:
// pq[c][n] = q_flat[c*4096+n]  =>  attention channel c = tok>>5 (qk) / tok>>4 (v),
// attention pos n mixes (tok & 31/15) with proj channel pc.
//
// Round-12 (vs 291.3us):
//  * prep_all DELETED. The projection GEMM epilogue writes the flash tile
//    images directly. Images are stored TRANSPOSED ([ch][pos]) so the
//    lane-varying index (pc -> pos) is contiguous => 16B store runs.
//    Mapping (derived from the flat-reinterpret algebra):
//      Q: tile=tok&31,        q=pc,    ch=tok>>5
//      K: kt=(tok&31)*4+(pc>>5), key=pc&31, ch=tok>>5
//      V: kt=(tok&15)*8+(pc>>5), key=pc&31, ch=tok>>4
//  * flash loads Q/K fragments via ldmatrix.trans (same ldsm/MMA counts,
//    conflict-free); V path unchanged. Numerics bit-identical to round 11
//    => rel_err should reproduce ~4.53e-4 (mapping check built in).

#define NTOK  4096
#define DQK   128
#define DV    256
#define BATCH 4
#define BM    128
#define BN    32
#define NKT   (NTOK / BN)
#define LDQF  136     // Q image row stride (q dim), [ch=128][q=128]
#define LDK   40      // K image row stride (key dim), [ch=128][key=32]
#define LDV   40      // V image row stride (key dim), [ch=256][key=32]

// -------- device scratch (no allocations allowed) --------
__device__ __align__(16) __half g_xhi[4 * BATCH * NTOK * 72];
__device__ __align__(16) __half g_whi[4 * 512 * 72];
__device__ float g_bias[512];
__device__ __align__(16) __half g_qimg[BATCH * 32 * 128 * LDQF];    // [b,qt][ch][q]
__device__ __align__(16) __half g_kimg[BATCH * 128 * 128 * LDK];    // [b,kt][ch][key]
__device__ __align__(16) __half g_vimg[BATCH * 128 * DV * LDV];     // [b,kt][ch][key]

// ---------------- wrappers ----------------
__device__ __forceinline__ uint32_t smem_u32(const void* p) {
    uint32_t a;
    asm("{ .reg .u64 t; cvta.to.shared.u64 t, %1; cvt.u32.u64 %0, t; }" : "=r"(a) : "l"(p));
    return a;
}
__device__ __forceinline__ void ldsm_x4(uint32_t* r, uint32_t saddr) {
    asm volatile("ldmatrix.sync.aligned.m8n8.x4.shared.b16 {%0,%1,%2,%3}, [%4];"
        : "=r"(r[0]), "=r"(r[1]), "=r"(r[2]), "=r"(r[3]) : "r"(saddr));
}
__device__ __forceinline__ void ldsm_x4_t(uint32_t* r, uint32_t saddr) {
    asm volatile("ldmatrix.sync.aligned.m8n8.x4.trans.shared.b16 {%0,%1,%2,%3}, [%4];"
        : "=r"(r[0]), "=r"(r[1]), "=r"(r[2]), "=r"(r[3]) : "r"(saddr));
}
__device__ __forceinline__ void mma_f16(float* d, const uint32_t* a, const uint32_t* b) {
    asm volatile("mma.sync.aligned.m16n8k16.row.col.f32.f16.f16.f32 "
        "{%0,%1,%2,%3}, {%4,%5,%6,%7}, {%8,%9}, {%0,%1,%2,%3};"
        : "+f"(d[0]), "+f"(d[1]), "+f"(d[2]), "+f"(d[3])
        : "r"(a[0]), "r"(a[1]), "r"(a[2]), "r"(a[3]), "r"(b[0]), "r"(b[1]));
}
__device__ __forceinline__ uint32_t packh2(__half x, __half y) {
    __half2 t; t.x = x; t.y = y;
    return *reinterpret_cast<uint32_t*>(&t);
}
__device__ __forceinline__ void bulk_cp(uint32_t dst, const void* src,
                                        uint32_t bytes, uint32_t mbar) {
    asm volatile(
        "cp.async.bulk.shared::cta.global.mbarrier::complete_tx::bytes [%0], [%1], %2, [%3];"
        :: "r"(dst), "l"(src), "r"(bytes), "r"(mbar) : "memory");
}
__device__ __forceinline__ void expect_tx(uint32_t mbar, uint32_t bytes) {
    asm volatile("mbarrier.arrive.expect_tx.shared.b64 _, [%0], %1;"
        :: "r"(mbar), "r"(bytes) : "memory");
}
#define MBARRIER_INIT(mbar, cnt) \
    asm volatile("mbarrier.init.shared.b64 [%0], %1;" :: "r"((uint32_t)(mbar)), "r"((uint32_t)(cnt)) : "memory")
#define MBARRIER_WAIT_PARITY(mbar, parity) do { \
    uint32_t _m = (uint32_t)(mbar); uint32_t _p = (uint32_t)(parity); uint32_t _d; \
    asm volatile("{\n\t.reg .pred p;\n\t" \
        "mbarrier.try_wait.parity.acquire.cta.shared::cta.b64 p, [%1], %2;\n\t" \
        "selp.b32 %0, 1, 0, p;\n\t}" : "=r"(_d) : "r"(_m), "r"(_p) : "memory"); \
    if (!_d) { \
        asm volatile("{\n\t.reg .pred P1;\n\t" \
            "WL_%=:\n\t" \
            "mbarrier.try_wait.parity.acquire.cta.shared::cta.b64 P1, [%0], %1, 0x989680;\n\t" \
            "@P1 bra.uni WD_%=;\n\t" \
            "bra.uni WL_%=;\n\t" \
            "WD_%=:\n\t}" :: "r"(_m), "r"(_p) : "memory"); \
    } } while (0)

// ---------------- prep_x: x fp32 -> fp16 padded k-step image ----------------
__global__ __launch_bounds__(256) void prep_x_kernel(const float* __restrict__ x) {
    size_t i = (size_t)blockIdx.x * 256 + threadIdx.x;
    int c = (int)(i & 255);
    size_t n = i >> 8;
    size_t off = ((size_t)(c >> 6) * (BATCH * NTOK) + n) * 72 + (c & 63);
    g_xhi[off] = __float2half_rn(x[i]);
}

// ---------------- prep_w: transpose weights -> fp16, concat bias ----------------
__global__ __launch_bounds__(256) void prep_w_kernel(
    const float* __restrict__ Wq, const float* __restrict__ bq,
    const float* __restrict__ Wk, const float* __restrict__ bk,
    const float* __restrict__ Wv, const float* __restrict__ bv)
{
    const int d = blockIdx.x, c = threadIdx.x;
    float w;
    if (d < 128)      w = Wq[c * 128 + d];
    else if (d < 256) w = Wk[c * 128 + (d - 128)];
    else              w = Wv[c * 256 + (d - 256)];
    size_t off = ((size_t)(c >> 6) * 512 + d) * 72 + (c & 63);
    g_whi[off] = __float2half_rn(w);
    if (c == 0)
        g_bias[d] = (d < 128) ? bq[d] : (d < 256) ? bk[d - 128] : bv[d - 256];
}

// ---------------- projection GEMM, epilogue writes flash images ----------------
#define GLDA 72
#define GSAHI 0
#define GSBHI 9216
#define GMBAR 36864
#define GSM_BYTES 36896

__global__ __launch_bounds__(256, 2) void gemm_tensor_kernel() {
    extern __shared__ __half sg[];
    const uint32_t sb = smem_u32(sg);
    const uint32_t mbar = sb + GMBAR;
    const int t = threadIdx.x, lane = t & 31, wid = t >> 5;
    const int nt = blockIdx.x;
    const int m0 = blockIdx.y * 128;
    const int n0 = nt * 128;
    const int lg = lane >> 3, lr = lane & 7;
    const uint32_t a_base = (uint32_t)((16 * wid + lr + (lg & 1) * 8) * GLDA + (lg >> 1) * 8);
    const uint32_t b_base = (uint32_t)(lr * GLDA + lg * 8);

    if (t == 0) MBARRIER_INIT(mbar, 1);
    __syncthreads();

    float acc[16][4];
#pragma unroll
    for (int nf = 0; nf < 16; nf++)
#pragma unroll
        for (int e = 0; e < 4; e++) acc[nf][e] = 0.f;

    for (int kb = 0; kb < 4; kb++) {
        if (t == 0) {
            expect_tx(mbar, 2 * 18432);
            const size_t aoff = ((size_t)kb * (BATCH * NTOK) + m0) * 72;
            const size_t boff = ((size_t)kb * 512 + n0) * 72;
            bulk_cp(sb + 2 * GSAHI, g_xhi + aoff, 18432, mbar);
            bulk_cp(sb + 2 * GSBHI, g_whi + boff, 18432, mbar);
        }
        MBARRIER_WAIT_PARITY(mbar, kb & 1);
#pragma unroll
        for (int kkp = 0; kkp < 2; kkp++) {
            uint32_t qh0[4], qh1[4];
            ldsm_x4(qh0, sb + 2 * (GSAHI + a_base + 32 * kkp));
            ldsm_x4(qh1, sb + 2 * (GSAHI + a_base + 32 * kkp + 16));
#pragma unroll
            for (int nf = 0; nf < 16; nf++) {
                uint32_t bh[4];
                ldsm_x4(bh, sb + 2 * (GSBHI + b_base + nf * 8 * GLDA + 32 * kkp));
                mma_f16(acc[nf], qh0, bh);
                mma_f16(acc[nf], qh1, bh + 2);
            }
        }
        __syncthreads();
    }

    // ---- epilogue: +bias, round fp16, write flash images directly ----
    const int lq = 2 * (lane & 3);           // within-8 pc offset (even)
    const int rr0 = m0 + 16 * wid + (lane >> 2);   // token of acc[.][0..1]
#pragma unroll
    for (int rowp = 0; rowp < 2; rowp++) {
        const int tok = rr0 + 8 * rowp;      // global token
        const int b   = tok >> 12;
        const int tt  = tok & 4095;
        if (nt == 0) {
            // Q: tile = tt&31, q = pc, ch = tt>>5
            __half* dst = g_qimg
                + ((size_t)(b * 32 + (tt & 31)) * 128 + (tt >> 5)) * LDQF;
#pragma unroll
            for (int nf = 0; nf < 16; nf++) {
                const int pc = nf * 8 + lq;
                const float b0 = g_bias[n0 + pc], b1 = g_bias[n0 + pc + 1];
                *(uint32_t*)(dst + pc) = packh2(
                    __float2half_rn(acc[nf][2 * rowp] + b0),
                    __float2half_rn(acc[nf][2 * rowp + 1] + b1));
            }
        } else if (nt == 1) {
            // K: kt = (tt&31)*4 + (pc>>5), key = pc&31, ch = tt>>5
            const int ktb = (tt & 31) * 4;
            const int ch  = tt >> 5;
#pragma unroll
            for (int nf = 0; nf < 16; nf++) {
                const int pc = nf * 8 + lq;
                const float b0 = g_bias[n0 + pc], b1 = g_bias[n0 + pc + 1];
                __half* dst = g_kimg
                    + ((size_t)(b * 128 + ktb + (nf >> 2)) * 128 + ch) * LDK
                    + ((nf & 3) * 8 + lq);
                *(uint32_t*)dst = packh2(
                    __float2half_rn(acc[nf][2 * rowp] + b0),
                    __float2half_rn(acc[nf][2 * rowp + 1] + b1));
            }
        } else {
            // V: pc_full = (nt-2)*128 + pc; kt = (tt&15)*8 + (pc_full>>5),
            //    key = pc_full&31, ch = tt>>4
            const int ktb = (tt & 15) * 8 + (nt - 2) * 4;
            const int ch  = tt >> 4;
#pragma unroll
            for (int nf = 0; nf < 16; nf++) {
                const int pc = nf * 8 + lq;
                const float b0 = g_bias[n0 + pc], b1 = g_bias[n0 + pc + 1];
                __half* dst = g_vimg
                    + ((size_t)(b * 128 + ktb + (nf >> 2)) * DV + ch) * LDV
                    + ((nf & 3) * 8 + lq);
                *(uint32_t*)dst = packh2(
                    __float2half_rn(acc[nf][2 * rowp] + b0),
                    __float2half_rn(acc[nf][2 * rowp + 1] + b1));
            }
        }
    }
}

// ---------------- flash kernel ----------------
// smem (halves): Q[128ch x 136]@0 (17408), K bufs @17408 (2x5120, [ch][key]),
// V bufs @27648 (2x10240, [ch][key]) -> 48128 halves = 96256 B in mainloop.
// epilogue Osm reuses [0,135168) B; mbars @135168, lrow @135232.
#define SQHI 0
#define SK0  17408
#define SV0  27648
#define KBUF 5120
#define VBUF 10240
#define MBAR_OFF 135168
#define LROW_OFF 135232
#define OSM_LD 132
#define SM_BYTES 135744
#define TILE_BYTES (2 * KBUF + 2 * VBUF)   // 30720 bytes

__global__ __launch_bounds__(256, 1) void flash_kernel(
    const float* __restrict__ xin, const float* __restrict__ gamma_p,
    float* __restrict__ yout)
{
    extern __shared__ __half sm[];
    const uint32_t sb = smem_u32(sm);
    const uint32_t mb0 = sb + MBAR_OFF, mb1 = sb + MBAR_OFF + 8;
    const int t = threadIdx.x, lane = t & 31, wid = t >> 5;
    const int qt = blockIdx.x, b = blockIdx.y;
    const int n0 = qt * BM;
    const int lg = lane >> 3, lr = lane & 7;
    // trans A-frag from [ch][q]: lanes: (k=lr+(lg>>1)*8, m=16*wid+(lg&1)*8)
    const uint32_t qa_base = (uint32_t)((lr + (lg >> 1) * 8) * LDQF
                                        + 16 * wid + (lg & 1) * 8);
    // trans B-frag from [ch][key]: lanes: (k=lr+lg*8, n=0)
    const uint32_t kb_base = (uint32_t)((lr + lg * 8) * LDK);
    // V non-trans from [ch][key] (unchanged)
    const uint32_t vb_base = (uint32_t)(lr * LDV + lg * 8);

    const __half* kimg = g_kimg + (size_t)b * 128 * (size_t)(128 * LDK);
    const __half* vimg = g_vimg + (size_t)b * 128 * (size_t)(DV * LDV);

    if (t == 0) { MBARRIER_INIT(mb0, 1); MBARRIER_INIT(mb1, 1); }
    __syncthreads();
    if (t == 0) {
        expect_tx(mb0, TILE_BYTES + 2 * 128 * LDQF);
        bulk_cp(sb, g_qimg + (size_t)(b * 32 + qt) * (128 * LDQF),
                2 * 128 * LDQF, mb0);
        bulk_cp(sb + 2 * SK0, kimg, 2 * KBUF, mb0);
        bulk_cp(sb + 2 * SV0, vimg, 2 * VBUF, mb0);
        expect_tx(mb1, TILE_BYTES);
        bulk_cp(sb + 2 * (SK0 + KBUF), kimg + KBUF, 2 * KBUF, mb1);
        bulk_cp(sb + 2 * (SV0 + VBUF), vimg + VBUF, 2 * VBUF, mb1);
    }

    float oacc[32][4];
#pragma unroll
    for (int nf = 0; nf < 32; nf++)
#pragma unroll
        for (int e = 0; e < 4; e++) oacc[nf][e] = 0.f;
    float lsum0 = 0.f, lsum1 = 0.f;
    float m0 = -1e30f, m1 = -1e30f;

    for (int kt = 0; kt < NKT; kt++) {
        const int buf = kt & 1;
        MBARRIER_WAIT_PARITY(buf ? mb1 : mb0, (kt >> 1) & 1);

        const uint32_t khi = SK0 + buf * KBUF;
        const uint32_t vhi = SV0 + buf * VBUF;

        // ---- S = Q K^T (single-term fp16, trans operand loads) ----
        float sa[4][4], sc[4][4];
#pragma unroll
        for (int nn = 0; nn < 4; nn++)
#pragma unroll
            for (int e = 0; e < 4; e++) { sa[nn][e] = 0.f; sc[nn][e] = 0.f; }
#pragma unroll
        for (int kkp = 0; kkp < 4; kkp++) {
            uint32_t qh0[4], qh1[4];
            ldsm_x4_t(qh0, sb + 2 * (SQHI + qa_base + (32 * kkp) * LDQF));
            ldsm_x4_t(qh1, sb + 2 * (SQHI + qa_base + (32 * kkp + 16) * LDQF));
#pragma unroll
            for (int nn = 0; nn < 4; nn++) {
                uint32_t kh[4];   // k 32kkp..+31 x key nn*8..+7
                ldsm_x4_t(kh, sb + 2 * (khi + kb_base + (32 * kkp) * LDK + nn * 8));
                mma_f16(sa[nn], qh0, kh);       // k 0-15 of chunk
                mma_f16(sc[nn], qh1, kh + 2);   // k 16-31 of chunk
            }
        }

        // ---- online softmax with running max ----
        float sv[4][4];
#pragma unroll
        for (int nn = 0; nn < 4; nn++)
#pragma unroll
            for (int e = 0; e < 4; e++) sv[nn][e] = sa[nn][e] + sc[nn][e];

        float tm0 = -1e30f, tm1 = -1e30f;
#pragma unroll
        for (int nn = 0; nn < 4; nn++) {
            tm0 = fmaxf(tm0, fmaxf(sv[nn][0], sv[nn][1]));
            tm1 = fmaxf(tm1, fmaxf(sv[nn][2], sv[nn][3]));
        }
        tm0 = fmaxf(tm0, __shfl_xor_sync(0xffffffffu, tm0, 1));
        tm0 = fmaxf(tm0, __shfl_xor_sync(0xffffffffu, tm0, 2));
        tm1 = fmaxf(tm1, __shfl_xor_sync(0xffffffffu, tm1, 1));
        tm1 = fmaxf(tm1, __shfl_xor_sync(0xffffffffu, tm1, 2));
        const float mn0 = fmaxf(m0, tm0), mn1 = fmaxf(m1, tm1);
        const float sc0 = __expf(m0 - mn0), sc1 = __expf(m1 - mn1);
        m0 = mn0; m1 = mn1;
        if (sc0 < 1.f) {
            lsum0 *= sc0;
#pragma unroll
            for (int nf = 0; nf < 32; nf++) { oacc[nf][0] *= sc0; oacc[nf][1] *= sc0; }
        }
        if (sc1 < 1.f) {
            lsum1 *= sc1;
#pragma unroll
            for (int nf = 0; nf < 32; nf++) { oacc[nf][2] *= sc1; oacc[nf][3] *= sc1; }
        }

        uint32_t phi[2][4];
#pragma unroll
        for (int kk = 0; kk < 2; kk++)
#pragma unroll
            for (int half = 0; half < 2; half++) {
                const float* p = sv[2 * kk + half];
                __half h0 = __float2half_rn(__expf(p[0] - mn0));
                __half h1 = __float2half_rn(__expf(p[1] - mn0));
                __half h2 = __float2half_rn(__expf(p[2] - mn1));
                __half h3 = __float2half_rn(__expf(p[3] - mn1));
                phi[kk][2 * half + 0] = packh2(h0, h1);
                phi[kk][2 * half + 1] = packh2(h2, h3);
                lsum0 += __half2float(h0) + __half2float(h1);
                lsum1 += __half2float(h2) + __half2float(h3);
            }

        // ---- O += P V (single-term fp16), all 256 channels ----
#pragma unroll
        for (int nf = 0; nf < 32; nf++) {
            uint32_t vh[4];
            ldsm_x4(vh, sb + 2 * (vhi + vb_base + nf * 8 * LDV));
            mma_f16(oacc[nf], phi[0], vh);
            mma_f16(oacc[nf], phi[1], vh + 2);
        }
        __syncthreads();
        if (t == 0 && kt + 2 < NKT) {
            const uint32_t mb = buf ? mb1 : mb0;
            expect_tx(mb, TILE_BYTES);
            bulk_cp(sb + 2 * (SK0 + buf * KBUF),
                    kimg + (size_t)(kt + 2) * KBUF, 2 * KBUF, mb);
            bulk_cp(sb + 2 * (SV0 + buf * VBUF),
                    vimg + (size_t)(kt + 2) * VBUF, 2 * VBUF, mb);
        }
    }

    // ---- epilogue: transpose O through smem, y = gamma*(O/l) + x ----
    lsum0 += __shfl_xor_sync(0xffffffffu, lsum0, 1);
    lsum0 += __shfl_xor_sync(0xffffffffu, lsum0, 2);
    lsum1 += __shfl_xor_sync(0xffffffffu, lsum1, 1);
    lsum1 += __shfl_xor_sync(0xffffffffu, lsum1, 2);
    float* Osm = (float*)sm;
    float* lrow = (float*)((char*)sm + LROW_OFF);
    const int rloc = 16 * wid + (lane >> 2);
    if ((lane & 3) == 0) { lrow[rloc] = lsum0; lrow[rloc + 8] = lsum1; }
#pragma unroll
    for (int nf = 0; nf < 32; nf++) {
        const int c = nf * 8 + 2 * (lane & 3);
        Osm[c * OSM_LD + rloc] = oacc[nf][0];
        Osm[(c + 1) * OSM_LD + rloc] = oacc[nf][1];
        Osm[c * OSM_LD + rloc + 8] = oacc[nf][2];
        Osm[(c + 1) * OSM_LD + rloc + 8] = oacc[nf][3];
    }
    __syncthreads();
    if (t < 128) lrow[t] = gamma_p[0] / lrow[t];
    __syncthreads();
    const float* xb = xin  + (size_t)b * DV * NTOK;
    float*       yb = yout + (size_t)b * DV * NTOK;
    for (int i = t; i < 256 * 32; i += 256) {
        const int c = i >> 5, nn = (i & 31) << 2;
        float4 o = *(float4*)&Osm[c * OSM_LD + nn];
        size_t gi = (size_t)c * NTOK + n0 + nn;
        float4 xv = *(const float4*)(xb + gi);
        float4 y;
        y.x = o.x * lrow[nn + 0] + xv.x;
        y.y = o.y * lrow[nn + 1] + xv.y;
        y.z = o.z * lrow[nn + 2] + xv.z;
        y.w = o.w * lrow[nn + 3] + xv.w;
        *(float4*)(yb + gi) = y;
    }
}

// ---------------- launch ----------------
extern "C" void kernel_launch(void* const* d_in, const int* in_sizes, int n_in,
                              void* d_out, int out_size)
{
    const float* x     = (const float*)d_in[0];
    const float* Wq    = (const float*)d_in[1];
    const float* bq    = (const float*)d_in[2];
    const float* Wk    = (const float*)d_in[3];
    const float* bk    = (const float*)d_in[4];
    const float* Wv    = (const float*)d_in[5];
    const float* bv    = (const float*)d_in[6];
    const float* gamma = (const float*)d_in[7];
    float* out = (float*)d_out;

    prep_x_kernel<<<BATCH * NTOK, 256>>>(x);
    prep_w_kernel<<<512, 256>>>(Wq, bq, Wk, bk, Wv, bv);

    cudaFuncSetAttribute(gemm_tensor_kernel,
                         cudaFuncAttributeMaxDynamicSharedMemorySize, GSM_BYTES);
    gemm_tensor_kernel<<<dim3(4, BATCH * NTOK / 128), 256, GSM_BYTES>>>();

    cudaFuncSetAttribute(flash_kernel,
                         cudaFuncAttributeMaxDynamicSharedMemorySize, SM_BYTES);
    flash_kernel<<<dim3(NTOK / BM, BATCH), 256, SM_BYTES>>>(x, gamma, out);
}